// round 1
// baseline (speedup 1.0000x reference)
#include <cuda_runtime.h>
#include <math.h>

#define DIM 768
#define NTOK 1024
#define BATCH 4
#define ROWS (BATCH * NTOK)        // 4096
#define F_DIM 256
#define HEADS 12
#define DHEAD 64
#define QKV3 (3 * DIM)             // 2304
#define MLPD 3072
#define DEPTH 8
#define LN_EPS 1e-5f

// ----------------------------------------------------------------------------
// Scratch (static device globals; no runtime allocation)
// ----------------------------------------------------------------------------
__device__ float g_pos[NTOK * DIM];
__device__ float g_x  [ROWS * DIM];
__device__ float g_y  [ROWS * DIM];
__device__ float g_o  [ROWS * DIM];
__device__ float g_qkv[ROWS * QKV3];
__device__ float g_h  [ROWS * MLPD];

// ----------------------------------------------------------------------------
// Sine position embedding: pos[n, d], n = r*32 + c, F = 384
// out[d even] = sin(coord/(32+1e-6)*2pi / 10000^(2*(id/2)/384)), odd -> cos
// ----------------------------------------------------------------------------
__global__ void pos_embed_kernel(float* __restrict__ pos) {
    int idx = blockIdx.x * blockDim.x + threadIdx.x;
    if (idx >= NTOK * DIM) return;
    int n = idx / DIM, d = idx % DIM;
    int r = n >> 5, c = n & 31;
    int id = (d < 384) ? d : d - 384;
    float coord = (d < 384) ? (float)(r + 1) : (float)(c + 1);
    float ang = coord / (32.0f + 1e-6f) * 6.283185307179586f;
    float ex = (float)(2 * (id / 2)) / 384.0f;
    float t = powf(10000.0f, ex);
    float p = ang / t;
    pos[idx] = (id & 1) ? cosf(p) : sinf(p);
}

// ----------------------------------------------------------------------------
// Embed: x[b,n,d] = sum_f cf[b,f,n] * w[d,f] + bias[d] + pos[n,d]
// cf: [B, 256, 1024], w: [768, 256]
// Block: 256 threads, tile 64(n) x 64(d), K chunks of 16.
// ----------------------------------------------------------------------------
__global__ __launch_bounds__(256) void embed_kernel(
    const float* __restrict__ cf, const float* __restrict__ w,
    const float* __restrict__ bias, const float* __restrict__ pos,
    float* __restrict__ x)
{
    __shared__ float As[16][64];   // [k][n]
    __shared__ float Bs[16][68];   // [k][d] (padded)
    int b  = blockIdx.z;
    int n0 = blockIdx.x * 64, d0 = blockIdx.y * 64;
    int tid = threadIdx.x;
    int ty = tid / 16, tx = tid % 16;
    float acc[4][4] = {};
    const float* cfb = cf + (size_t)b * F_DIM * NTOK;

    for (int k0 = 0; k0 < F_DIM; k0 += 16) {
        #pragma unroll
        for (int it = 0; it < 4; it++) {
            int idx = tid + it * 256;
            int kk = idx >> 6, nn = idx & 63;
            As[kk][nn] = cfb[(size_t)(k0 + kk) * NTOK + n0 + nn];
        }
        #pragma unroll
        for (int it = 0; it < 4; it++) {
            int idx = tid + it * 256;
            int dd = idx >> 4, kk = idx & 15;
            Bs[kk][dd] = w[(size_t)(d0 + dd) * F_DIM + k0 + kk];
        }
        __syncthreads();
        #pragma unroll
        for (int kk = 0; kk < 16; kk++) {
            float a[4], bb[4];
            #pragma unroll
            for (int i = 0; i < 4; i++) a[i]  = As[kk][ty * 4 + i];
            #pragma unroll
            for (int j = 0; j < 4; j++) bb[j] = Bs[kk][tx * 4 + j];
            #pragma unroll
            for (int i = 0; i < 4; i++)
                #pragma unroll
                for (int j = 0; j < 4; j++)
                    acc[i][j] += a[i] * bb[j];
        }
        __syncthreads();
    }
    #pragma unroll
    for (int i = 0; i < 4; i++) {
        int n = n0 + ty * 4 + i;
        #pragma unroll
        for (int j = 0; j < 4; j++) {
            int d = d0 + tx * 4 + j;
            x[((size_t)b * NTOK + n) * DIM + d] =
                acc[i][j] + bias[d] + pos[(size_t)n * DIM + d];
        }
    }
}

// ----------------------------------------------------------------------------
// LayerNorm: y = (x - mu) * rsqrt(var + eps) * w + b, per row of 768
// One block (256 threads) per row.
// ----------------------------------------------------------------------------
__global__ __launch_bounds__(256) void layernorm_kernel(
    const float* __restrict__ x, const float* __restrict__ w,
    const float* __restrict__ bias, float* __restrict__ y)
{
    int row = blockIdx.x;
    const float* xr = x + (size_t)row * DIM;
    float s = 0.f, ss = 0.f;
    float v[3];
    #pragma unroll
    for (int it = 0; it < 3; it++) {
        v[it] = xr[threadIdx.x + it * 256];
        s += v[it]; ss += v[it] * v[it];
    }
    __shared__ float red[64];
    #pragma unroll
    for (int off = 16; off; off >>= 1) {
        s  += __shfl_down_sync(0xffffffffu, s,  off);
        ss += __shfl_down_sync(0xffffffffu, ss, off);
    }
    int warp = threadIdx.x >> 5, lane = threadIdx.x & 31;
    if (lane == 0) { red[warp] = s; red[32 + warp] = ss; }
    __syncthreads();
    if (warp == 0) {
        s  = (lane < 8) ? red[lane] : 0.f;
        ss = (lane < 8) ? red[32 + lane] : 0.f;
        #pragma unroll
        for (int off = 4; off; off >>= 1) {
            s  += __shfl_down_sync(0xffffffffu, s,  off);
            ss += __shfl_down_sync(0xffffffffu, ss, off);
        }
        if (lane == 0) { red[0] = s; red[1] = ss; }
    }
    __syncthreads();
    float mu  = red[0] * (1.0f / DIM);
    float var = red[1] * (1.0f / DIM) - mu * mu;
    float inv = rsqrtf(var + LN_EPS);
    float* yr = y + (size_t)row * DIM;
    #pragma unroll
    for (int it = 0; it < 3; it++) {
        int i = threadIdx.x + it * 256;
        yr[i] = (v[it] - mu) * inv * w[i] + bias[i];
    }
}

// ----------------------------------------------------------------------------
// Generic SGEMM with fused epilogue: C = A[M,K] @ B[K,N] (+bias)(+gelu)(+resid)
// 128x128x8 tile, 256 threads, 8x8 microtile. M,N multiples of 128; K of 8.
// ----------------------------------------------------------------------------
#define BM 128
#define BN 128
#define BK 8
#define TM 8
#define TN 8

__global__ __launch_bounds__(256) void sgemm_ep_kernel(
    int M, int N, int K,
    const float* __restrict__ A, const float* __restrict__ B,
    const float* __restrict__ bias, const float* __restrict__ resid,
    float* __restrict__ C, int gelu)
{
    __shared__ float As[BK][BM];
    __shared__ float Bs[BK][BN];
    int tid = threadIdx.x;
    int bx = blockIdx.x, by = blockIdx.y;
    const float* Ab = A + (size_t)by * BM * K;
    const float* Bb = B + (size_t)bx * BN;

    int arow  = tid >> 1;            // 0..127
    int acol4 = (tid & 1) * 4;       // 0 or 4
    int brow  = tid >> 5;            // 0..7
    int bcol4 = (tid & 31) * 4;      // 0..124
    int ty = tid >> 4, tx = tid & 15;

    float acc[TM][TN] = {};
    float regM[TM], regN[TN];

    for (int k0 = 0; k0 < K; k0 += BK) {
        float4 a4 = *(const float4*)(Ab + (size_t)arow * K + k0 + acol4);
        As[acol4 + 0][arow] = a4.x;
        As[acol4 + 1][arow] = a4.y;
        As[acol4 + 2][arow] = a4.z;
        As[acol4 + 3][arow] = a4.w;
        float4 b4 = *(const float4*)(Bb + (size_t)(k0 + brow) * N + bcol4);
        *(float4*)(&Bs[brow][bcol4]) = b4;
        __syncthreads();
        #pragma unroll
        for (int kk = 0; kk < BK; kk++) {
            *(float4*)(&regM[0]) = *(const float4*)(&As[kk][ty * TM]);
            *(float4*)(&regM[4]) = *(const float4*)(&As[kk][ty * TM + 4]);
            *(float4*)(&regN[0]) = *(const float4*)(&Bs[kk][tx * TN]);
            *(float4*)(&regN[4]) = *(const float4*)(&Bs[kk][tx * TN + 4]);
            #pragma unroll
            for (int i = 0; i < TM; i++)
                #pragma unroll
                for (int j = 0; j < TN; j++)
                    acc[i][j] += regM[i] * regN[j];
        }
        __syncthreads();
    }

    int row0 = by * BM + ty * TM;
    int col0 = bx * BN + tx * TN;
    float bv[TN];
    #pragma unroll
    for (int j = 0; j < TN; j++) bv[j] = bias ? bias[col0 + j] : 0.f;

    #pragma unroll
    for (int i = 0; i < TM; i++) {
        float* crow = C + (size_t)(row0 + i) * N + col0;
        const float* rrow = resid ? (resid + (size_t)(row0 + i) * N + col0) : nullptr;
        float vals[TN];
        #pragma unroll
        for (int j = 0; j < TN; j++) {
            float v = acc[i][j] + bv[j];
            if (gelu) v = 0.5f * v * (1.0f + erff(v * 0.7071067811865475f));
            vals[j] = v;
        }
        if (rrow) {
            float4 r0 = *(const float4*)(rrow);
            float4 r1 = *(const float4*)(rrow + 4);
            vals[0] += r0.x; vals[1] += r0.y; vals[2] += r0.z; vals[3] += r0.w;
            vals[4] += r1.x; vals[5] += r1.y; vals[6] += r1.z; vals[7] += r1.w;
        }
        *(float4*)(crow)     = make_float4(vals[0], vals[1], vals[2], vals[3]);
        *(float4*)(crow + 4) = make_float4(vals[4], vals[5], vals[6], vals[7]);
    }
}

// ----------------------------------------------------------------------------
// Flash attention (fp32, online softmax).
// qkv: [4096, 2304] (q|k|v each 768 = 12 heads x 64).
// Grid: (16 qtiles, 12 heads, 4 batch). Block 256 = 64 rows x 4 lanes.
// Each lane owns 16 of the 64 head dims.
// ----------------------------------------------------------------------------
#define QT 64
#define KT 32

__global__ __launch_bounds__(256) void flash_attn_kernel(
    const float* __restrict__ qkv, float* __restrict__ o)
{
    __shared__ float Ks[KT][65];
    __shared__ float Vs[KT][65];
    int qb = blockIdx.x, h = blockIdx.y, b = blockIdx.z;
    int tid = threadIdx.x;
    int r = tid >> 2, l4 = tid & 3;
    int row = b * NTOK + qb * QT + r;
    int dbase = l4 * 16;

    const float* qp = qkv + (size_t)row * QKV3 + h * DHEAD + dbase;
    float q[16];
    #pragma unroll
    for (int i = 0; i < 16; i++) q[i] = qp[i];

    float oacc[16] = {};
    float m = -1e30f, lsum = 0.f;
    const float scale = 0.125f;  // 64^-0.5

    for (int kt = 0; kt < NTOK; kt += KT) {
        #pragma unroll
        for (int it = 0; it < 8; it++) {
            int idx = tid + it * 256;
            int j = idx >> 6, d = idx & 63;
            size_t base = (size_t)(b * NTOK + kt + j) * QKV3 + h * DHEAD + d;
            Ks[j][d] = qkv[base + DIM];
            Vs[j][d] = qkv[base + 2 * DIM];
        }
        __syncthreads();

        float s[KT];
        float cmax = -1e30f;
        #pragma unroll
        for (int j = 0; j < KT; j++) {
            float p = 0.f;
            #pragma unroll
            for (int i = 0; i < 16; i++) p += q[i] * Ks[j][dbase + i];
            p += __shfl_xor_sync(0xffffffffu, p, 1);
            p += __shfl_xor_sync(0xffffffffu, p, 2);
            p *= scale;
            s[j] = p;
            cmax = fmaxf(cmax, p);
        }
        float mnew = fmaxf(m, cmax);
        float corr = __expf(m - mnew);
        lsum *= corr;
        #pragma unroll
        for (int i = 0; i < 16; i++) oacc[i] *= corr;
        #pragma unroll
        for (int j = 0; j < KT; j++) {
            float p = __expf(s[j] - mnew);
            lsum += p;
            #pragma unroll
            for (int i = 0; i < 16; i++) oacc[i] += p * Vs[j][dbase + i];
        }
        m = mnew;
        __syncthreads();
    }
    float inv = 1.f / lsum;
    float* op = o + (size_t)row * DIM + h * DHEAD + dbase;
    #pragma unroll
    for (int i = 0; i < 16; i++) op[i] = oacc[i] * inv;
}

// ----------------------------------------------------------------------------
// Final transpose: x[b,n,d] -> out[b,d,n]
// ----------------------------------------------------------------------------
__global__ void transpose_out_kernel(const float* __restrict__ x,
                                     float* __restrict__ out)
{
    __shared__ float t[32][33];
    int b = blockIdx.z;
    int n0 = blockIdx.x * 32, d0 = blockIdx.y * 32;
    int tx = threadIdx.x, ty = threadIdx.y;
    #pragma unroll
    for (int i = ty; i < 32; i += 8)
        t[i][tx] = x[((size_t)b * NTOK + n0 + i) * DIM + d0 + tx];
    __syncthreads();
    #pragma unroll
    for (int i = ty; i < 32; i += 8)
        out[((size_t)b * DIM + d0 + i) * NTOK + n0 + tx] = t[tx][i];
}

// ----------------------------------------------------------------------------
// Host orchestration
// ----------------------------------------------------------------------------
extern "C" void kernel_launch(void* const* d_in, const int* in_sizes, int n_in,
                              void* d_out, int out_size)
{
    const float* c_f    = (const float*)d_in[0];
    const float* conv_w = (const float*)d_in[1];
    const float* conv_b = (const float*)d_in[2];
    const float* ln1_w  = (const float*)d_in[3];
    const float* ln1_b  = (const float*)d_in[4];
    const float* qkv_w  = (const float*)d_in[5];
    const float* out_w  = (const float*)d_in[6];
    const float* out_b  = (const float*)d_in[7];
    const float* ln2_w  = (const float*)d_in[8];
    const float* ln2_b  = (const float*)d_in[9];
    const float* mlp_w1 = (const float*)d_in[10];
    const float* mlp_b1 = (const float*)d_in[11];
    const float* mlp_w2 = (const float*)d_in[12];
    const float* mlp_b2 = (const float*)d_in[13];
    float* out = (float*)d_out;

    float *p_pos, *p_x, *p_y, *p_o, *p_qkv, *p_h;
    cudaGetSymbolAddress((void**)&p_pos, g_pos);
    cudaGetSymbolAddress((void**)&p_x,   g_x);
    cudaGetSymbolAddress((void**)&p_y,   g_y);
    cudaGetSymbolAddress((void**)&p_o,   g_o);
    cudaGetSymbolAddress((void**)&p_qkv, g_qkv);
    cudaGetSymbolAddress((void**)&p_h,   g_h);

    pos_embed_kernel<<<(NTOK * DIM + 255) / 256, 256>>>(p_pos);
    embed_kernel<<<dim3(NTOK / 64, DIM / 64, BATCH), 256>>>(
        c_f, conv_w, conv_b, p_pos, p_x);

    for (int l = 0; l < DEPTH; l++) {
        layernorm_kernel<<<ROWS, 256>>>(p_x, ln1_w + l * DIM, ln1_b + l * DIM, p_y);
        sgemm_ep_kernel<<<dim3(QKV3 / BN, ROWS / BM), 256>>>(
            ROWS, QKV3, DIM, p_y, qkv_w + (size_t)l * DIM * QKV3,
            nullptr, nullptr, p_qkv, 0);
        flash_attn_kernel<<<dim3(NTOK / QT, HEADS, BATCH), 256>>>(p_qkv, p_o);
        sgemm_ep_kernel<<<dim3(DIM / BN, ROWS / BM), 256>>>(
            ROWS, DIM, DIM, p_o, out_w + (size_t)l * DIM * DIM,
            out_b + l * DIM, p_x, p_x, 0);
        layernorm_kernel<<<ROWS, 256>>>(p_x, ln2_w + l * DIM, ln2_b + l * DIM, p_y);
        sgemm_ep_kernel<<<dim3(MLPD / BN, ROWS / BM), 256>>>(
            ROWS, MLPD, DIM, p_y, mlp_w1 + (size_t)l * DIM * MLPD,
            mlp_b1 + l * MLPD, nullptr, p_h, 1);
        sgemm_ep_kernel<<<dim3(DIM / BN, ROWS / BM), 256>>>(
            ROWS, DIM, MLPD, p_h, mlp_w2 + (size_t)l * MLPD * DIM,
            mlp_b2 + l * DIM, p_x, p_x, 0);
    }

    transpose_out_kernel<<<dim3(NTOK / 32, DIM / 32, BATCH), dim3(32, 8)>>>(p_x, out);
}

// round 3
// speedup vs baseline: 1.6166x; 1.6166x over previous
#include <cuda_runtime.h>
#include <cuda_bf16.h>
#include <math.h>
#include <stdint.h>

#define DIM 768
#define NTOK 1024
#define BATCH 4
#define ROWS (BATCH * NTOK)        // 4096
#define F_DIM 256
#define HEADS 12
#define DHEAD 64
#define QKV3 (3 * DIM)             // 2304
#define MLPD 3072
#define DEPTH 8
#define LN_EPS 1e-5f

// ============================================================================
// Helpers
// ============================================================================
__device__ __forceinline__ uint32_t smem_u32(const void* p) {
    uint32_t a;
    asm("{ .reg .u64 t; cvta.to.shared.u64 t, %1; cvt.u32.u64 %0, t; }"
        : "=r"(a) : "l"(p));
    return a;
}
#define SW128(o) ((o) ^ (((o) >> 3) & 0x70))

__device__ __forceinline__ void cp16(uint32_t s, const void* g) {
    asm volatile("cp.async.cg.shared.global [%0], [%1], 16;" :: "r"(s), "l"(g));
}
#define CP_COMMIT() asm volatile("cp.async.commit_group;" ::: "memory")
#define CP_WAIT2()  asm volatile("cp.async.wait_group 2;" ::: "memory")

#define LDSM_X4(r0, r1, r2, r3, addr) \
    asm volatile("ldmatrix.sync.aligned.m8n8.x4.shared.b16 {%0,%1,%2,%3}, [%4];" \
        : "=r"(r0), "=r"(r1), "=r"(r2), "=r"(r3) : "r"(addr))

__device__ __forceinline__ void mma_bf16(float* c, const uint32_t* a, const uint32_t* b) {
    asm volatile(
        "mma.sync.aligned.m16n8k16.row.col.f32.bf16.bf16.f32 "
        "{%0,%1,%2,%3}, {%4,%5,%6,%7}, {%8,%9}, {%0,%1,%2,%3};"
        : "+f"(c[0]), "+f"(c[1]), "+f"(c[2]), "+f"(c[3])
        : "r"(a[0]), "r"(a[1]), "r"(a[2]), "r"(a[3]), "r"(b[0]), "r"(b[1]));
}

__device__ __forceinline__ void split2(float v, __nv_bfloat16& h, __nv_bfloat16& l) {
    h = __float2bfloat16(v);
    l = __float2bfloat16(v - __bfloat162float(h));
}
__device__ __forceinline__ float gelu_f(float v) {
    return 0.5f * v * (1.0f + erff(v * 0.7071067811865475f));
}

// ============================================================================
// Scratch (device globals)
// ============================================================================
__device__ __align__(16) float g_pos[NTOK * DIM];
__device__ __align__(16) float g_x  [ROWS * DIM];
__device__ __align__(16) float g_qkv[ROWS * QKV3];
__device__ __align__(16) __nv_bfloat16 g_yh[ROWS * DIM],  g_yl[ROWS * DIM];
__device__ __align__(16) __nv_bfloat16 g_oh[ROWS * DIM],  g_ol[ROWS * DIM];
__device__ __align__(16) __nv_bfloat16 g_hh[ROWS * MLPD], g_hl[ROWS * MLPD];
// transposed + split weights: [L][N][K]
__device__ __align__(16) __nv_bfloat16 g_qkvw_h[DEPTH * QKV3 * DIM], g_qkvw_l[DEPTH * QKV3 * DIM];
__device__ __align__(16) __nv_bfloat16 g_outw_h[DEPTH * DIM * DIM],  g_outw_l[DEPTH * DIM * DIM];
__device__ __align__(16) __nv_bfloat16 g_m1w_h [DEPTH * MLPD * DIM], g_m1w_l [DEPTH * MLPD * DIM];
__device__ __align__(16) __nv_bfloat16 g_m2w_h [DEPTH * DIM * MLPD], g_m2w_l [DEPTH * DIM * MLPD];

// ============================================================================
// Position embedding
// ============================================================================
__global__ void pos_embed_kernel(float* __restrict__ pos) {
    int idx = blockIdx.x * blockDim.x + threadIdx.x;
    if (idx >= NTOK * DIM) return;
    int n = idx / DIM, d = idx % DIM;
    int r = n >> 5, c = n & 31;
    int id = (d < 384) ? d : d - 384;
    float coord = (d < 384) ? (float)(r + 1) : (float)(c + 1);
    float ang = coord / (32.0f + 1e-6f) * 6.283185307179586f;
    float ex = (float)(2 * (id / 2)) / 384.0f;
    float p = ang / powf(10000.0f, ex);
    pos[idx] = (id & 1) ? cosf(p) : sinf(p);
}

// ============================================================================
// Embed GEMM (small, SIMT fp32)
// ============================================================================
__global__ __launch_bounds__(256) void embed_kernel(
    const float* __restrict__ cf, const float* __restrict__ w,
    const float* __restrict__ bias, const float* __restrict__ pos,
    float* __restrict__ x)
{
    __shared__ float As[16][64];
    __shared__ float Bs[16][68];
    int b  = blockIdx.z;
    int n0 = blockIdx.x * 64, d0 = blockIdx.y * 64;
    int tid = threadIdx.x;
    int ty = tid / 16, tx = tid % 16;
    float acc[4][4] = {};
    const float* cfb = cf + (size_t)b * F_DIM * NTOK;
    for (int k0 = 0; k0 < F_DIM; k0 += 16) {
        #pragma unroll
        for (int it = 0; it < 4; it++) {
            int idx = tid + it * 256;
            As[idx >> 6][idx & 63] = cfb[(size_t)(k0 + (idx >> 6)) * NTOK + n0 + (idx & 63)];
        }
        #pragma unroll
        for (int it = 0; it < 4; it++) {
            int idx = tid + it * 256;
            Bs[idx & 15][idx >> 4] = w[(size_t)(d0 + (idx >> 4)) * F_DIM + k0 + (idx & 15)];
        }
        __syncthreads();
        #pragma unroll
        for (int kk = 0; kk < 16; kk++) {
            float a[4], bb[4];
            #pragma unroll
            for (int i = 0; i < 4; i++) a[i]  = As[kk][ty * 4 + i];
            #pragma unroll
            for (int j = 0; j < 4; j++) bb[j] = Bs[kk][tx * 4 + j];
            #pragma unroll
            for (int i = 0; i < 4; i++)
                #pragma unroll
                for (int j = 0; j < 4; j++)
                    acc[i][j] += a[i] * bb[j];
        }
        __syncthreads();
    }
    #pragma unroll
    for (int i = 0; i < 4; i++) {
        int n = n0 + ty * 4 + i;
        #pragma unroll
        for (int j = 0; j < 4; j++) {
            int d = d0 + tx * 4 + j;
            x[((size_t)b * NTOK + n) * DIM + d] = acc[i][j] + bias[d] + pos[(size_t)n * DIM + d];
        }
    }
}

// ============================================================================
// Weight transpose + bf16 split: w[l][K][N] -> hi/lo[l][N][K]
// ============================================================================
__global__ void wsplit_kernel(const float* __restrict__ w,
                              __nv_bfloat16* __restrict__ hi,
                              __nv_bfloat16* __restrict__ lo, int K, int N)
{
    __shared__ float t[32][33];
    int l = blockIdx.z;
    int n0 = blockIdx.x * 32, k0 = blockIdx.y * 32;
    int tx = threadIdx.x, ty = threadIdx.y;
    const float* wl = w + (size_t)l * K * N;
    for (int i = ty; i < 32; i += 8)
        t[i][tx] = wl[(size_t)(k0 + i) * N + n0 + tx];
    __syncthreads();
    size_t ob = (size_t)l * K * N;
    for (int i = ty; i < 32; i += 8) {
        float v = t[tx][i];  // = wl[k0+tx][n0+i]
        __nv_bfloat16 h, lw;
        split2(v, h, lw);
        size_t o = ob + (size_t)(n0 + i) * K + k0 + tx;
        hi[o] = h; lo[o] = lw;
    }
}

// ============================================================================
// LayerNorm -> split bf16 hi/lo
// ============================================================================
__global__ __launch_bounds__(256) void ln_split_kernel(
    const float* __restrict__ x, const float* __restrict__ w,
    const float* __restrict__ bias,
    __nv_bfloat16* __restrict__ yh, __nv_bfloat16* __restrict__ yl)
{
    int row = blockIdx.x;
    const float* xr = x + (size_t)row * DIM;
    float s = 0.f, ss = 0.f;
    float v[3];
    #pragma unroll
    for (int it = 0; it < 3; it++) {
        v[it] = xr[threadIdx.x + it * 256];
        s += v[it]; ss += v[it] * v[it];
    }
    __shared__ float red[64];
    #pragma unroll
    for (int off = 16; off; off >>= 1) {
        s  += __shfl_down_sync(0xffffffffu, s,  off);
        ss += __shfl_down_sync(0xffffffffu, ss, off);
    }
    int warp = threadIdx.x >> 5, lane = threadIdx.x & 31;
    if (lane == 0) { red[warp] = s; red[32 + warp] = ss; }
    __syncthreads();
    if (warp == 0) {
        s  = (lane < 8) ? red[lane] : 0.f;
        ss = (lane < 8) ? red[32 + lane] : 0.f;
        #pragma unroll
        for (int off = 4; off; off >>= 1) {
            s  += __shfl_down_sync(0xffffffffu, s,  off);
            ss += __shfl_down_sync(0xffffffffu, ss, off);
        }
        if (lane == 0) { red[0] = s; red[1] = ss; }
    }
    __syncthreads();
    float mu  = red[0] * (1.0f / DIM);
    float var = red[1] * (1.0f / DIM) - mu * mu;
    float inv = rsqrtf(var + LN_EPS);
    #pragma unroll
    for (int it = 0; it < 3; it++) {
        int i = threadIdx.x + it * 256;
        float y = (v[it] - mu) * inv * w[i] + bias[i];
        __nv_bfloat16 h, l;
        split2(y, h, l);
        yh[(size_t)row * DIM + i] = h;
        yl[(size_t)row * DIM + i] = l;
    }
}

// ============================================================================
// Tensor-core GEMM via mma.sync (bf16x3 split, fp32 accum).
// C[4096, N] = A[4096, K] @ Bt[N, K]^T  (+bias)(+gelu)(+resid)
// CTA tile 128x128, BK=32, 8 warps (2m x 4n), warp tile 64x32.
// SMEM: 4 tiles (Ah/Al/Bh/Bl) x 128 rows x 64B, SW128 swizzle, 3 stages.
// ============================================================================
#define STG_BYTES 32768
#define MMA_SMEM  (3 * STG_BYTES)   // 98304

__device__ __forceinline__ void issue_stage(
    int ch, int nch, int K, int tid, uint32_t sbase,
    const __nv_bfloat16* s0, const __nv_bfloat16* s1,
    const __nv_bfloat16* s2, const __nv_bfloat16* s3)
{
    if (ch < nch) {
        int k0 = ch * 32;
        uint32_t sb0 = sbase + (uint32_t)(ch % 3) * STG_BYTES;
        const __nv_bfloat16* srcs[4] = { s0, s1, s2, s3 };
        #pragma unroll
        for (int t = 0; t < 4; t++) {
            #pragma unroll
            for (int i = 0; i < 2; i++) {
                int idx = tid + i * 256;
                int r = idx >> 2, c = idx & 3;
                const void* g = (const char*)srcs[t] + ((size_t)r * K + k0 + c * 8) * 2;
                cp16(sb0 + t * 8192 + SW128((uint32_t)(r * 64 + c * 16)), g);
            }
        }
    }
    CP_COMMIT();
}

__global__ __launch_bounds__(256) void mma_gemm_kernel(
    int K, int N,
    const __nv_bfloat16* __restrict__ Ah, const __nv_bfloat16* __restrict__ Al,
    const __nv_bfloat16* __restrict__ Bh, const __nv_bfloat16* __restrict__ Bl,
    const float* __restrict__ bias, const float* __restrict__ resid,
    float* __restrict__ outf,
    __nv_bfloat16* __restrict__ oh, __nv_bfloat16* __restrict__ ol,
    int gelu)
{
    extern __shared__ char smem[];
    uint32_t sbase = smem_u32(smem);
    int tid = threadIdx.x, wid = tid >> 5, lane = tid & 31;
    int n0 = blockIdx.x * 128, m0 = blockIdx.y * 128;
    const __nv_bfloat16* s0 = Ah + (size_t)m0 * K;
    const __nv_bfloat16* s1 = Al + (size_t)m0 * K;
    const __nv_bfloat16* s2 = Bh + (size_t)n0 * K;
    const __nv_bfloat16* s3 = Bl + (size_t)n0 * K;
    int nch = K / 32;

    int wm = wid >> 2, wn = wid & 3;
    uint32_t lrow = lane & 15, lhalf = lane >> 4;

    float acc[4][4][4] = {};

    issue_stage(0, nch, K, tid, sbase, s0, s1, s2, s3);
    issue_stage(1, nch, K, tid, sbase, s0, s1, s2, s3);
    issue_stage(2, nch, K, tid, sbase, s0, s1, s2, s3);

    for (int ch = 0; ch < nch; ch++) {
        CP_WAIT2();
        __syncthreads();
        uint32_t st = sbase + (uint32_t)(ch % 3) * STG_BYTES;
        uint32_t aH = st, aL = st + 8192, bH = st + 16384, bL = st + 24576;
        #pragma unroll
        for (int ks = 0; ks < 2; ks++) {
            uint32_t koff = (uint32_t)(ks * 2 + lhalf) * 16;
            uint32_t ah[4][4], al[4][4], bh[4][2], bl[4][2];
            #pragma unroll
            for (int mf = 0; mf < 4; mf++) {
                uint32_t ro = (uint32_t)((wm * 64 + mf * 16 + lrow) * 64) + koff;
                LDSM_X4(ah[mf][0], ah[mf][1], ah[mf][2], ah[mf][3], aH + SW128(ro));
                LDSM_X4(al[mf][0], al[mf][1], al[mf][2], al[mf][3], aL + SW128(ro));
            }
            #pragma unroll
            for (int nf2 = 0; nf2 < 2; nf2++) {
                uint32_t ro = (uint32_t)((wn * 32 + nf2 * 16 + lrow) * 64) + koff;
                uint32_t t0, t1, t2, t3;
                LDSM_X4(t0, t1, t2, t3, bH + SW128(ro));
                bh[nf2 * 2][0] = t0; bh[nf2 * 2 + 1][0] = t1;
                bh[nf2 * 2][1] = t2; bh[nf2 * 2 + 1][1] = t3;
                LDSM_X4(t0, t1, t2, t3, bL + SW128(ro));
                bl[nf2 * 2][0] = t0; bl[nf2 * 2 + 1][0] = t1;
                bl[nf2 * 2][1] = t2; bl[nf2 * 2 + 1][1] = t3;
            }
            #pragma unroll
            for (int mf = 0; mf < 4; mf++) {
                #pragma unroll
                for (int nf = 0; nf < 4; nf++) {
                    mma_bf16(acc[mf][nf], ah[mf], bh[nf]);
                    mma_bf16(acc[mf][nf], ah[mf], bl[nf]);
                    mma_bf16(acc[mf][nf], al[mf], bh[nf]);
                }
            }
        }
        __syncthreads();
        issue_stage(ch + 3, nch, K, tid, sbase, s0, s1, s2, s3);
    }

    // Epilogue: registers -> global, fused bias/gelu/resid, fp32 or split bf16
    int g = lane >> 2, tg = lane & 3;
    #pragma unroll
    for (int mf = 0; mf < 4; mf++) {
        #pragma unroll
        for (int nf = 0; nf < 4; nf++) {
            int col = n0 + wn * 32 + nf * 8 + tg * 2;
            float bv0 = bias ? __ldg(bias + col)     : 0.f;
            float bv1 = bias ? __ldg(bias + col + 1) : 0.f;
            #pragma unroll
            for (int half = 0; half < 2; half++) {
                int row = m0 + wm * 64 + mf * 16 + g + half * 8;
                float v0 = acc[mf][nf][half * 2 + 0] + bv0;
                float v1 = acc[mf][nf][half * 2 + 1] + bv1;
                if (gelu) { v0 = gelu_f(v0); v1 = gelu_f(v1); }
                size_t gb = (size_t)row * N + col;
                if (resid) {
                    float2 rr = *(const float2*)(resid + gb);
                    v0 += rr.x; v1 += rr.y;
                }
                if (outf) {
                    *(float2*)(outf + gb) = make_float2(v0, v1);
                } else {
                    __nv_bfloat16 h0, l0, h1, l1;
                    split2(v0, h0, l0); split2(v1, h1, l1);
                    *(__nv_bfloat162*)(oh + gb) = __nv_bfloat162(h0, h1);
                    *(__nv_bfloat162*)(ol + gb) = __nv_bfloat162(l0, l1);
                }
            }
        }
    }
}

// ============================================================================
// Flash attention (fp32, online softmax) -> split bf16 output
// ============================================================================
#define QT 64
#define KT 32

__global__ __launch_bounds__(256) void flash_attn_kernel(
    const float* __restrict__ qkv,
    __nv_bfloat16* __restrict__ ohp, __nv_bfloat16* __restrict__ olp)
{
    __shared__ float Ks[KT][65];
    __shared__ float Vs[KT][65];
    int qb = blockIdx.x, h = blockIdx.y, b = blockIdx.z;
    int tid = threadIdx.x;
    int r = tid >> 2, l4 = tid & 3;
    int row = b * NTOK + qb * QT + r;
    int dbase = l4 * 16;

    const float* qp = qkv + (size_t)row * QKV3 + h * DHEAD + dbase;
    float q[16];
    #pragma unroll
    for (int i = 0; i < 16; i++) q[i] = qp[i];

    float oacc[16] = {};
    float m = -1e30f, lsum = 0.f;
    const float scale = 0.125f;

    for (int kt = 0; kt < NTOK; kt += KT) {
        #pragma unroll
        for (int it = 0; it < 8; it++) {
            int idx = tid + it * 256;
            int j = idx >> 6, d = idx & 63;
            size_t base = (size_t)(b * NTOK + kt + j) * QKV3 + h * DHEAD + d;
            Ks[j][d] = qkv[base + DIM];
            Vs[j][d] = qkv[base + 2 * DIM];
        }
        __syncthreads();
        float s[KT];
        float cmax = -1e30f;
        #pragma unroll
        for (int j = 0; j < KT; j++) {
            float p = 0.f;
            #pragma unroll
            for (int i = 0; i < 16; i++) p += q[i] * Ks[j][dbase + i];
            p += __shfl_xor_sync(0xffffffffu, p, 1);
            p += __shfl_xor_sync(0xffffffffu, p, 2);
            p *= scale;
            s[j] = p;
            cmax = fmaxf(cmax, p);
        }
        float mnew = fmaxf(m, cmax);
        float corr = __expf(m - mnew);
        lsum *= corr;
        #pragma unroll
        for (int i = 0; i < 16; i++) oacc[i] *= corr;
        #pragma unroll
        for (int j = 0; j < KT; j++) {
            float p = __expf(s[j] - mnew);
            lsum += p;
            #pragma unroll
            for (int i = 0; i < 16; i++) oacc[i] += p * Vs[j][dbase + i];
        }
        m = mnew;
        __syncthreads();
    }
    float inv = 1.f / lsum;
    size_t ob = (size_t)row * DIM + h * DHEAD + dbase;
    #pragma unroll
    for (int i = 0; i < 16; i++) {
        float v = oacc[i] * inv;
        __nv_bfloat16 hh, ll;
        split2(v, hh, ll);
        ohp[ob + i] = hh;
        olp[ob + i] = ll;
    }
}

// ============================================================================
// Final transpose: x[b,n,d] -> out[b,d,n]
// ============================================================================
__global__ void transpose_out_kernel(const float* __restrict__ x,
                                     float* __restrict__ out)
{
    __shared__ float t[32][33];
    int b = blockIdx.z;
    int n0 = blockIdx.x * 32, d0 = blockIdx.y * 32;
    int tx = threadIdx.x, ty = threadIdx.y;
    for (int i = ty; i < 32; i += 8)
        t[i][tx] = x[((size_t)b * NTOK + n0 + i) * DIM + d0 + tx];
    __syncthreads();
    for (int i = ty; i < 32; i += 8)
        out[((size_t)b * DIM + d0 + i) * NTOK + n0 + tx] = t[tx][i];
}

// ============================================================================
// Host orchestration
// ============================================================================
extern "C" void kernel_launch(void* const* d_in, const int* in_sizes, int n_in,
                              void* d_out, int out_size)
{
    const float* c_f    = (const float*)d_in[0];
    const float* conv_w = (const float*)d_in[1];
    const float* conv_b = (const float*)d_in[2];
    const float* ln1_w  = (const float*)d_in[3];
    const float* ln1_b  = (const float*)d_in[4];
    const float* qkv_w  = (const float*)d_in[5];
    const float* out_w  = (const float*)d_in[6];
    const float* out_b  = (const float*)d_in[7];
    const float* ln2_w  = (const float*)d_in[8];
    const float* ln2_b  = (const float*)d_in[9];
    const float* mlp_w1 = (const float*)d_in[10];
    const float* mlp_b1 = (const float*)d_in[11];
    const float* mlp_w2 = (const float*)d_in[12];
    const float* mlp_b2 = (const float*)d_in[13];
    float* out = (float*)d_out;

    cudaFuncSetAttribute(mma_gemm_kernel,
                         cudaFuncAttributeMaxDynamicSharedMemorySize, MMA_SMEM);

    float *p_pos, *p_x, *p_qkv;
    __nv_bfloat16 *p_yh, *p_yl, *p_oh, *p_ol, *p_hh, *p_hl;
    __nv_bfloat16 *p_qwh, *p_qwl, *p_owh, *p_owl, *p_m1h, *p_m1l, *p_m2h, *p_m2l;
    cudaGetSymbolAddress((void**)&p_pos, g_pos);
    cudaGetSymbolAddress((void**)&p_x,   g_x);
    cudaGetSymbolAddress((void**)&p_qkv, g_qkv);
    cudaGetSymbolAddress((void**)&p_yh,  g_yh);
    cudaGetSymbolAddress((void**)&p_yl,  g_yl);
    cudaGetSymbolAddress((void**)&p_oh,  g_oh);
    cudaGetSymbolAddress((void**)&p_ol,  g_ol);
    cudaGetSymbolAddress((void**)&p_hh,  g_hh);
    cudaGetSymbolAddress((void**)&p_hl,  g_hl);
    cudaGetSymbolAddress((void**)&p_qwh, g_qkvw_h);
    cudaGetSymbolAddress((void**)&p_qwl, g_qkvw_l);
    cudaGetSymbolAddress((void**)&p_owh, g_outw_h);
    cudaGetSymbolAddress((void**)&p_owl, g_outw_l);
    cudaGetSymbolAddress((void**)&p_m1h, g_m1w_h);
    cudaGetSymbolAddress((void**)&p_m1l, g_m1w_l);
    cudaGetSymbolAddress((void**)&p_m2h, g_m2w_h);
    cudaGetSymbolAddress((void**)&p_m2l, g_m2w_l);

    // weight transpose + split (once per launch)
    dim3 wb(32, 8);
    wsplit_kernel<<<dim3(QKV3 / 32, DIM / 32, DEPTH), wb>>>(qkv_w, p_qwh, p_qwl, DIM, QKV3);
    wsplit_kernel<<<dim3(DIM / 32, DIM / 32, DEPTH), wb>>>(out_w, p_owh, p_owl, DIM, DIM);
    wsplit_kernel<<<dim3(MLPD / 32, DIM / 32, DEPTH), wb>>>(mlp_w1, p_m1h, p_m1l, DIM, MLPD);
    wsplit_kernel<<<dim3(DIM / 32, MLPD / 32, DEPTH), wb>>>(mlp_w2, p_m2h, p_m2l, MLPD, DIM);

    pos_embed_kernel<<<(NTOK * DIM + 255) / 256, 256>>>(p_pos);
    embed_kernel<<<dim3(NTOK / 64, DIM / 64, BATCH), 256>>>(c_f, conv_w, conv_b, p_pos, p_x);

    for (int l = 0; l < DEPTH; l++) {
        ln_split_kernel<<<ROWS, 256>>>(p_x, ln1_w + l * DIM, ln1_b + l * DIM, p_yh, p_yl);
        mma_gemm_kernel<<<dim3(QKV3 / 128, ROWS / 128), 256, MMA_SMEM>>>(
            DIM, QKV3, p_yh, p_yl,
            p_qwh + (size_t)l * QKV3 * DIM, p_qwl + (size_t)l * QKV3 * DIM,
            nullptr, nullptr, p_qkv, nullptr, nullptr, 0);
        flash_attn_kernel<<<dim3(NTOK / QT, HEADS, BATCH), 256>>>(p_qkv, p_oh, p_ol);
        mma_gemm_kernel<<<dim3(DIM / 128, ROWS / 128), 256, MMA_SMEM>>>(
            DIM, DIM, p_oh, p_ol,
            p_owh + (size_t)l * DIM * DIM, p_owl + (size_t)l * DIM * DIM,
            out_b + l * DIM, p_x, p_x, nullptr, nullptr, 0);
        ln_split_kernel<<<ROWS, 256>>>(p_x, ln2_w + l * DIM, ln2_b + l * DIM, p_yh, p_yl);
        mma_gemm_kernel<<<dim3(MLPD / 128, ROWS / 128), 256, MMA_SMEM>>>(
            DIM, MLPD, p_yh, p_yl,
            p_m1h + (size_t)l * MLPD * DIM, p_m1l + (size_t)l * MLPD * DIM,
            mlp_b1 + l * MLPD, nullptr, nullptr, p_hh, p_hl, 1);
        mma_gemm_kernel<<<dim3(DIM / 128, ROWS / 128), 256, MMA_SMEM>>>(
            MLPD, DIM, p_hh, p_hl,
            p_m2h + (size_t)l * DIM * MLPD, p_m2l + (size_t)l * DIM * MLPD,
            mlp_b2 + l * DIM, p_x, p_x, nullptr, nullptr, 0);
    }

    transpose_out_kernel<<<dim3(NTOK / 32, DIM / 32, BATCH), dim3(32, 8)>>>(p_x, out);
}

// round 6
// speedup vs baseline: 4.1556x; 2.5705x over previous
#include <cuda_runtime.h>
#include <cuda_bf16.h>
#include <math.h>
#include <stdint.h>

#define DIM 768
#define NTOK 1024
#define BATCH 4
#define ROWS (BATCH * NTOK)        // 4096
#define F_DIM 256
#define HEADS 12
#define DHEAD 64
#define QKV3 (3 * DIM)             // 2304
#define MLPD 3072
#define DEPTH 8
#define LN_EPS 1e-5f

// ============================================================================
// Helpers
// ============================================================================
__device__ __forceinline__ uint32_t smem_u32(const void* p) {
    uint32_t a;
    asm("{ .reg .u64 t; cvta.to.shared.u64 t, %1; cvt.u32.u64 %0, t; }"
        : "=r"(a) : "l"(p));
    return a;
}
#define SW128(o) ((o) ^ (((o) >> 3) & 0x70))

__device__ __forceinline__ void cp16(uint32_t s, const void* g) {
    asm volatile("cp.async.cg.shared.global [%0], [%1], 16;" :: "r"(s), "l"(g));
}
#define CP_COMMIT() asm volatile("cp.async.commit_group;" ::: "memory")
#define CP_WAIT2()  asm volatile("cp.async.wait_group 2;" ::: "memory")
#define CP_WAIT1()  asm volatile("cp.async.wait_group 1;" ::: "memory")

#define LDSM_X4(r0, r1, r2, r3, addr) \
    asm volatile("ldmatrix.sync.aligned.m8n8.x4.shared.b16 {%0,%1,%2,%3}, [%4];" \
        : "=r"(r0), "=r"(r1), "=r"(r2), "=r"(r3) : "r"(addr))
#define LDSM_X4_T(r0, r1, r2, r3, addr) \
    asm volatile("ldmatrix.sync.aligned.m8n8.x4.trans.shared.b16 {%0,%1,%2,%3}, [%4];" \
        : "=r"(r0), "=r"(r1), "=r"(r2), "=r"(r3) : "r"(addr))

__device__ __forceinline__ void mma_bf16(float* c, const uint32_t* a, const uint32_t* b) {
    asm volatile(
        "mma.sync.aligned.m16n8k16.row.col.f32.bf16.bf16.f32 "
        "{%0,%1,%2,%3}, {%4,%5,%6,%7}, {%8,%9}, {%0,%1,%2,%3};"
        : "+f"(c[0]), "+f"(c[1]), "+f"(c[2]), "+f"(c[3])
        : "r"(a[0]), "r"(a[1]), "r"(a[2]), "r"(a[3]), "r"(b[0]), "r"(b[1]));
}
__device__ __forceinline__ void mma4(float* c, const uint32_t* a, uint32_t b0, uint32_t b1) {
    uint32_t b[2] = { b0, b1 };
    mma_bf16(c, a, b);
}

__device__ __forceinline__ void split2(float v, __nv_bfloat16& h, __nv_bfloat16& l) {
    h = __float2bfloat16(v);
    l = __float2bfloat16(v - __bfloat162float(h));
}
__device__ __forceinline__ void pack_split(float a, float b, uint32_t& hi, uint32_t& lo) {
    __nv_bfloat16 ha = __float2bfloat16(a);
    __nv_bfloat16 hb = __float2bfloat16(b);
    __nv_bfloat162 H(ha, hb);
    __nv_bfloat162 L(__float2bfloat16(a - __bfloat162float(ha)),
                     __float2bfloat16(b - __bfloat162float(hb)));
    hi = *(uint32_t*)&H;
    lo = *(uint32_t*)&L;
}
__device__ __forceinline__ float gelu_f(float v) {
    return 0.5f * v * (1.0f + erff(v * 0.7071067811865475f));
}

// ============================================================================
// Scratch (device globals)
// ============================================================================
__device__ __align__(16) float g_x  [ROWS * DIM];
__device__ __align__(16) __nv_bfloat16 g_yh[ROWS * DIM],  g_yl[ROWS * DIM];
__device__ __align__(16) __nv_bfloat16 g_oh[ROWS * DIM],  g_ol[ROWS * DIM];
__device__ __align__(16) __nv_bfloat16 g_hh[ROWS * MLPD], g_hl[ROWS * MLPD];
__device__ __align__(16) __nv_bfloat16 g_qh[ROWS * QKV3], g_ql[ROWS * QKV3];
// transposed + split weights: [L][N][K]
__device__ __align__(16) __nv_bfloat16 g_qkvw_h[DEPTH * QKV3 * DIM], g_qkvw_l[DEPTH * QKV3 * DIM];
__device__ __align__(16) __nv_bfloat16 g_outw_h[DEPTH * DIM * DIM],  g_outw_l[DEPTH * DIM * DIM];
__device__ __align__(16) __nv_bfloat16 g_m1w_h [DEPTH * MLPD * DIM], g_m1w_l [DEPTH * MLPD * DIM];
__device__ __align__(16) __nv_bfloat16 g_m2w_h [DEPTH * DIM * MLPD], g_m2w_l [DEPTH * DIM * MLPD];

// ============================================================================
// Combined weight transpose + bf16 split (one launch).
// Per layer: qkv 72x24, out 24x24, m1 96x24, m2 24x96 (x = n0/32, y = k0/32)
// ============================================================================
#define WL_BLOCKS 6912
__global__ void wsplit_all_kernel(
    const float* __restrict__ qkv_w, const float* __restrict__ out_w,
    const float* __restrict__ m1w,   const float* __restrict__ m2w,
    __nv_bfloat16* qh, __nv_bfloat16* ql,
    __nv_bfloat16* owh, __nv_bfloat16* owl,
    __nv_bfloat16* m1h, __nv_bfloat16* m1l,
    __nv_bfloat16* m2h, __nv_bfloat16* m2l)
{
    int z = blockIdx.x;
    int l = z / WL_BLOCKS, r = z % WL_BLOCKS;
    const float* w; __nv_bfloat16 *hi, *lo; int K, N, nx, ny;
    if (r < 1728)      { w = qkv_w; hi = qh;  lo = ql;  K = DIM;  N = QKV3; nx = r % 72; ny = r / 72; }
    else if (r < 2304) { int rr = r - 1728; w = out_w; hi = owh; lo = owl; K = DIM;  N = DIM;  nx = rr % 24; ny = rr / 24; }
    else if (r < 4608) { int rr = r - 2304; w = m1w;   hi = m1h; lo = m1l; K = DIM;  N = MLPD; nx = rr % 96; ny = rr / 96; }
    else               { int rr = r - 4608; w = m2w;   hi = m2h; lo = m2l; K = MLPD; N = DIM;  nx = rr % 24; ny = rr / 24; }
    __shared__ float t[32][33];
    int n0 = nx * 32, k0 = ny * 32;
    int tx = threadIdx.x, ty = threadIdx.y;
    const float* wl = w + (size_t)l * K * N;
    for (int i = ty; i < 32; i += 8)
        t[i][tx] = wl[(size_t)(k0 + i) * N + n0 + tx];
    __syncthreads();
    size_t ob = (size_t)l * K * N;
    for (int i = ty; i < 32; i += 8) {
        float v = t[tx][i];
        __nv_bfloat16 h, lw;
        split2(v, h, lw);
        size_t o = ob + (size_t)(n0 + i) * K + k0 + tx;
        hi[o] = h; lo[o] = lw;
    }
}

// ============================================================================
// Embed GEMM with fused sine pos-embed
// ============================================================================
__device__ __forceinline__ float posval(int n, int d) {
    int r = n >> 5, c = n & 31;
    int id = (d < 384) ? d : d - 384;
    float coord = (d < 384) ? (float)(r + 1) : (float)(c + 1);
    float ang = coord * (6.283185307179586f / (32.0f + 1e-6f));
    float ex = (float)(2 * (id / 2)) * (1.0f / 384.0f);
    float p = ang / __powf(10000.0f, ex);
    return (id & 1) ? cosf(p) : sinf(p);
}

__global__ __launch_bounds__(256) void embed_kernel(
    const float* __restrict__ cf, const float* __restrict__ w,
    const float* __restrict__ bias, float* __restrict__ x)
{
    __shared__ float As[16][64];
    __shared__ float Bs[16][68];
    int b  = blockIdx.z;
    int n0 = blockIdx.x * 64, d0 = blockIdx.y * 64;
    int tid = threadIdx.x;
    int ty = tid / 16, tx = tid % 16;
    float acc[4][4] = {};
    const float* cfb = cf + (size_t)b * F_DIM * NTOK;
    for (int k0 = 0; k0 < F_DIM; k0 += 16) {
        #pragma unroll
        for (int it = 0; it < 4; it++) {
            int idx = tid + it * 256;
            As[idx >> 6][idx & 63] = cfb[(size_t)(k0 + (idx >> 6)) * NTOK + n0 + (idx & 63)];
        }
        #pragma unroll
        for (int it = 0; it < 4; it++) {
            int idx = tid + it * 256;
            Bs[idx & 15][idx >> 4] = w[(size_t)(d0 + (idx >> 4)) * F_DIM + k0 + (idx & 15)];
        }
        __syncthreads();
        #pragma unroll
        for (int kk = 0; kk < 16; kk++) {
            float a[4], bb[4];
            #pragma unroll
            for (int i = 0; i < 4; i++) a[i]  = As[kk][ty * 4 + i];
            #pragma unroll
            for (int j = 0; j < 4; j++) bb[j] = Bs[kk][tx * 4 + j];
            #pragma unroll
            for (int i = 0; i < 4; i++)
                #pragma unroll
                for (int j = 0; j < 4; j++)
                    acc[i][j] += a[i] * bb[j];
        }
        __syncthreads();
    }
    #pragma unroll
    for (int i = 0; i < 4; i++) {
        int n = n0 + ty * 4 + i;
        #pragma unroll
        for (int j = 0; j < 4; j++) {
            int d = d0 + tx * 4 + j;
            x[((size_t)b * NTOK + n) * DIM + d] = acc[i][j] + bias[d] + posval(n, d);
        }
    }
}

// ============================================================================
// LayerNorm -> split bf16 hi/lo
// ============================================================================
__global__ __launch_bounds__(256) void ln_split_kernel(
    const float* __restrict__ x, const float* __restrict__ w,
    const float* __restrict__ bias,
    __nv_bfloat16* __restrict__ yh, __nv_bfloat16* __restrict__ yl)
{
    int row = blockIdx.x;
    const float* xr = x + (size_t)row * DIM;
    float s = 0.f, ss = 0.f;
    float v[3];
    #pragma unroll
    for (int it = 0; it < 3; it++) {
        v[it] = xr[threadIdx.x + it * 256];
        s += v[it]; ss += v[it] * v[it];
    }
    __shared__ float red[64];
    #pragma unroll
    for (int off = 16; off; off >>= 1) {
        s  += __shfl_down_sync(0xffffffffu, s,  off);
        ss += __shfl_down_sync(0xffffffffu, ss, off);
    }
    int warp = threadIdx.x >> 5, lane = threadIdx.x & 31;
    if (lane == 0) { red[warp] = s; red[32 + warp] = ss; }
    __syncthreads();
    if (warp == 0) {
        s  = (lane < 8) ? red[lane] : 0.f;
        ss = (lane < 8) ? red[32 + lane] : 0.f;
        #pragma unroll
        for (int off = 4; off; off >>= 1) {
            s  += __shfl_down_sync(0xffffffffu, s,  off);
            ss += __shfl_down_sync(0xffffffffu, ss, off);
        }
        if (lane == 0) { red[0] = s; red[1] = ss; }
    }
    __syncthreads();
    float mu  = red[0] * (1.0f / DIM);
    float var = red[1] * (1.0f / DIM) - mu * mu;
    float inv = rsqrtf(var + LN_EPS);
    #pragma unroll
    for (int it = 0; it < 3; it++) {
        int i = threadIdx.x + it * 256;
        float y = (v[it] - mu) * inv * w[i] + bias[i];
        __nv_bfloat16 h, l;
        split2(y, h, l);
        yh[(size_t)row * DIM + i] = h;
        yl[(size_t)row * DIM + i] = l;
    }
}

// ============================================================================
// Tensor-core GEMM (bf16x3 split, fp32 accum), 4-stage cp.async pipeline,
// one __syncthreads per K-iter, issue-before-compute.
// ============================================================================
#define STG_BYTES 32768
#define MMA_SMEM  (4 * STG_BYTES)   // 131072

__device__ __forceinline__ void issue_stage(
    int ch, int nch, int K, int tid, uint32_t sbase,
    const __nv_bfloat16* s0, const __nv_bfloat16* s1,
    const __nv_bfloat16* s2, const __nv_bfloat16* s3)
{
    if (ch < nch) {
        int k0 = ch * 32;
        uint32_t sb0 = sbase + (uint32_t)(ch & 3) * STG_BYTES;
        const __nv_bfloat16* srcs[4] = { s0, s1, s2, s3 };
        #pragma unroll
        for (int t = 0; t < 4; t++) {
            #pragma unroll
            for (int i = 0; i < 2; i++) {
                int idx = tid + i * 256;
                int r = idx >> 2, c = idx & 3;
                const void* g = (const char*)srcs[t] + ((size_t)r * K + k0 + c * 8) * 2;
                cp16(sb0 + t * 8192 + SW128((uint32_t)(r * 64 + c * 16)), g);
            }
        }
    }
    CP_COMMIT();
}

__global__ __launch_bounds__(256) void mma_gemm_kernel(
    int K, int N,
    const __nv_bfloat16* __restrict__ Ah, const __nv_bfloat16* __restrict__ Al,
    const __nv_bfloat16* __restrict__ Bh, const __nv_bfloat16* __restrict__ Bl,
    const float* __restrict__ bias, const float* __restrict__ resid,
    float* __restrict__ outf,
    __nv_bfloat16* __restrict__ oh, __nv_bfloat16* __restrict__ ol,
    int gelu)
{
    extern __shared__ char smem[];
    uint32_t sbase = smem_u32(smem);
    int tid = threadIdx.x, wid = tid >> 5, lane = tid & 31;
    int n0 = blockIdx.x * 128, m0 = blockIdx.y * 128;
    const __nv_bfloat16* s0 = Ah + (size_t)m0 * K;
    const __nv_bfloat16* s1 = Al + (size_t)m0 * K;
    const __nv_bfloat16* s2 = Bh + (size_t)n0 * K;
    const __nv_bfloat16* s3 = Bl + (size_t)n0 * K;
    int nch = K / 32;

    int wm = wid >> 2, wn = wid & 3;
    uint32_t lrow = lane & 15, lhalf = lane >> 4;

    float acc[4][4][4] = {};

    issue_stage(0, nch, K, tid, sbase, s0, s1, s2, s3);
    issue_stage(1, nch, K, tid, sbase, s0, s1, s2, s3);
    issue_stage(2, nch, K, tid, sbase, s0, s1, s2, s3);

    for (int ch = 0; ch < nch; ch++) {
        CP_WAIT2();
        __syncthreads();
        issue_stage(ch + 3, nch, K, tid, sbase, s0, s1, s2, s3);
        uint32_t st = sbase + (uint32_t)(ch & 3) * STG_BYTES;
        uint32_t aH = st, aL = st + 8192, bH = st + 16384, bL = st + 24576;
        #pragma unroll
        for (int ks = 0; ks < 2; ks++) {
            uint32_t koff = (uint32_t)(ks * 2 + lhalf) * 16;
            uint32_t ah[4][4], al[4][4], bh[4][2], bl[4][2];
            #pragma unroll
            for (int mf = 0; mf < 4; mf++) {
                uint32_t ro = (uint32_t)((wm * 64 + mf * 16 + lrow) * 64) + koff;
                LDSM_X4(ah[mf][0], ah[mf][1], ah[mf][2], ah[mf][3], aH + SW128(ro));
                LDSM_X4(al[mf][0], al[mf][1], al[mf][2], al[mf][3], aL + SW128(ro));
            }
            #pragma unroll
            for (int nf2 = 0; nf2 < 2; nf2++) {
                uint32_t ro = (uint32_t)((wn * 32 + nf2 * 16 + lrow) * 64) + koff;
                uint32_t t0, t1, t2, t3;
                LDSM_X4(t0, t1, t2, t3, bH + SW128(ro));
                bh[nf2 * 2][0] = t0; bh[nf2 * 2 + 1][0] = t1;
                bh[nf2 * 2][1] = t2; bh[nf2 * 2 + 1][1] = t3;
                LDSM_X4(t0, t1, t2, t3, bL + SW128(ro));
                bl[nf2 * 2][0] = t0; bl[nf2 * 2 + 1][0] = t1;
                bl[nf2 * 2][1] = t2; bl[nf2 * 2 + 1][1] = t3;
            }
            #pragma unroll
            for (int mf = 0; mf < 4; mf++) {
                #pragma unroll
                for (int nf = 0; nf < 4; nf++) {
                    mma_bf16(acc[mf][nf], ah[mf], bh[nf]);
                    mma_bf16(acc[mf][nf], ah[mf], bl[nf]);
                    mma_bf16(acc[mf][nf], al[mf], bh[nf]);
                }
            }
        }
    }

    // Epilogue
    int g = lane >> 2, tg = lane & 3;
    #pragma unroll
    for (int mf = 0; mf < 4; mf++) {
        #pragma unroll
        for (int nf = 0; nf < 4; nf++) {
            int col = n0 + wn * 32 + nf * 8 + tg * 2;
            float bv0 = bias ? __ldg(bias + col)     : 0.f;
            float bv1 = bias ? __ldg(bias + col + 1) : 0.f;
            #pragma unroll
            for (int half = 0; half < 2; half++) {
                int row = m0 + wm * 64 + mf * 16 + g + half * 8;
                float v0 = acc[mf][nf][half * 2 + 0] + bv0;
                float v1 = acc[mf][nf][half * 2 + 1] + bv1;
                if (gelu) { v0 = gelu_f(v0); v1 = gelu_f(v1); }
                size_t gb = (size_t)row * N + col;
                if (resid) {
                    float2 rr = *(const float2*)(resid + gb);
                    v0 += rr.x; v1 += rr.y;
                }
                if (outf) {
                    *(float2*)(outf + gb) = make_float2(v0, v1);
                } else {
                    __nv_bfloat16 h0, l0, h1, l1;
                    split2(v0, h0, l0); split2(v1, h1, l1);
                    *(__nv_bfloat162*)(oh + gb) = __nv_bfloat162(h0, h1);
                    *(__nv_bfloat162*)(ol + gb) = __nv_bfloat162(l0, l1);
                }
            }
        }
    }
}

// ============================================================================
// Flash attention via mma.sync (bf16 split Q,K,V,P; fp32 softmax/accum).
// CTA: 128 q-rows x 1 head. 8 warps x 16 rows. K-tile = 64 keys.
// qkv split arrays: [ROWS][2304] hi/lo. Output: [ROWS][768] hi/lo.
// ============================================================================
#define ATT_SMEM 65536

__device__ __forceinline__ void attn_issue(
    int kt, int tid, uint32_t sb,
    const __nv_bfloat16* qh, const __nv_bfloat16* ql,
    size_t batch_row0, int kcol, int vcol)
{
    if (kt < 16) {
        uint32_t st = sb + (uint32_t)(kt & 1) * 32768;
        size_t rb = batch_row0 + (size_t)kt * 64;
        #pragma unroll
        for (int i = 0; i < 2; i++) {
            int idx = tid + i * 256;   // 512 units: r = key 0..63, c = 0..7
            int r = idx >> 3, c = idx & 7;
            size_t rowoff = (rb + r) * QKV3;
            uint32_t so = SW128((uint32_t)(r * 128 + c * 16));
            cp16(st +         so, (const char*)(qh + rowoff + kcol) + c * 16);
            cp16(st + 8192  + so, (const char*)(ql + rowoff + kcol) + c * 16);
            cp16(st + 16384 + so, (const char*)(qh + rowoff + vcol) + c * 16);
            cp16(st + 24576 + so, (const char*)(ql + rowoff + vcol) + c * 16);
        }
    }
    CP_COMMIT();
}

__global__ __launch_bounds__(256) void flash_mma_kernel(
    const __nv_bfloat16* __restrict__ qh, const __nv_bfloat16* __restrict__ ql,
    __nv_bfloat16* __restrict__ oh, __nv_bfloat16* __restrict__ ol)
{
    extern __shared__ char smem[];
    uint32_t sb = smem_u32(smem);
    int tid = threadIdx.x, wid = tid >> 5, lane = tid & 31;
    int qt = blockIdx.x;
    int b = blockIdx.y / HEADS, h = blockIdx.y % HEADS;
    int g = lane >> 2, tg = lane & 3;
    size_t batch_row0 = (size_t)b * NTOK;
    size_t qrow0 = batch_row0 + (size_t)qt * 128;
    int qcol = h * 64, kcol = DIM + h * 64, vcol = 2 * DIM + h * 64;

    // Stage Q (hi at 0, lo at 16384), swizzled 128B rows
    #pragma unroll
    for (int i = 0; i < 4; i++) {
        int idx = tid + i * 256;   // 1024 units
        int r = idx >> 3, c = idx & 7;
        size_t rowoff = (qrow0 + r) * QKV3 + qcol;
        uint32_t so = SW128((uint32_t)(r * 128 + c * 16));
        *(uint4*)(smem + so)         = *((const uint4*)(qh + rowoff) + c);
        *(uint4*)(smem + 16384 + so) = *((const uint4*)(ql + rowoff) + c);
    }
    __syncthreads();

    uint32_t ah[4][4], al[4][4];
    {
        uint32_t lrow = lane & 15, lh = lane >> 4;
        #pragma unroll
        for (int kf = 0; kf < 4; kf++) {
            uint32_t ro = (uint32_t)((wid * 16 + lrow) * 128) + kf * 32 + lh * 16;
            LDSM_X4(ah[kf][0], ah[kf][1], ah[kf][2], ah[kf][3], sb + SW128(ro));
            LDSM_X4(al[kf][0], al[kf][1], al[kf][2], al[kf][3], sb + 16384 + SW128(ro));
        }
    }
    __syncthreads();

    float m0v = -1e30f, m1v = -1e30f, l0 = 0.f, l1 = 0.f;
    float oacc[8][4] = {};
    const float scale = 0.125f;

    attn_issue(0, tid, sb, qh, ql, batch_row0, kcol, vcol);

    for (int kt = 0; kt < 16; kt++) {
        attn_issue(kt + 1, tid, sb, qh, ql, batch_row0, kcol, vcol);
        CP_WAIT1();
        __syncthreads();
        uint32_t kb = sb + (uint32_t)(kt & 1) * 32768;

        // S = Q @ K^T (3-split)
        float sc[8][4] = {};
        #pragma unroll
        for (int kg = 0; kg < 4; kg++) {
            #pragma unroll
            for (int kf = 0; kf < 4; kf++) {
                uint32_t ro = (uint32_t)((kg * 16 + (lane & 15)) * 128) + kf * 32 + (lane >> 4) * 16;
                uint32_t t0, t1, t2, t3, u0, u1, u2, u3;
                LDSM_X4(t0, t1, t2, t3, kb + SW128(ro));
                LDSM_X4(u0, u1, u2, u3, kb + 8192 + SW128(ro));
                mma4(sc[2 * kg],     ah[kf], t0, t2);
                mma4(sc[2 * kg],     ah[kf], u0, u2);
                mma4(sc[2 * kg],     al[kf], t0, t2);
                mma4(sc[2 * kg + 1], ah[kf], t1, t3);
                mma4(sc[2 * kg + 1], ah[kf], u1, u3);
                mma4(sc[2 * kg + 1], al[kf], t1, t3);
            }
        }

        // Online softmax
        float mx0 = -1e30f, mx1 = -1e30f;
        #pragma unroll
        for (int nf = 0; nf < 8; nf++) {
            #pragma unroll
            for (int i = 0; i < 4; i++) sc[nf][i] *= scale;
            mx0 = fmaxf(mx0, fmaxf(sc[nf][0], sc[nf][1]));
            mx1 = fmaxf(mx1, fmaxf(sc[nf][2], sc[nf][3]));
        }
        mx0 = fmaxf(mx0, __shfl_xor_sync(0xffffffffu, mx0, 1));
        mx0 = fmaxf(mx0, __shfl_xor_sync(0xffffffffu, mx0, 2));
        mx1 = fmaxf(mx1, __shfl_xor_sync(0xffffffffu, mx1, 1));
        mx1 = fmaxf(mx1, __shfl_xor_sync(0xffffffffu, mx1, 2));
        float nm0 = fmaxf(m0v, mx0), nm1 = fmaxf(m1v, mx1);
        float c0 = __expf(m0v - nm0), c1 = __expf(m1v - nm1);
        l0 *= c0; l1 *= c1;
        #pragma unroll
        for (int nf = 0; nf < 8; nf++) {
            oacc[nf][0] *= c0; oacc[nf][1] *= c0;
            oacc[nf][2] *= c1; oacc[nf][3] *= c1;
        }
        m0v = nm0; m1v = nm1;
        float ps0 = 0.f, ps1 = 0.f;
        #pragma unroll
        for (int nf = 0; nf < 8; nf++) {
            sc[nf][0] = __expf(sc[nf][0] - nm0);
            sc[nf][1] = __expf(sc[nf][1] - nm0);
            sc[nf][2] = __expf(sc[nf][2] - nm1);
            sc[nf][3] = __expf(sc[nf][3] - nm1);
            ps0 += sc[nf][0] + sc[nf][1];
            ps1 += sc[nf][2] + sc[nf][3];
        }
        ps0 += __shfl_xor_sync(0xffffffffu, ps0, 1);
        ps0 += __shfl_xor_sync(0xffffffffu, ps0, 2);
        ps1 += __shfl_xor_sync(0xffffffffu, ps1, 1);
        ps1 += __shfl_xor_sync(0xffffffffu, ps1, 2);
        l0 += ps0; l1 += ps1;

        // O += P @ V (P split in registers; V via ldmatrix.trans)
        #pragma unroll
        for (int c = 0; c < 4; c++) {
            uint32_t pah[4], pal[4];
            pack_split(sc[2 * c][0],     sc[2 * c][1],     pah[0], pal[0]);
            pack_split(sc[2 * c][2],     sc[2 * c][3],     pah[1], pal[1]);
            pack_split(sc[2 * c + 1][0], sc[2 * c + 1][1], pah[2], pal[2]);
            pack_split(sc[2 * c + 1][2], sc[2 * c + 1][3], pah[3], pal[3]);
            #pragma unroll
            for (int dg = 0; dg < 4; dg++) {
                uint32_t ro = (uint32_t)((c * 16 + (lane & 15)) * 128) + dg * 32 + (lane >> 4) * 16;
                uint32_t t0, t1, t2, t3, u0, u1, u2, u3;
                LDSM_X4_T(t0, t1, t2, t3, kb + 16384 + SW128(ro));
                LDSM_X4_T(u0, u1, u2, u3, kb + 24576 + SW128(ro));
                mma4(oacc[2 * dg],     pah, t0, t1);
                mma4(oacc[2 * dg],     pah, u0, u1);
                mma4(oacc[2 * dg],     pal, t0, t1);
                mma4(oacc[2 * dg + 1], pah, t2, t3);
                mma4(oacc[2 * dg + 1], pah, u2, u3);
                mma4(oacc[2 * dg + 1], pal, t2, t3);
            }
        }
        __syncthreads();
    }

    // Epilogue: normalize + split-store
    float inv0 = 1.f / l0, inv1 = 1.f / l1;
    size_t r0 = qrow0 + wid * 16 + g;
    #pragma unroll
    for (int nf = 0; nf < 8; nf++) {
        int col = h * 64 + nf * 8 + tg * 2;
        float v0 = oacc[nf][0] * inv0, v1 = oacc[nf][1] * inv0;
        float v2 = oacc[nf][2] * inv1, v3 = oacc[nf][3] * inv1;
        __nv_bfloat16 h0, lo0, h1, lo1;
        split2(v0, h0, lo0); split2(v1, h1, lo1);
        *(__nv_bfloat162*)(oh + r0 * DIM + col) = __nv_bfloat162(h0, h1);
        *(__nv_bfloat162*)(ol + r0 * DIM + col) = __nv_bfloat162(lo0, lo1);
        split2(v2, h0, lo0); split2(v3, h1, lo1);
        *(__nv_bfloat162*)(oh + (r0 + 8) * DIM + col) = __nv_bfloat162(h0, h1);
        *(__nv_bfloat162*)(ol + (r0 + 8) * DIM + col) = __nv_bfloat162(lo0, lo1);
    }
}

// ============================================================================
// Final transpose: x[b,n,d] -> out[b,d,n]
// ============================================================================
__global__ void transpose_out_kernel(const float* __restrict__ x,
                                     float* __restrict__ out)
{
    __shared__ float t[32][33];
    int b = blockIdx.z;
    int n0 = blockIdx.x * 32, d0 = blockIdx.y * 32;
    int tx = threadIdx.x, ty = threadIdx.y;
    for (int i = ty; i < 32; i += 8)
        t[i][tx] = x[((size_t)b * NTOK + n0 + i) * DIM + d0 + tx];
    __syncthreads();
    for (int i = ty; i < 32; i += 8)
        out[((size_t)b * DIM + d0 + i) * NTOK + n0 + tx] = t[tx][i];
}

// ============================================================================
// Host orchestration
// ============================================================================
extern "C" void kernel_launch(void* const* d_in, const int* in_sizes, int n_in,
                              void* d_out, int out_size)
{
    const float* c_f    = (const float*)d_in[0];
    const float* conv_w = (const float*)d_in[1];
    const float* conv_b = (const float*)d_in[2];
    const float* ln1_w  = (const float*)d_in[3];
    const float* ln1_b  = (const float*)d_in[4];
    const float* qkv_w  = (const float*)d_in[5];
    const float* out_w  = (const float*)d_in[6];
    const float* out_b  = (const float*)d_in[7];
    const float* ln2_w  = (const float*)d_in[8];
    const float* ln2_b  = (const float*)d_in[9];
    const float* mlp_w1 = (const float*)d_in[10];
    const float* mlp_b1 = (const float*)d_in[11];
    const float* mlp_w2 = (const float*)d_in[12];
    const float* mlp_b2 = (const float*)d_in[13];
    float* out = (float*)d_out;

    cudaFuncSetAttribute(mma_gemm_kernel,
                         cudaFuncAttributeMaxDynamicSharedMemorySize, MMA_SMEM);
    cudaFuncSetAttribute(flash_mma_kernel,
                         cudaFuncAttributeMaxDynamicSharedMemorySize, ATT_SMEM);

    float *p_x;
    __nv_bfloat16 *p_yh, *p_yl, *p_oh, *p_ol, *p_hh, *p_hl, *p_qh, *p_ql;
    __nv_bfloat16 *p_qwh, *p_qwl, *p_owh, *p_owl, *p_m1h, *p_m1l, *p_m2h, *p_m2l;
    cudaGetSymbolAddress((void**)&p_x,   g_x);
    cudaGetSymbolAddress((void**)&p_yh,  g_yh);
    cudaGetSymbolAddress((void**)&p_yl,  g_yl);
    cudaGetSymbolAddress((void**)&p_oh,  g_oh);
    cudaGetSymbolAddress((void**)&p_ol,  g_ol);
    cudaGetSymbolAddress((void**)&p_hh,  g_hh);
    cudaGetSymbolAddress((void**)&p_hl,  g_hl);
    cudaGetSymbolAddress((void**)&p_qh,  g_qh);
    cudaGetSymbolAddress((void**)&p_ql,  g_ql);
    cudaGetSymbolAddress((void**)&p_qwh, g_qkvw_h);
    cudaGetSymbolAddress((void**)&p_qwl, g_qkvw_l);
    cudaGetSymbolAddress((void**)&p_owh, g_outw_h);
    cudaGetSymbolAddress((void**)&p_owl, g_outw_l);
    cudaGetSymbolAddress((void**)&p_m1h, g_m1w_h);
    cudaGetSymbolAddress((void**)&p_m1l, g_m1w_l);
    cudaGetSymbolAddress((void**)&p_m2h, g_m2w_h);
    cudaGetSymbolAddress((void**)&p_m2l, g_m2w_l);

    wsplit_all_kernel<<<DEPTH * WL_BLOCKS, dim3(32, 8)>>>(
        qkv_w, out_w, mlp_w1, mlp_w2,
        p_qwh, p_qwl, p_owh, p_owl, p_m1h, p_m1l, p_m2h, p_m2l);

    embed_kernel<<<dim3(NTOK / 64, DIM / 64, BATCH), 256>>>(c_f, conv_w, conv_b, p_x);

    for (int l = 0; l < DEPTH; l++) {
        ln_split_kernel<<<ROWS, 256>>>(p_x, ln1_w + l * DIM, ln1_b + l * DIM, p_yh, p_yl);
        mma_gemm_kernel<<<dim3(QKV3 / 128, ROWS / 128), 256, MMA_SMEM>>>(
            DIM, QKV3, p_yh, p_yl,
            p_qwh + (size_t)l * QKV3 * DIM, p_qwl + (size_t)l * QKV3 * DIM,
            nullptr, nullptr, nullptr, p_qh, p_ql, 0);
        flash_mma_kernel<<<dim3(NTOK / 128, BATCH * HEADS), 256, ATT_SMEM>>>(
            p_qh, p_ql, p_oh, p_ol);
        mma_gemm_kernel<<<dim3(DIM / 128, ROWS / 128), 256, MMA_SMEM>>>(
            DIM, DIM, p_oh, p_ol,
            p_owh + (size_t)l * DIM * DIM, p_owl + (size_t)l * DIM * DIM,
            out_b + l * DIM, p_x, p_x, nullptr, nullptr, 0);
        ln_split_kernel<<<ROWS, 256>>>(p_x, ln2_w + l * DIM, ln2_b + l * DIM, p_yh, p_yl);
        mma_gemm_kernel<<<dim3(MLPD / 128, ROWS / 128), 256, MMA_SMEM>>>(
            DIM, MLPD, p_yh, p_yl,
            p_m1h + (size_t)l * MLPD * DIM, p_m1l + (size_t)l * MLPD * DIM,
            mlp_b1 + l * MLPD, nullptr, nullptr, p_hh, p_hl, 1);
        mma_gemm_kernel<<<dim3(DIM / 128, ROWS / 128), 256, MMA_SMEM>>>(
            MLPD, DIM, p_hh, p_hl,
            p_m2h + (size_t)l * DIM * MLPD, p_m2l + (size_t)l * DIM * MLPD,
            mlp_b2 + l * DIM, p_x, p_x, nullptr, nullptr, 0);
    }

    transpose_out_kernel<<<dim3(NTOK / 32, DIM / 32, BATCH), dim3(32, 8)>>>(p_x, out);
}

// round 8
// speedup vs baseline: 4.6508x; 1.1192x over previous
#include <cuda_runtime.h>
#include <cuda_bf16.h>
#include <math.h>
#include <stdint.h>

#define DIM 768
#define NTOK 1024
#define BATCH 4
#define ROWS (BATCH * NTOK)        // 4096
#define F_DIM 256
#define HEADS 12
#define DHEAD 64
#define QKV3 (3 * DIM)             // 2304
#define MLPD 3072
#define DEPTH 8
#define LN_EPS 1e-5f

// ============================================================================
// Helpers
// ============================================================================
__device__ __forceinline__ uint32_t smem_u32(const void* p) {
    uint32_t a;
    asm("{ .reg .u64 t; cvta.to.shared.u64 t, %1; cvt.u32.u64 %0, t; }"
        : "=r"(a) : "l"(p));
    return a;
}
#define SW128(o) ((o) ^ (((o) >> 3) & 0x70))

__device__ __forceinline__ void cp16(uint32_t s, const void* g) {
    asm volatile("cp.async.cg.shared.global [%0], [%1], 16;" :: "r"(s), "l"(g));
}
#define CP_COMMIT() asm volatile("cp.async.commit_group;" ::: "memory")
#define CP_WAIT1()  asm volatile("cp.async.wait_group 1;" ::: "memory")

#define LDSM_X4(r0, r1, r2, r3, addr) \
    asm volatile("ldmatrix.sync.aligned.m8n8.x4.shared.b16 {%0,%1,%2,%3}, [%4];" \
        : "=r"(r0), "=r"(r1), "=r"(r2), "=r"(r3) : "r"(addr))
#define LDSM_X4_T(r0, r1, r2, r3, addr) \
    asm volatile("ldmatrix.sync.aligned.m8n8.x4.trans.shared.b16 {%0,%1,%2,%3}, [%4];" \
        : "=r"(r0), "=r"(r1), "=r"(r2), "=r"(r3) : "r"(addr))

__device__ __forceinline__ void mma_bf16(float* c, const uint32_t* a, const uint32_t* b) {
    asm volatile(
        "mma.sync.aligned.m16n8k16.row.col.f32.bf16.bf16.f32 "
        "{%0,%1,%2,%3}, {%4,%5,%6,%7}, {%8,%9}, {%0,%1,%2,%3};"
        : "+f"(c[0]), "+f"(c[1]), "+f"(c[2]), "+f"(c[3])
        : "r"(a[0]), "r"(a[1]), "r"(a[2]), "r"(a[3]), "r"(b[0]), "r"(b[1]));
}
__device__ __forceinline__ void mma4(float* c, const uint32_t* a, uint32_t b0, uint32_t b1) {
    uint32_t b[2] = { b0, b1 };
    mma_bf16(c, a, b);
}

__device__ __forceinline__ void split2(float v, __nv_bfloat16& h, __nv_bfloat16& l) {
    h = __float2bfloat16(v);
    l = __float2bfloat16(v - __bfloat162float(h));
}
__device__ __forceinline__ void pack_split(float a, float b, uint32_t& hi, uint32_t& lo) {
    __nv_bfloat16 ha = __float2bfloat16(a);
    __nv_bfloat16 hb = __float2bfloat16(b);
    __nv_bfloat162 H(ha, hb);
    __nv_bfloat162 L(__float2bfloat16(a - __bfloat162float(ha)),
                     __float2bfloat16(b - __bfloat162float(hb)));
    hi = *(uint32_t*)&H;
    lo = *(uint32_t*)&L;
}
__device__ __forceinline__ float gelu_f(float v) {
    return 0.5f * v * (1.0f + erff(v * 0.7071067811865475f));
}

// ============================================================================
// Scratch (device globals)
// ============================================================================
__device__ __align__(16) float g_x  [ROWS * DIM];
__device__ __align__(16) __nv_bfloat16 g_yh[ROWS * DIM],  g_yl[ROWS * DIM];
__device__ __align__(16) __nv_bfloat16 g_oh[ROWS * DIM],  g_ol[ROWS * DIM];
__device__ __align__(16) __nv_bfloat16 g_hh[ROWS * MLPD], g_hl[ROWS * MLPD];
__device__ __align__(16) __nv_bfloat16 g_qh[ROWS * QKV3], g_ql[ROWS * QKV3];
// transposed + split weights: [L][N][K]
__device__ __align__(16) __nv_bfloat16 g_qkvw_h[DEPTH * QKV3 * DIM], g_qkvw_l[DEPTH * QKV3 * DIM];
__device__ __align__(16) __nv_bfloat16 g_outw_h[DEPTH * DIM * DIM],  g_outw_l[DEPTH * DIM * DIM];
__device__ __align__(16) __nv_bfloat16 g_m1w_h [DEPTH * MLPD * DIM], g_m1w_l [DEPTH * MLPD * DIM];
__device__ __align__(16) __nv_bfloat16 g_m2w_h [DEPTH * DIM * MLPD], g_m2w_l [DEPTH * DIM * MLPD];

// ============================================================================
// Combined weight transpose + bf16 split (one launch).
// ============================================================================
#define WL_BLOCKS 6912
__global__ void wsplit_all_kernel(
    const float* __restrict__ qkv_w, const float* __restrict__ out_w,
    const float* __restrict__ m1w,   const float* __restrict__ m2w,
    __nv_bfloat16* qh, __nv_bfloat16* ql,
    __nv_bfloat16* owh, __nv_bfloat16* owl,
    __nv_bfloat16* m1h, __nv_bfloat16* m1l,
    __nv_bfloat16* m2h, __nv_bfloat16* m2l)
{
    int z = blockIdx.x;
    int l = z / WL_BLOCKS, r = z % WL_BLOCKS;
    const float* w; __nv_bfloat16 *hi, *lo; int K, N, nx, ny;
    if (r < 1728)      { w = qkv_w; hi = qh;  lo = ql;  K = DIM;  N = QKV3; nx = r % 72; ny = r / 72; }
    else if (r < 2304) { int rr = r - 1728; w = out_w; hi = owh; lo = owl; K = DIM;  N = DIM;  nx = rr % 24; ny = rr / 24; }
    else if (r < 4608) { int rr = r - 2304; w = m1w;   hi = m1h; lo = m1l; K = DIM;  N = MLPD; nx = rr % 96; ny = rr / 96; }
    else               { int rr = r - 4608; w = m2w;   hi = m2h; lo = m2l; K = MLPD; N = DIM;  nx = rr % 24; ny = rr / 24; }
    __shared__ float t[32][33];
    int n0 = nx * 32, k0 = ny * 32;
    int tx = threadIdx.x, ty = threadIdx.y;
    const float* wl = w + (size_t)l * K * N;
    for (int i = ty; i < 32; i += 8)
        t[i][tx] = wl[(size_t)(k0 + i) * N + n0 + tx];
    __syncthreads();
    size_t ob = (size_t)l * K * N;
    for (int i = ty; i < 32; i += 8) {
        float v = t[tx][i];
        __nv_bfloat16 h, lw;
        split2(v, h, lw);
        size_t o = ob + (size_t)(n0 + i) * K + k0 + tx;
        hi[o] = h; lo[o] = lw;
    }
}

// ============================================================================
// Embed GEMM with fused sine pos-embed
// ============================================================================
__device__ __forceinline__ float posval(int n, int d) {
    int r = n >> 5, c = n & 31;
    int id = (d < 384) ? d : d - 384;
    float coord = (d < 384) ? (float)(r + 1) : (float)(c + 1);
    float ang = coord * (6.283185307179586f / (32.0f + 1e-6f));
    float ex = (float)(2 * (id / 2)) * (1.0f / 384.0f);
    float p = ang / __powf(10000.0f, ex);
    return (id & 1) ? cosf(p) : sinf(p);
}

__global__ __launch_bounds__(256) void embed_kernel(
    const float* __restrict__ cf, const float* __restrict__ w,
    const float* __restrict__ bias, float* __restrict__ x)
{
    __shared__ float As[16][64];
    __shared__ float Bs[16][68];
    int b  = blockIdx.z;
    int n0 = blockIdx.x * 64, d0 = blockIdx.y * 64;
    int tid = threadIdx.x;
    int ty = tid / 16, tx = tid % 16;
    float acc[4][4] = {};
    const float* cfb = cf + (size_t)b * F_DIM * NTOK;
    for (int k0 = 0; k0 < F_DIM; k0 += 16) {
        #pragma unroll
        for (int it = 0; it < 4; it++) {
            int idx = tid + it * 256;
            As[idx >> 6][idx & 63] = cfb[(size_t)(k0 + (idx >> 6)) * NTOK + n0 + (idx & 63)];
        }
        #pragma unroll
        for (int it = 0; it < 4; it++) {
            int idx = tid + it * 256;
            Bs[idx & 15][idx >> 4] = w[(size_t)(d0 + (idx >> 4)) * F_DIM + k0 + (idx & 15)];
        }
        __syncthreads();
        #pragma unroll
        for (int kk = 0; kk < 16; kk++) {
            float a[4], bb[4];
            #pragma unroll
            for (int i = 0; i < 4; i++) a[i]  = As[kk][ty * 4 + i];
            #pragma unroll
            for (int j = 0; j < 4; j++) bb[j] = Bs[kk][tx * 4 + j];
            #pragma unroll
            for (int i = 0; i < 4; i++)
                #pragma unroll
                for (int j = 0; j < 4; j++)
                    acc[i][j] += a[i] * bb[j];
        }
        __syncthreads();
    }
    #pragma unroll
    for (int i = 0; i < 4; i++) {
        int n = n0 + ty * 4 + i;
        #pragma unroll
        for (int j = 0; j < 4; j++) {
            int d = d0 + tx * 4 + j;
            x[((size_t)b * NTOK + n) * DIM + d] = acc[i][j] + bias[d] + posval(n, d);
        }
    }
}

// ============================================================================
// LayerNorm -> split bf16 hi/lo.  Warp-per-row: 8 warps/block, float4 loads.
// ============================================================================
__global__ __launch_bounds__(256) void ln_split_kernel(
    const float* __restrict__ x, const float* __restrict__ w,
    const float* __restrict__ bias,
    __nv_bfloat16* __restrict__ yh, __nv_bfloat16* __restrict__ yl)
{
    int warp = threadIdx.x >> 5, lane = threadIdx.x & 31;
    int row = blockIdx.x * 8 + warp;
    const float4* xr = (const float4*)(x + (size_t)row * DIM);
    float4 v[6];
    float s = 0.f, ss = 0.f;
    #pragma unroll
    for (int i = 0; i < 6; i++) {
        v[i] = xr[lane + i * 32];
        s  += v[i].x + v[i].y + v[i].z + v[i].w;
        ss += v[i].x * v[i].x + v[i].y * v[i].y + v[i].z * v[i].z + v[i].w * v[i].w;
    }
    #pragma unroll
    for (int off = 16; off; off >>= 1) {
        s  += __shfl_xor_sync(0xffffffffu, s,  off);
        ss += __shfl_xor_sync(0xffffffffu, ss, off);
    }
    float mu  = s * (1.0f / DIM);
    float var = ss * (1.0f / DIM) - mu * mu;
    float inv = rsqrtf(var + LN_EPS);
    const float4* wv = (const float4*)w;
    const float4* bv = (const float4*)bias;
    #pragma unroll
    for (int i = 0; i < 6; i++) {
        int idx4 = lane + i * 32;
        float4 ww = wv[idx4], bb = bv[idx4];
        float y0 = (v[i].x - mu) * inv * ww.x + bb.x;
        float y1 = (v[i].y - mu) * inv * ww.y + bb.y;
        float y2 = (v[i].z - mu) * inv * ww.z + bb.z;
        float y3 = (v[i].w - mu) * inv * ww.w + bb.w;
        uint32_t h01, l01, h23, l23;
        pack_split(y0, y1, h01, l01);
        pack_split(y2, y3, h23, l23);
        uint32_t* ph = (uint32_t*)(yh + (size_t)row * DIM) + idx4 * 2;
        uint32_t* pl = (uint32_t*)(yl + (size_t)row * DIM) + idx4 * 2;
        ph[0] = h01; ph[1] = h23;
        pl[0] = l01; pl[1] = l23;
    }
}

// ============================================================================
// Tensor-core GEMM (bf16x3 split, fp32 accum), 3-stage cp.async pipeline,
// one __syncthreads per K-iter, 96KB smem -> 2 CTAs/SM.
// ============================================================================
#define STG_BYTES 32768
#define MMA_SMEM  (3 * STG_BYTES)   // 98304

__device__ __forceinline__ void issue_stage(
    int ch, int nch, int K, int tid, uint32_t sbase,
    const __nv_bfloat16* s0, const __nv_bfloat16* s1,
    const __nv_bfloat16* s2, const __nv_bfloat16* s3)
{
    if (ch < nch) {
        int k0 = ch * 32;
        uint32_t sb0 = sbase + (uint32_t)(ch % 3) * STG_BYTES;
        const __nv_bfloat16* srcs[4] = { s0, s1, s2, s3 };
        #pragma unroll
        for (int t = 0; t < 4; t++) {
            #pragma unroll
            for (int i = 0; i < 2; i++) {
                int idx = tid + i * 256;
                int r = idx >> 2, c = idx & 3;
                const void* g = (const char*)srcs[t] + ((size_t)r * K + k0 + c * 8) * 2;
                cp16(sb0 + t * 8192 + SW128((uint32_t)(r * 64 + c * 16)), g);
            }
        }
    }
    CP_COMMIT();
}

__global__ __launch_bounds__(256) void mma_gemm_kernel(
    int K, int N,
    const __nv_bfloat16* __restrict__ Ah, const __nv_bfloat16* __restrict__ Al,
    const __nv_bfloat16* __restrict__ Bh, const __nv_bfloat16* __restrict__ Bl,
    const float* __restrict__ bias, const float* __restrict__ resid,
    float* __restrict__ outf,
    __nv_bfloat16* __restrict__ oh, __nv_bfloat16* __restrict__ ol,
    int gelu)
{
    extern __shared__ char smem[];
    uint32_t sbase = smem_u32(smem);
    int tid = threadIdx.x, wid = tid >> 5, lane = tid & 31;
    int n0 = blockIdx.x * 128, m0 = blockIdx.y * 128;
    const __nv_bfloat16* s0 = Ah + (size_t)m0 * K;
    const __nv_bfloat16* s1 = Al + (size_t)m0 * K;
    const __nv_bfloat16* s2 = Bh + (size_t)n0 * K;
    const __nv_bfloat16* s3 = Bl + (size_t)n0 * K;
    int nch = K / 32;

    int wm = wid >> 2, wn = wid & 3;
    uint32_t lrow = lane & 15, lhalf = lane >> 4;

    float acc[4][4][4] = {};

    issue_stage(0, nch, K, tid, sbase, s0, s1, s2, s3);
    issue_stage(1, nch, K, tid, sbase, s0, s1, s2, s3);

    for (int ch = 0; ch < nch; ch++) {
        CP_WAIT1();
        __syncthreads();
        issue_stage(ch + 2, nch, K, tid, sbase, s0, s1, s2, s3);
        uint32_t st = sbase + (uint32_t)(ch % 3) * STG_BYTES;
        uint32_t aH = st, aL = st + 8192, bH = st + 16384, bL = st + 24576;
        #pragma unroll
        for (int ks = 0; ks < 2; ks++) {
            uint32_t koff = (uint32_t)(ks * 2 + lhalf) * 16;
            uint32_t ah[4][4], al[4][4], bh[4][2], bl[4][2];
            #pragma unroll
            for (int mf = 0; mf < 4; mf++) {
                uint32_t ro = (uint32_t)((wm * 64 + mf * 16 + lrow) * 64) + koff;
                LDSM_X4(ah[mf][0], ah[mf][1], ah[mf][2], ah[mf][3], aH + SW128(ro));
                LDSM_X4(al[mf][0], al[mf][1], al[mf][2], al[mf][3], aL + SW128(ro));
            }
            #pragma unroll
            for (int nf2 = 0; nf2 < 2; nf2++) {
                uint32_t ro = (uint32_t)((wn * 32 + nf2 * 16 + lrow) * 64) + koff;
                uint32_t t0, t1, t2, t3;
                LDSM_X4(t0, t1, t2, t3, bH + SW128(ro));
                bh[nf2 * 2][0] = t0; bh[nf2 * 2 + 1][0] = t1;
                bh[nf2 * 2][1] = t2; bh[nf2 * 2 + 1][1] = t3;
                LDSM_X4(t0, t1, t2, t3, bL + SW128(ro));
                bl[nf2 * 2][0] = t0; bl[nf2 * 2 + 1][0] = t1;
                bl[nf2 * 2][1] = t2; bl[nf2 * 2 + 1][1] = t3;
            }
            #pragma unroll
            for (int mf = 0; mf < 4; mf++) {
                #pragma unroll
                for (int nf = 0; nf < 4; nf++) {
                    mma_bf16(acc[mf][nf], ah[mf], bh[nf]);
                    mma_bf16(acc[mf][nf], ah[mf], bl[nf]);
                    mma_bf16(acc[mf][nf], al[mf], bh[nf]);
                }
            }
        }
    }

    // Epilogue
    int g = lane >> 2, tg = lane & 3;
    #pragma unroll
    for (int mf = 0; mf < 4; mf++) {
        #pragma unroll
        for (int nf = 0; nf < 4; nf++) {
            int col = n0 + wn * 32 + nf * 8 + tg * 2;
            float bv0 = bias ? __ldg(bias + col)     : 0.f;
            float bv1 = bias ? __ldg(bias + col + 1) : 0.f;
            #pragma unroll
            for (int half = 0; half < 2; half++) {
                int row = m0 + wm * 64 + mf * 16 + g + half * 8;
                float v0 = acc[mf][nf][half * 2 + 0] + bv0;
                float v1 = acc[mf][nf][half * 2 + 1] + bv1;
                if (gelu) { v0 = gelu_f(v0); v1 = gelu_f(v1); }
                size_t gb = (size_t)row * N + col;
                if (resid) {
                    float2 rr = *(const float2*)(resid + gb);
                    v0 += rr.x; v1 += rr.y;
                }
                if (outf) {
                    *(float2*)(outf + gb) = make_float2(v0, v1);
                } else {
                    __nv_bfloat16 h0, l0, h1, l1;
                    split2(v0, h0, l0); split2(v1, h1, l1);
                    *(__nv_bfloat162*)(oh + gb) = __nv_bfloat162(h0, h1);
                    *(__nv_bfloat162*)(ol + gb) = __nv_bfloat162(l0, l1);
                }
            }
        }
    }
}

// ============================================================================
// Flash attention via mma.sync (bf16 split Q,K,V,P; fp32 softmax/accum).
// ============================================================================
#define ATT_SMEM 65536

__device__ __forceinline__ void attn_issue(
    int kt, int tid, uint32_t sb,
    const __nv_bfloat16* qh, const __nv_bfloat16* ql,
    size_t batch_row0, int kcol, int vcol)
{
    if (kt < 16) {
        uint32_t st = sb + (uint32_t)(kt & 1) * 32768;
        size_t rb = batch_row0 + (size_t)kt * 64;
        #pragma unroll
        for (int i = 0; i < 2; i++) {
            int idx = tid + i * 256;
            int r = idx >> 3, c = idx & 7;
            size_t rowoff = (rb + r) * QKV3;
            uint32_t so = SW128((uint32_t)(r * 128 + c * 16));
            cp16(st +         so, (const char*)(qh + rowoff + kcol) + c * 16);
            cp16(st + 8192  + so, (const char*)(ql + rowoff + kcol) + c * 16);
            cp16(st + 16384 + so, (const char*)(qh + rowoff + vcol) + c * 16);
            cp16(st + 24576 + so, (const char*)(ql + rowoff + vcol) + c * 16);
        }
    }
    CP_COMMIT();
}

__global__ __launch_bounds__(256) void flash_mma_kernel(
    const __nv_bfloat16* __restrict__ qh, const __nv_bfloat16* __restrict__ ql,
    __nv_bfloat16* __restrict__ oh, __nv_bfloat16* __restrict__ ol)
{
    extern __shared__ char smem[];
    uint32_t sb = smem_u32(smem);
    int tid = threadIdx.x, wid = tid >> 5, lane = tid & 31;
    int qt = blockIdx.x;
    int b = blockIdx.y / HEADS, h = blockIdx.y % HEADS;
    int g = lane >> 2, tg = lane & 3;
    size_t batch_row0 = (size_t)b * NTOK;
    size_t qrow0 = batch_row0 + (size_t)qt * 128;
    int qcol = h * 64, kcol = DIM + h * 64, vcol = 2 * DIM + h * 64;

    #pragma unroll
    for (int i = 0; i < 4; i++) {
        int idx = tid + i * 256;
        int r = idx >> 3, c = idx & 7;
        size_t rowoff = (qrow0 + r) * QKV3 + qcol;
        uint32_t so = SW128((uint32_t)(r * 128 + c * 16));
        *(uint4*)(smem + so)         = *((const uint4*)(qh + rowoff) + c);
        *(uint4*)(smem + 16384 + so) = *((const uint4*)(ql + rowoff) + c);
    }
    __syncthreads();

    uint32_t ah[4][4], al[4][4];
    {
        uint32_t lrow = lane & 15, lh = lane >> 4;
        #pragma unroll
        for (int kf = 0; kf < 4; kf++) {
            uint32_t ro = (uint32_t)((wid * 16 + lrow) * 128) + kf * 32 + lh * 16;
            LDSM_X4(ah[kf][0], ah[kf][1], ah[kf][2], ah[kf][3], sb + SW128(ro));
            LDSM_X4(al[kf][0], al[kf][1], al[kf][2], al[kf][3], sb + 16384 + SW128(ro));
        }
    }
    __syncthreads();

    float m0v = -1e30f, m1v = -1e30f, l0 = 0.f, l1 = 0.f;
    float oacc[8][4] = {};
    const float scale = 0.125f;

    attn_issue(0, tid, sb, qh, ql, batch_row0, kcol, vcol);

    for (int kt = 0; kt < 16; kt++) {
        attn_issue(kt + 1, tid, sb, qh, ql, batch_row0, kcol, vcol);
        CP_WAIT1();
        __syncthreads();
        uint32_t kb = sb + (uint32_t)(kt & 1) * 32768;

        float sc[8][4] = {};
        #pragma unroll
        for (int kg = 0; kg < 4; kg++) {
            #pragma unroll
            for (int kf = 0; kf < 4; kf++) {
                uint32_t ro = (uint32_t)((kg * 16 + (lane & 15)) * 128) + kf * 32 + (lane >> 4) * 16;
                uint32_t t0, t1, t2, t3, u0, u1, u2, u3;
                LDSM_X4(t0, t1, t2, t3, kb + SW128(ro));
                LDSM_X4(u0, u1, u2, u3, kb + 8192 + SW128(ro));
                mma4(sc[2 * kg],     ah[kf], t0, t2);
                mma4(sc[2 * kg],     ah[kf], u0, u2);
                mma4(sc[2 * kg],     al[kf], t0, t2);
                mma4(sc[2 * kg + 1], ah[kf], t1, t3);
                mma4(sc[2 * kg + 1], ah[kf], u1, u3);
                mma4(sc[2 * kg + 1], al[kf], t1, t3);
            }
        }

        float mx0 = -1e30f, mx1 = -1e30f;
        #pragma unroll
        for (int nf = 0; nf < 8; nf++) {
            #pragma unroll
            for (int i = 0; i < 4; i++) sc[nf][i] *= scale;
            mx0 = fmaxf(mx0, fmaxf(sc[nf][0], sc[nf][1]));
            mx1 = fmaxf(mx1, fmaxf(sc[nf][2], sc[nf][3]));
        }
        mx0 = fmaxf(mx0, __shfl_xor_sync(0xffffffffu, mx0, 1));
        mx0 = fmaxf(mx0, __shfl_xor_sync(0xffffffffu, mx0, 2));
        mx1 = fmaxf(mx1, __shfl_xor_sync(0xffffffffu, mx1, 1));
        mx1 = fmaxf(mx1, __shfl_xor_sync(0xffffffffu, mx1, 2));
        float nm0 = fmaxf(m0v, mx0), nm1 = fmaxf(m1v, mx1);
        float c0 = __expf(m0v - nm0), c1 = __expf(m1v - nm1);
        l0 *= c0; l1 *= c1;
        #pragma unroll
        for (int nf = 0; nf < 8; nf++) {
            oacc[nf][0] *= c0; oacc[nf][1] *= c0;
            oacc[nf][2] *= c1; oacc[nf][3] *= c1;
        }
        m0v = nm0; m1v = nm1;
        float ps0 = 0.f, ps1 = 0.f;
        #pragma unroll
        for (int nf = 0; nf < 8; nf++) {
            sc[nf][0] = __expf(sc[nf][0] - nm0);
            sc[nf][1] = __expf(sc[nf][1] - nm0);
            sc[nf][2] = __expf(sc[nf][2] - nm1);
            sc[nf][3] = __expf(sc[nf][3] - nm1);
            ps0 += sc[nf][0] + sc[nf][1];
            ps1 += sc[nf][2] + sc[nf][3];
        }
        ps0 += __shfl_xor_sync(0xffffffffu, ps0, 1);
        ps0 += __shfl_xor_sync(0xffffffffu, ps0, 2);
        ps1 += __shfl_xor_sync(0xffffffffu, ps1, 1);
        ps1 += __shfl_xor_sync(0xffffffffu, ps1, 2);
        l0 += ps0; l1 += ps1;

        #pragma unroll
        for (int c = 0; c < 4; c++) {
            uint32_t pah[4], pal[4];
            pack_split(sc[2 * c][0],     sc[2 * c][1],     pah[0], pal[0]);
            pack_split(sc[2 * c][2],     sc[2 * c][3],     pah[1], pal[1]);
            pack_split(sc[2 * c + 1][0], sc[2 * c + 1][1], pah[2], pal[2]);
            pack_split(sc[2 * c + 1][2], sc[2 * c + 1][3], pah[3], pal[3]);
            #pragma unroll
            for (int dg = 0; dg < 4; dg++) {
                uint32_t ro = (uint32_t)((c * 16 + (lane & 15)) * 128) + dg * 32 + (lane >> 4) * 16;
                uint32_t t0, t1, t2, t3, u0, u1, u2, u3;
                LDSM_X4_T(t0, t1, t2, t3, kb + 16384 + SW128(ro));
                LDSM_X4_T(u0, u1, u2, u3, kb + 24576 + SW128(ro));
                mma4(oacc[2 * dg],     pah, t0, t1);
                mma4(oacc[2 * dg],     pah, u0, u1);
                mma4(oacc[2 * dg],     pal, t0, t1);
                mma4(oacc[2 * dg + 1], pah, t2, t3);
                mma4(oacc[2 * dg + 1], pah, u2, u3);
                mma4(oacc[2 * dg + 1], pal, t2, t3);
            }
        }
        __syncthreads();
    }

    float inv0 = 1.f / l0, inv1 = 1.f / l1;
    size_t r0 = qrow0 + wid * 16 + g;
    #pragma unroll
    for (int nf = 0; nf < 8; nf++) {
        int col = h * 64 + nf * 8 + tg * 2;
        float v0 = oacc[nf][0] * inv0, v1 = oacc[nf][1] * inv0;
        float v2 = oacc[nf][2] * inv1, v3 = oacc[nf][3] * inv1;
        __nv_bfloat16 h0, lo0, h1, lo1;
        split2(v0, h0, lo0); split2(v1, h1, lo1);
        *(__nv_bfloat162*)(oh + r0 * DIM + col) = __nv_bfloat162(h0, h1);
        *(__nv_bfloat162*)(ol + r0 * DIM + col) = __nv_bfloat162(lo0, lo1);
        split2(v2, h0, lo0); split2(v3, h1, lo1);
        *(__nv_bfloat162*)(oh + (r0 + 8) * DIM + col) = __nv_bfloat162(h0, h1);
        *(__nv_bfloat162*)(ol + (r0 + 8) * DIM + col) = __nv_bfloat162(lo0, lo1);
    }
}

// ============================================================================
// Final transpose: x[b,n,d] -> out[b,d,n]
// ============================================================================
__global__ void transpose_out_kernel(const float* __restrict__ x,
                                     float* __restrict__ out)
{
    __shared__ float t[32][33];
    int b = blockIdx.z;
    int n0 = blockIdx.x * 32, d0 = blockIdx.y * 32;
    int tx = threadIdx.x, ty = threadIdx.y;
    for (int i = ty; i < 32; i += 8)
        t[i][tx] = x[((size_t)b * NTOK + n0 + i) * DIM + d0 + tx];
    __syncthreads();
    for (int i = ty; i < 32; i += 8)
        out[((size_t)b * DIM + d0 + i) * NTOK + n0 + tx] = t[tx][i];
}

// ============================================================================
// Host orchestration
// ============================================================================
extern "C" void kernel_launch(void* const* d_in, const int* in_sizes, int n_in,
                              void* d_out, int out_size)
{
    const float* c_f    = (const float*)d_in[0];
    const float* conv_w = (const float*)d_in[1];
    const float* conv_b = (const float*)d_in[2];
    const float* ln1_w  = (const float*)d_in[3];
    const float* ln1_b  = (const float*)d_in[4];
    const float* qkv_w  = (const float*)d_in[5];
    const float* out_w  = (const float*)d_in[6];
    const float* out_b  = (const float*)d_in[7];
    const float* ln2_w  = (const float*)d_in[8];
    const float* ln2_b  = (const float*)d_in[9];
    const float* mlp_w1 = (const float*)d_in[10];
    const float* mlp_b1 = (const float*)d_in[11];
    const float* mlp_w2 = (const float*)d_in[12];
    const float* mlp_b2 = (const float*)d_in[13];
    float* out = (float*)d_out;

    cudaFuncSetAttribute(mma_gemm_kernel,
                         cudaFuncAttributeMaxDynamicSharedMemorySize, MMA_SMEM);
    cudaFuncSetAttribute(flash_mma_kernel,
                         cudaFuncAttributeMaxDynamicSharedMemorySize, ATT_SMEM);

    float *p_x;
    __nv_bfloat16 *p_yh, *p_yl, *p_oh, *p_ol, *p_hh, *p_hl, *p_qh, *p_ql;
    __nv_bfloat16 *p_qwh, *p_qwl, *p_owh, *p_owl, *p_m1h, *p_m1l, *p_m2h, *p_m2l;
    cudaGetSymbolAddress((void**)&p_x,   g_x);
    cudaGetSymbolAddress((void**)&p_yh,  g_yh);
    cudaGetSymbolAddress((void**)&p_yl,  g_yl);
    cudaGetSymbolAddress((void**)&p_oh,  g_oh);
    cudaGetSymbolAddress((void**)&p_ol,  g_ol);
    cudaGetSymbolAddress((void**)&p_hh,  g_hh);
    cudaGetSymbolAddress((void**)&p_hl,  g_hl);
    cudaGetSymbolAddress((void**)&p_qh,  g_qh);
    cudaGetSymbolAddress((void**)&p_ql,  g_ql);
    cudaGetSymbolAddress((void**)&p_qwh, g_qkvw_h);
    cudaGetSymbolAddress((void**)&p_qwl, g_qkvw_l);
    cudaGetSymbolAddress((void**)&p_owh, g_outw_h);
    cudaGetSymbolAddress((void**)&p_owl, g_outw_l);
    cudaGetSymbolAddress((void**)&p_m1h, g_m1w_h);
    cudaGetSymbolAddress((void**)&p_m1l, g_m1w_l);
    cudaGetSymbolAddress((void**)&p_m2h, g_m2w_h);
    cudaGetSymbolAddress((void**)&p_m2l, g_m2w_l);

    wsplit_all_kernel<<<DEPTH * WL_BLOCKS, dim3(32, 8)>>>(
        qkv_w, out_w, mlp_w1, mlp_w2,
        p_qwh, p_qwl, p_owh, p_owl, p_m1h, p_m1l, p_m2h, p_m2l);

    embed_kernel<<<dim3(NTOK / 64, DIM / 64, BATCH), 256>>>(c_f, conv_w, conv_b, p_x);

    for (int l = 0; l < DEPTH; l++) {
        ln_split_kernel<<<ROWS / 8, 256>>>(p_x, ln1_w + l * DIM, ln1_b + l * DIM, p_yh, p_yl);
        mma_gemm_kernel<<<dim3(QKV3 / 128, ROWS / 128), 256, MMA_SMEM>>>(
            DIM, QKV3, p_yh, p_yl,
            p_qwh + (size_t)l * QKV3 * DIM, p_qwl + (size_t)l * QKV3 * DIM,
            nullptr, nullptr, nullptr, p_qh, p_ql, 0);
        flash_mma_kernel<<<dim3(NTOK / 128, BATCH * HEADS), 256, ATT_SMEM>>>(
            p_qh, p_ql, p_oh, p_ol);
        mma_gemm_kernel<<<dim3(DIM / 128, ROWS / 128), 256, MMA_SMEM>>>(
            DIM, DIM, p_oh, p_ol,
            p_owh + (size_t)l * DIM * DIM, p_owl + (size_t)l * DIM * DIM,
            out_b + l * DIM, p_x, p_x, nullptr, nullptr, 0);
        ln_split_kernel<<<ROWS / 8, 256>>>(p_x, ln2_w + l * DIM, ln2_b + l * DIM, p_yh, p_yl);
        mma_gemm_kernel<<<dim3(MLPD / 128, ROWS / 128), 256, MMA_SMEM>>>(
            DIM, MLPD, p_yh, p_yl,
            p_m1h + (size_t)l * MLPD * DIM, p_m1l + (size_t)l * MLPD * DIM,
            mlp_b1 + l * MLPD, nullptr, nullptr, p_hh, p_hl, 1);
        mma_gemm_kernel<<<dim3(DIM / 128, ROWS / 128), 256, MMA_SMEM>>>(
            MLPD, DIM, p_hh, p_hl,
            p_m2h + (size_t)l * DIM * MLPD, p_m2l + (size_t)l * DIM * MLPD,
            mlp_b2 + l * DIM, p_x, p_x, nullptr, nullptr, 0);
    }

    transpose_out_kernel<<<dim3(NTOK / 32, DIM / 32, BATCH), dim3(32, 8)>>>(p_x, out);
}

// round 11
// speedup vs baseline: 5.1245x; 1.1019x over previous
#include <cuda_runtime.h>
#include <cuda_bf16.h>
#include <math.h>
#include <stdint.h>

#define DIM 768
#define NTOK 1024
#define BATCH 4
#define ROWS (BATCH * NTOK)        // 4096
#define F_DIM 256
#define HEADS 12
#define DHEAD 64
#define QKV3 (3 * DIM)             // 2304
#define MLPD 3072
#define DEPTH 8
#define LN_EPS 1e-5f

// ============================================================================
// Helpers
// ============================================================================
__device__ __forceinline__ uint32_t smem_u32(const void* p) {
    uint32_t a;
    asm("{ .reg .u64 t; cvta.to.shared.u64 t, %1; cvt.u32.u64 %0, t; }"
        : "=r"(a) : "l"(p));
    return a;
}
#define SW128(o) ((o) ^ (((o) >> 3) & 0x70))

__device__ __forceinline__ void cp16(uint32_t s, const void* g) {
    asm volatile("cp.async.cg.shared.global [%0], [%1], 16;" :: "r"(s), "l"(g));
}
#define CP_COMMIT() asm volatile("cp.async.commit_group;" ::: "memory")
#define CP_WAIT1()  asm volatile("cp.async.wait_group 1;" ::: "memory")

#define LDSM_X4(r0, r1, r2, r3, addr) \
    asm volatile("ldmatrix.sync.aligned.m8n8.x4.shared.b16 {%0,%1,%2,%3}, [%4];" \
        : "=r"(r0), "=r"(r1), "=r"(r2), "=r"(r3) : "r"(addr))
#define LDSM_X4_T(r0, r1, r2, r3, addr) \
    asm volatile("ldmatrix.sync.aligned.m8n8.x4.trans.shared.b16 {%0,%1,%2,%3}, [%4];" \
        : "=r"(r0), "=r"(r1), "=r"(r2), "=r"(r3) : "r"(addr))

__device__ __forceinline__ void mma_bf16(float* c, const uint32_t* a, const uint32_t* b) {
    asm volatile(
        "mma.sync.aligned.m16n8k16.row.col.f32.bf16.bf16.f32 "
        "{%0,%1,%2,%3}, {%4,%5,%6,%7}, {%8,%9}, {%0,%1,%2,%3};"
        : "+f"(c[0]), "+f"(c[1]), "+f"(c[2]), "+f"(c[3])
        : "r"(a[0]), "r"(a[1]), "r"(a[2]), "r"(a[3]), "r"(b[0]), "r"(b[1]));
}
__device__ __forceinline__ void mma4(float* c, const uint32_t* a, uint32_t b0, uint32_t b1) {
    uint32_t b[2] = { b0, b1 };
    mma_bf16(c, a, b);
}

__device__ __forceinline__ void split2(float v, __nv_bfloat16& h, __nv_bfloat16& l) {
    h = __float2bfloat16(v);
    l = __float2bfloat16(v - __bfloat162float(h));
}
__device__ __forceinline__ void pack_split(float a, float b, uint32_t& hi, uint32_t& lo) {
    __nv_bfloat16 ha = __float2bfloat16(a);
    __nv_bfloat16 hb = __float2bfloat16(b);
    __nv_bfloat162 H(ha, hb);
    __nv_bfloat162 L(__float2bfloat16(a - __bfloat162float(ha)),
                     __float2bfloat16(b - __bfloat162float(hb)));
    hi = *(uint32_t*)&H;
    lo = *(uint32_t*)&L;
}
__device__ __forceinline__ float gelu_f(float v) {
    return 0.5f * v * (1.0f + erff(v * 0.7071067811865475f));
}

// ============================================================================
// Scratch (device globals)
// ============================================================================
__device__ __align__(16) float g_x  [ROWS * DIM];
__device__ __align__(16) float g_part[2 * ROWS * DIM];
__device__ __align__(16) __nv_bfloat16 g_yh[ROWS * DIM],  g_yl[ROWS * DIM];
__device__ __align__(16) __nv_bfloat16 g_oh[ROWS * DIM],  g_ol[ROWS * DIM];
__device__ __align__(16) __nv_bfloat16 g_hh[ROWS * MLPD], g_hl[ROWS * MLPD];
__device__ __align__(16) __nv_bfloat16 g_qh[ROWS * QKV3], g_ql[ROWS * QKV3];
// transposed + split weights: [L][N][K]
__device__ __align__(16) __nv_bfloat16 g_qkvw_h[DEPTH * QKV3 * DIM], g_qkvw_l[DEPTH * QKV3 * DIM];
__device__ __align__(16) __nv_bfloat16 g_outw_h[DEPTH * DIM * DIM],  g_outw_l[DEPTH * DIM * DIM];
__device__ __align__(16) __nv_bfloat16 g_m1w_h [DEPTH * MLPD * DIM], g_m1w_l [DEPTH * MLPD * DIM];
__device__ __align__(16) __nv_bfloat16 g_m2w_h [DEPTH * DIM * MLPD], g_m2w_l [DEPTH * DIM * MLPD];

// ============================================================================
// Combined weight transpose + bf16 split (one launch).
// ============================================================================
#define WL_BLOCKS 6912
__global__ void wsplit_all_kernel(
    const float* __restrict__ qkv_w, const float* __restrict__ out_w,
    const float* __restrict__ m1w,   const float* __restrict__ m2w,
    __nv_bfloat16* qh, __nv_bfloat16* ql,
    __nv_bfloat16* owh, __nv_bfloat16* owl,
    __nv_bfloat16* m1h, __nv_bfloat16* m1l,
    __nv_bfloat16* m2h, __nv_bfloat16* m2l)
{
    int z = blockIdx.x;
    int l = z / WL_BLOCKS, r = z % WL_BLOCKS;
    const float* w; __nv_bfloat16 *hi, *lo; int K, N, nx, ny;
    if (r < 1728)      { w = qkv_w; hi = qh;  lo = ql;  K = DIM;  N = QKV3; nx = r % 72; ny = r / 72; }
    else if (r < 2304) { int rr = r - 1728; w = out_w; hi = owh; lo = owl; K = DIM;  N = DIM;  nx = rr % 24; ny = rr / 24; }
    else if (r < 4608) { int rr = r - 2304; w = m1w;   hi = m1h; lo = m1l; K = DIM;  N = MLPD; nx = rr % 96; ny = rr / 96; }
    else               { int rr = r - 4608; w = m2w;   hi = m2h; lo = m2l; K = MLPD; N = DIM;  nx = rr % 24; ny = rr / 24; }
    __shared__ float t[32][33];
    int n0 = nx * 32, k0 = ny * 32;
    int tx = threadIdx.x, ty = threadIdx.y;
    const float* wl = w + (size_t)l * K * N;
    for (int i = ty; i < 32; i += 8)
        t[i][tx] = wl[(size_t)(k0 + i) * N + n0 + tx];
    __syncthreads();
    size_t ob = (size_t)l * K * N;
    for (int i = ty; i < 32; i += 8) {
        float v = t[tx][i];
        __nv_bfloat16 h, lw;
        split2(v, h, lw);
        size_t o = ob + (size_t)(n0 + i) * K + k0 + tx;
        hi[o] = h; lo[o] = lw;
    }
}

// ============================================================================
// Embed GEMM with fused sine pos-embed
// ============================================================================
__device__ __forceinline__ float posval(int n, int d) {
    int r = n >> 5, c = n & 31;
    int id = (d < 384) ? d : d - 384;
    float coord = (d < 384) ? (float)(r + 1) : (float)(c + 1);
    float ang = coord * (6.283185307179586f / (32.0f + 1e-6f));
    float ex = (float)(2 * (id / 2)) * (1.0f / 384.0f);
    float p = ang / __powf(10000.0f, ex);
    return (id & 1) ? cosf(p) : sinf(p);
}

__global__ __launch_bounds__(256) void embed_kernel(
    const float* __restrict__ cf, const float* __restrict__ w,
    const float* __restrict__ bias, float* __restrict__ x)
{
    __shared__ float As[16][64];
    __shared__ float Bs[16][68];
    int b  = blockIdx.z;
    int n0 = blockIdx.x * 64, d0 = blockIdx.y * 64;
    int tid = threadIdx.x;
    int ty = tid / 16, tx = tid % 16;
    float acc[4][4] = {};
    const float* cfb = cf + (size_t)b * F_DIM * NTOK;
    for (int k0 = 0; k0 < F_DIM; k0 += 16) {
        #pragma unroll
        for (int it = 0; it < 4; it++) {
            int idx = tid + it * 256;
            As[idx >> 6][idx & 63] = cfb[(size_t)(k0 + (idx >> 6)) * NTOK + n0 + (idx & 63)];
        }
        #pragma unroll
        for (int it = 0; it < 4; it++) {
            int idx = tid + it * 256;
            Bs[idx & 15][idx >> 4] = w[(size_t)(d0 + (idx >> 4)) * F_DIM + k0 + (idx & 15)];
        }
        __syncthreads();
        #pragma unroll
        for (int kk = 0; kk < 16; kk++) {
            float a[4], bb[4];
            #pragma unroll
            for (int i = 0; i < 4; i++) a[i]  = As[kk][ty * 4 + i];
            #pragma unroll
            for (int j = 0; j < 4; j++) bb[j] = Bs[kk][tx * 4 + j];
            #pragma unroll
            for (int i = 0; i < 4; i++)
                #pragma unroll
                for (int j = 0; j < 4; j++)
                    acc[i][j] += a[i] * bb[j];
        }
        __syncthreads();
    }
    #pragma unroll
    for (int i = 0; i < 4; i++) {
        int n = n0 + ty * 4 + i;
        #pragma unroll
        for (int j = 0; j < 4; j++) {
            int d = d0 + tx * 4 + j;
            x[((size_t)b * NTOK + n) * DIM + d] = acc[i][j] + bias[d] + posval(n, d);
        }
    }
}

// ============================================================================
// LayerNorm -> split bf16 hi/lo.  Warp-per-row.
// ============================================================================
__global__ __launch_bounds__(256) void ln_split_kernel(
    const float* __restrict__ x, const float* __restrict__ w,
    const float* __restrict__ bias,
    __nv_bfloat16* __restrict__ yh, __nv_bfloat16* __restrict__ yl)
{
    int warp = threadIdx.x >> 5, lane = threadIdx.x & 31;
    int row = blockIdx.x * 8 + warp;
    const float4* xr = (const float4*)(x + (size_t)row * DIM);
    float4 v[6];
    float s = 0.f, ss = 0.f;
    #pragma unroll
    for (int i = 0; i < 6; i++) {
        v[i] = xr[lane + i * 32];
        s  += v[i].x + v[i].y + v[i].z + v[i].w;
        ss += v[i].x * v[i].x + v[i].y * v[i].y + v[i].z * v[i].z + v[i].w * v[i].w;
    }
    #pragma unroll
    for (int off = 16; off; off >>= 1) {
        s  += __shfl_xor_sync(0xffffffffu, s,  off);
        ss += __shfl_xor_sync(0xffffffffu, ss, off);
    }
    float mu  = s * (1.0f / DIM);
    float var = ss * (1.0f / DIM) - mu * mu;
    float inv = rsqrtf(var + LN_EPS);
    const float4* wv = (const float4*)w;
    const float4* bv = (const float4*)bias;
    #pragma unroll
    for (int i = 0; i < 6; i++) {
        int idx4 = lane + i * 32;
        float4 ww = wv[idx4], bb = bv[idx4];
        float y0 = (v[i].x - mu) * inv * ww.x + bb.x;
        float y1 = (v[i].y - mu) * inv * ww.y + bb.y;
        float y2 = (v[i].z - mu) * inv * ww.z + bb.z;
        float y3 = (v[i].w - mu) * inv * ww.w + bb.w;
        uint32_t h01, l01, h23, l23;
        pack_split(y0, y1, h01, l01);
        pack_split(y2, y3, h23, l23);
        uint32_t* ph = (uint32_t*)(yh + (size_t)row * DIM) + idx4 * 2;
        uint32_t* pl = (uint32_t*)(yl + (size_t)row * DIM) + idx4 * 2;
        ph[0] = h01; ph[1] = h23;
        pl[0] = l01; pl[1] = l23;
    }
}

// ============================================================================
// Tensor-core GEMM (bf16x3 split, fp32 accum), 3-stage cp.async pipeline,
// 2 CTAs/SM pinned, hoisted addressing, optional split-K via gridDim.z.
// ============================================================================
#define STG_BYTES 32768
#define MMA_SMEM  (3 * STG_BYTES)   // 98304

__global__ __launch_bounds__(256, 2) void mma_gemm_kernel(
    int K, int N,
    const __nv_bfloat16* __restrict__ Ah, const __nv_bfloat16* __restrict__ Al,
    const __nv_bfloat16* __restrict__ Bh, const __nv_bfloat16* __restrict__ Bl,
    const float* __restrict__ bias, const float* __restrict__ resid,
    float* __restrict__ outf,
    __nv_bfloat16* __restrict__ oh, __nv_bfloat16* __restrict__ ol,
    int gelu)
{
    extern __shared__ char smem[];
    uint32_t sbase = smem_u32(smem);
    int tid = threadIdx.x, wid = tid >> 5, lane = tid & 31;
    int n0 = blockIdx.x * 128, m0 = blockIdx.y * 128;

    // split-K range
    int nch_tot = K / 32;
    int per = nch_tot / gridDim.z;
    int ch_begin = blockIdx.z * per;
    int chend = ch_begin + per;

    // hoisted cp.async addressing
    int r_cp = tid >> 2, c_cp = tid & 3;
    uint32_t soff0 = SW128((uint32_t)(r_cp * 64 + c_cp * 16));
    uint32_t soff1 = SW128((uint32_t)((r_cp + 64) * 64 + c_cp * 16));
    size_t goff0 = ((size_t)r_cp * K + c_cp * 8) * 2;
    size_t goff1 = ((size_t)(r_cp + 64) * K + c_cp * 8) * 2;
    const char* pAh = (const char*)(Ah + (size_t)m0 * K);
    const char* pAl = (const char*)(Al + (size_t)m0 * K);
    const char* pBh = (const char*)(Bh + (size_t)n0 * K);
    const char* pBl = (const char*)(Bl + (size_t)n0 * K);

#define ISSUE(CH) do { \
    if ((CH) < chend) { \
        uint32_t sb0 = sbase + (uint32_t)((CH) % 3) * STG_BYTES; \
        size_t kb = (size_t)(CH) * 64; \
        cp16(sb0 +          soff0, pAh + kb + goff0); \
        cp16(sb0 +          soff1, pAh + kb + goff1); \
        cp16(sb0 + 8192  +  soff0, pAl + kb + goff0); \
        cp16(sb0 + 8192  +  soff1, pAl + kb + goff1); \
        cp16(sb0 + 16384 +  soff0, pBh + kb + goff0); \
        cp16(sb0 + 16384 +  soff1, pBh + kb + goff1); \
        cp16(sb0 + 24576 +  soff0, pBl + kb + goff0); \
        cp16(sb0 + 24576 +  soff1, pBl + kb + goff1); \
    } \
    CP_COMMIT(); } while (0)

    int wm = wid >> 2, wn = wid & 3;
    uint32_t lrow = lane & 15, lhalf = lane >> 4;

    // hoisted ldmatrix swizzled offsets (lo tile = hi addr + 8192)
    uint32_t aoff[2][4], boff[2][2];
    #pragma unroll
    for (int ks = 0; ks < 2; ks++) {
        uint32_t koff = (uint32_t)(ks * 2 + lhalf) * 16;
        #pragma unroll
        for (int mf = 0; mf < 4; mf++)
            aoff[ks][mf] = SW128((uint32_t)((wm * 64 + mf * 16 + lrow) * 64) + koff);
        #pragma unroll
        for (int nf2 = 0; nf2 < 2; nf2++)
            boff[ks][nf2] = SW128((uint32_t)((wn * 32 + nf2 * 16 + lrow) * 64) + koff);
    }

    float acc[4][4][4] = {};

    ISSUE(ch_begin);
    ISSUE(ch_begin + 1);

    for (int ch = ch_begin; ch < chend; ch++) {
        CP_WAIT1();
        __syncthreads();
        ISSUE(ch + 2);
        uint32_t st = sbase + (uint32_t)(ch % 3) * STG_BYTES;
        #pragma unroll
        for (int ks = 0; ks < 2; ks++) {
            uint32_t ah[4][4], al[4][4], bh[4][2], bl[4][2];
            #pragma unroll
            for (int mf = 0; mf < 4; mf++) {
                uint32_t a0 = st + aoff[ks][mf];
                LDSM_X4(ah[mf][0], ah[mf][1], ah[mf][2], ah[mf][3], a0);
                LDSM_X4(al[mf][0], al[mf][1], al[mf][2], al[mf][3], a0 + 8192);
            }
            #pragma unroll
            for (int nf2 = 0; nf2 < 2; nf2++) {
                uint32_t b0 = st + 16384 + boff[ks][nf2];
                uint32_t t0, t1, t2, t3;
                LDSM_X4(t0, t1, t2, t3, b0);
                bh[nf2 * 2][0] = t0; bh[nf2 * 2 + 1][0] = t1;
                bh[nf2 * 2][1] = t2; bh[nf2 * 2 + 1][1] = t3;
                LDSM_X4(t0, t1, t2, t3, b0 + 8192);
                bl[nf2 * 2][0] = t0; bl[nf2 * 2 + 1][0] = t1;
                bl[nf2 * 2][1] = t2; bl[nf2 * 2 + 1][1] = t3;
            }
            #pragma unroll
            for (int mf = 0; mf < 4; mf++) {
                #pragma unroll
                for (int nf = 0; nf < 4; nf++) {
                    mma_bf16(acc[mf][nf], ah[mf], bh[nf]);
                    mma_bf16(acc[mf][nf], ah[mf], bl[nf]);
                    mma_bf16(acc[mf][nf], al[mf], bh[nf]);
                }
            }
        }
    }
#undef ISSUE

    // Epilogue
    float* myout = outf ? (outf + (size_t)blockIdx.z * ((size_t)ROWS * N)) : (float*)0;
    int g = lane >> 2, tg = lane & 3;
    #pragma unroll
    for (int mf = 0; mf < 4; mf++) {
        #pragma unroll
        for (int nf = 0; nf < 4; nf++) {
            int col = n0 + wn * 32 + nf * 8 + tg * 2;
            float bv0 = bias ? __ldg(bias + col)     : 0.f;
            float bv1 = bias ? __ldg(bias + col + 1) : 0.f;
            #pragma unroll
            for (int half = 0; half < 2; half++) {
                int row = m0 + wm * 64 + mf * 16 + g + half * 8;
                float v0 = acc[mf][nf][half * 2 + 0] + bv0;
                float v1 = acc[mf][nf][half * 2 + 1] + bv1;
                if (gelu) { v0 = gelu_f(v0); v1 = gelu_f(v1); }
                size_t gb = (size_t)row * N + col;
                if (resid) {
                    float2 rr = *(const float2*)(resid + gb);
                    v0 += rr.x; v1 += rr.y;
                }
                if (myout) {
                    *(float2*)(myout + gb) = make_float2(v0, v1);
                } else {
                    __nv_bfloat16 h0, l0, h1, l1;
                    split2(v0, h0, l0); split2(v1, h1, l1);
                    *(__nv_bfloat162*)(oh + gb) = __nv_bfloat162(h0, h1);
                    *(__nv_bfloat162*)(ol + gb) = __nv_bfloat162(l0, l1);
                }
            }
        }
    }
}

// ============================================================================
// Split-K reduce: x += p0 + p1 + bias   (vectorized)
// ============================================================================
__global__ __launch_bounds__(256) void reduce_add_kernel(
    const float* __restrict__ part, const float* __restrict__ bias,
    float* __restrict__ x, int N)
{
    int i = blockIdx.x * 256 + threadIdx.x;          // float4 index
    const float4* p0 = (const float4*)part;
    const float4* p1 = p0 + ((size_t)ROWS * N) / 4;
    float4 a = p0[i], b = p1[i];
    float4 xx = ((const float4*)x)[i];
    float4 bb = ((const float4*)bias)[i & (N / 4 - 1)];
    xx.x += a.x + b.x + bb.x;
    xx.y += a.y + b.y + bb.y;
    xx.z += a.z + b.z + bb.z;
    xx.w += a.w + b.w + bb.w;
    ((float4*)x)[i] = xx;
}

// ============================================================================
// Flash attention via mma.sync (bf16 split Q,K,V,P; fp32 softmax/accum).
// ============================================================================
#define ATT_SMEM 65536

__device__ __forceinline__ void attn_issue(
    int kt, int tid, uint32_t sb,
    const __nv_bfloat16* qh, const __nv_bfloat16* ql,
    size_t batch_row0, int kcol, int vcol)
{
    if (kt < 16) {
        uint32_t st = sb + (uint32_t)(kt & 1) * 32768;
        size_t rb = batch_row0 + (size_t)kt * 64;
        #pragma unroll
        for (int i = 0; i < 2; i++) {
            int idx = tid + i * 256;
            int r = idx >> 3, c = idx & 7;
            size_t rowoff = (rb + r) * QKV3;
            uint32_t so = SW128((uint32_t)(r * 128 + c * 16));
            cp16(st +         so, (const char*)(qh + rowoff + kcol) + c * 16);
            cp16(st + 8192  + so, (const char*)(ql + rowoff + kcol) + c * 16);
            cp16(st + 16384 + so, (const char*)(qh + rowoff + vcol) + c * 16);
            cp16(st + 24576 + so, (const char*)(ql + rowoff + vcol) + c * 16);
        }
    }
    CP_COMMIT();
}

__global__ __launch_bounds__(256) void flash_mma_kernel(
    const __nv_bfloat16* __restrict__ qh, const __nv_bfloat16* __restrict__ ql,
    __nv_bfloat16* __restrict__ oh, __nv_bfloat16* __restrict__ ol)
{
    extern __shared__ char smem[];
    uint32_t sb = smem_u32(smem);
    int tid = threadIdx.x, wid = tid >> 5, lane = tid & 31;
    int qt = blockIdx.x;
    int b = blockIdx.y / HEADS, h = blockIdx.y % HEADS;
    int g = lane >> 2, tg = lane & 3;
    size_t batch_row0 = (size_t)b * NTOK;
    size_t qrow0 = batch_row0 + (size_t)qt * 128;
    int qcol = h * 64, kcol = DIM + h * 64, vcol = 2 * DIM + h * 64;

    #pragma unroll
    for (int i = 0; i < 4; i++) {
        int idx = tid + i * 256;
        int r = idx >> 3, c = idx & 7;
        size_t rowoff = (qrow0 + r) * QKV3 + qcol;
        uint32_t so = SW128((uint32_t)(r * 128 + c * 16));
        *(uint4*)(smem + so)         = *((const uint4*)(qh + rowoff) + c);
        *(uint4*)(smem + 16384 + so) = *((const uint4*)(ql + rowoff) + c);
    }
    __syncthreads();

    uint32_t ah[4][4], al[4][4];
    {
        uint32_t lrow = lane & 15, lh = lane >> 4;
        #pragma unroll
        for (int kf = 0; kf < 4; kf++) {
            uint32_t ro = (uint32_t)((wid * 16 + lrow) * 128) + kf * 32 + lh * 16;
            LDSM_X4(ah[kf][0], ah[kf][1], ah[kf][2], ah[kf][3], sb + SW128(ro));
            LDSM_X4(al[kf][0], al[kf][1], al[kf][2], al[kf][3], sb + 16384 + SW128(ro));
        }
    }
    __syncthreads();

    float m0v = -1e30f, m1v = -1e30f, l0 = 0.f, l1 = 0.f;
    float oacc[8][4] = {};
    const float scale = 0.125f;

    attn_issue(0, tid, sb, qh, ql, batch_row0, kcol, vcol);

    for (int kt = 0; kt < 16; kt++) {
        attn_issue(kt + 1, tid, sb, qh, ql, batch_row0, kcol, vcol);
        CP_WAIT1();
        __syncthreads();
        uint32_t kb = sb + (uint32_t)(kt & 1) * 32768;

        float sc[8][4] = {};
        #pragma unroll
        for (int kg = 0; kg < 4; kg++) {
            #pragma unroll
            for (int kf = 0; kf < 4; kf++) {
                uint32_t ro = (uint32_t)((kg * 16 + (lane & 15)) * 128) + kf * 32 + (lane >> 4) * 16;
                uint32_t t0, t1, t2, t3, u0, u1, u2, u3;
                LDSM_X4(t0, t1, t2, t3, kb + SW128(ro));
                LDSM_X4(u0, u1, u2, u3, kb + 8192 + SW128(ro));
                mma4(sc[2 * kg],     ah[kf], t0, t2);
                mma4(sc[2 * kg],     ah[kf], u0, u2);
                mma4(sc[2 * kg],     al[kf], t0, t2);
                mma4(sc[2 * kg + 1], ah[kf], t1, t3);
                mma4(sc[2 * kg + 1], ah[kf], u1, u3);
                mma4(sc[2 * kg + 1], al[kf], t1, t3);
            }
        }

        float mx0 = -1e30f, mx1 = -1e30f;
        #pragma unroll
        for (int nf = 0; nf < 8; nf++) {
            #pragma unroll
            for (int i = 0; i < 4; i++) sc[nf][i] *= scale;
            mx0 = fmaxf(mx0, fmaxf(sc[nf][0], sc[nf][1]));
            mx1 = fmaxf(mx1, fmaxf(sc[nf][2], sc[nf][3]));
        }
        mx0 = fmaxf(mx0, __shfl_xor_sync(0xffffffffu, mx0, 1));
        mx0 = fmaxf(mx0, __shfl_xor_sync(0xffffffffu, mx0, 2));
        mx1 = fmaxf(mx1, __shfl_xor_sync(0xffffffffu, mx1, 1));
        mx1 = fmaxf(mx1, __shfl_xor_sync(0xffffffffu, mx1, 2));
        float nm0 = fmaxf(m0v, mx0), nm1 = fmaxf(m1v, mx1);
        float c0 = __expf(m0v - nm0), c1 = __expf(m1v - nm1);
        l0 *= c0; l1 *= c1;
        #pragma unroll
        for (int nf = 0; nf < 8; nf++) {
            oacc[nf][0] *= c0; oacc[nf][1] *= c0;
            oacc[nf][2] *= c1; oacc[nf][3] *= c1;
        }
        m0v = nm0; m1v = nm1;
        float ps0 = 0.f, ps1 = 0.f;
        #pragma unroll
        for (int nf = 0; nf < 8; nf++) {
            sc[nf][0] = __expf(sc[nf][0] - nm0);
            sc[nf][1] = __expf(sc[nf][1] - nm0);
            sc[nf][2] = __expf(sc[nf][2] - nm1);
            sc[nf][3] = __expf(sc[nf][3] - nm1);
            ps0 += sc[nf][0] + sc[nf][1];
            ps1 += sc[nf][2] + sc[nf][3];
        }
        ps0 += __shfl_xor_sync(0xffffffffu, ps0, 1);
        ps0 += __shfl_xor_sync(0xffffffffu, ps0, 2);
        ps1 += __shfl_xor_sync(0xffffffffu, ps1, 1);
        ps1 += __shfl_xor_sync(0xffffffffu, ps1, 2);
        l0 += ps0; l1 += ps1;

        #pragma unroll
        for (int c = 0; c < 4; c++) {
            uint32_t pah[4], pal[4];
            pack_split(sc[2 * c][0],     sc[2 * c][1],     pah[0], pal[0]);
            pack_split(sc[2 * c][2],     sc[2 * c][3],     pah[1], pal[1]);
            pack_split(sc[2 * c + 1][0], sc[2 * c + 1][1], pah[2], pal[2]);
            pack_split(sc[2 * c + 1][2], sc[2 * c + 1][3], pah[3], pal[3]);
            #pragma unroll
            for (int dg = 0; dg < 4; dg++) {
                uint32_t ro = (uint32_t)((c * 16 + (lane & 15)) * 128) + dg * 32 + (lane >> 4) * 16;
                uint32_t t0, t1, t2, t3, u0, u1, u2, u3;
                LDSM_X4_T(t0, t1, t2, t3, kb + 16384 + SW128(ro));
                LDSM_X4_T(u0, u1, u2, u3, kb + 24576 + SW128(ro));
                mma4(oacc[2 * dg],     pah, t0, t1);
                mma4(oacc[2 * dg],     pah, u0, u1);
                mma4(oacc[2 * dg],     pal, t0, t1);
                mma4(oacc[2 * dg + 1], pah, t2, t3);
                mma4(oacc[2 * dg + 1], pah, u2, u3);
                mma4(oacc[2 * dg + 1], pal, t2, t3);
            }
        }
        __syncthreads();
    }

    float inv0 = 1.f / l0, inv1 = 1.f / l1;
    size_t r0 = qrow0 + wid * 16 + g;
    #pragma unroll
    for (int nf = 0; nf < 8; nf++) {
        int col = h * 64 + nf * 8 + tg * 2;
        float v0 = oacc[nf][0] * inv0, v1 = oacc[nf][1] * inv0;
        float v2 = oacc[nf][2] * inv1, v3 = oacc[nf][3] * inv1;
        __nv_bfloat16 h0, lo0, h1, lo1;
        split2(v0, h0, lo0); split2(v1, h1, lo1);
        *(__nv_bfloat162*)(oh + r0 * DIM + col) = __nv_bfloat162(h0, h1);
        *(__nv_bfloat162*)(ol + r0 * DIM + col) = __nv_bfloat162(lo0, lo1);
        split2(v2, h0, lo0); split2(v3, h1, lo1);
        *(__nv_bfloat162*)(oh + (r0 + 8) * DIM + col) = __nv_bfloat162(h0, h1);
        *(__nv_bfloat162*)(ol + (r0 + 8) * DIM + col) = __nv_bfloat162(lo0, lo1);
    }
}

// ============================================================================
// Final transpose: x[b,n,d] -> out[b,d,n]
// ============================================================================
__global__ void transpose_out_kernel(const float* __restrict__ x,
                                     float* __restrict__ out)
{
    __shared__ float t[32][33];
    int b = blockIdx.z;
    int n0 = blockIdx.x * 32, d0 = blockIdx.y * 32;
    int tx = threadIdx.x, ty = threadIdx.y;
    for (int i = ty; i < 32; i += 8)
        t[i][tx] = x[((size_t)b * NTOK + n0 + i) * DIM + d0 + tx];
    __syncthreads();
    for (int i = ty; i < 32; i += 8)
        out[((size_t)b * DIM + d0 + i) * NTOK + n0 + tx] = t[tx][i];
}

// ============================================================================
// Host orchestration
// ============================================================================
extern "C" void kernel_launch(void* const* d_in, const int* in_sizes, int n_in,
                              void* d_out, int out_size)
{
    const float* c_f    = (const float*)d_in[0];
    const float* conv_w = (const float*)d_in[1];
    const float* conv_b = (const float*)d_in[2];
    const float* ln1_w  = (const float*)d_in[3];
    const float* ln1_b  = (const float*)d_in[4];
    const float* qkv_w  = (const float*)d_in[5];
    const float* out_w  = (const float*)d_in[6];
    const float* out_b  = (const float*)d_in[7];
    const float* ln2_w  = (const float*)d_in[8];
    const float* ln2_b  = (const float*)d_in[9];
    const float* mlp_w1 = (const float*)d_in[10];
    const float* mlp_b1 = (const float*)d_in[11];
    const float* mlp_w2 = (const float*)d_in[12];
    const float* mlp_b2 = (const float*)d_in[13];
    float* out = (float*)d_out;

    cudaFuncSetAttribute(mma_gemm_kernel,
                         cudaFuncAttributeMaxDynamicSharedMemorySize, MMA_SMEM);
    cudaFuncSetAttribute(flash_mma_kernel,
                         cudaFuncAttributeMaxDynamicSharedMemorySize, ATT_SMEM);

    float *p_x, *p_part;
    __nv_bfloat16 *p_yh, *p_yl, *p_oh, *p_ol, *p_hh, *p_hl, *p_qh, *p_ql;
    __nv_bfloat16 *p_qwh, *p_qwl, *p_owh, *p_owl, *p_m1h, *p_m1l, *p_m2h, *p_m2l;
    cudaGetSymbolAddress((void**)&p_x,    g_x);
    cudaGetSymbolAddress((void**)&p_part, g_part);
    cudaGetSymbolAddress((void**)&p_yh,  g_yh);
    cudaGetSymbolAddress((void**)&p_yl,  g_yl);
    cudaGetSymbolAddress((void**)&p_oh,  g_oh);
    cudaGetSymbolAddress((void**)&p_ol,  g_ol);
    cudaGetSymbolAddress((void**)&p_hh,  g_hh);
    cudaGetSymbolAddress((void**)&p_hl,  g_hl);
    cudaGetSymbolAddress((void**)&p_qh,  g_qh);
    cudaGetSymbolAddress((void**)&p_ql,  g_ql);
    cudaGetSymbolAddress((void**)&p_qwh, g_qkvw_h);
    cudaGetSymbolAddress((void**)&p_qwl, g_qkvw_l);
    cudaGetSymbolAddress((void**)&p_owh, g_outw_h);
    cudaGetSymbolAddress((void**)&p_owl, g_outw_l);
    cudaGetSymbolAddress((void**)&p_m1h, g_m1w_h);
    cudaGetSymbolAddress((void**)&p_m1l, g_m1w_l);
    cudaGetSymbolAddress((void**)&p_m2h, g_m2w_h);
    cudaGetSymbolAddress((void**)&p_m2l, g_m2w_l);

    wsplit_all_kernel<<<DEPTH * WL_BLOCKS, dim3(32, 8)>>>(
        qkv_w, out_w, mlp_w1, mlp_w2,
        p_qwh, p_qwl, p_owh, p_owl, p_m1h, p_m1l, p_m2h, p_m2l);

    embed_kernel<<<dim3(NTOK / 64, DIM / 64, BATCH), 256>>>(c_f, conv_w, conv_b, p_x);

    for (int l = 0; l < DEPTH; l++) {
        ln_split_kernel<<<ROWS / 8, 256>>>(p_x, ln1_w + l * DIM, ln1_b + l * DIM, p_yh, p_yl);
        mma_gemm_kernel<<<dim3(QKV3 / 128, ROWS / 128, 1), 256, MMA_SMEM>>>(
            DIM, QKV3, p_yh, p_yl,
            p_qwh + (size_t)l * QKV3 * DIM, p_qwl + (size_t)l * QKV3 * DIM,
            nullptr, nullptr, nullptr, p_qh, p_ql, 0);
        flash_mma_kernel<<<dim3(NTOK / 128, BATCH * HEADS), 256, ATT_SMEM>>>(
            p_qh, p_ql, p_oh, p_ol);
        // attn out-proj: split-K=2 -> partials -> fused reduce (+bias +resid into x)
        mma_gemm_kernel<<<dim3(DIM / 128, ROWS / 128, 2), 256, MMA_SMEM>>>(
            DIM, DIM, p_oh, p_ol,
            p_owh + (size_t)l * DIM * DIM, p_owl + (size_t)l * DIM * DIM,
            nullptr, nullptr, p_part, nullptr, nullptr, 0);
        reduce_add_kernel<<<ROWS * DIM / 1024, 256>>>(p_part, out_b + l * DIM, p_x, DIM);
        ln_split_kernel<<<ROWS / 8, 256>>>(p_x, ln2_w + l * DIM, ln2_b + l * DIM, p_yh, p_yl);
        mma_gemm_kernel<<<dim3(MLPD / 128, ROWS / 128, 1), 256, MMA_SMEM>>>(
            DIM, MLPD, p_yh, p_yl,
            p_m1h + (size_t)l * MLPD * DIM, p_m1l + (size_t)l * MLPD * DIM,
            mlp_b1 + l * MLPD, nullptr, nullptr, p_hh, p_hl, 1);
        // mlp2: split-K=2
        mma_gemm_kernel<<<dim3(DIM / 128, ROWS / 128, 2), 256, MMA_SMEM>>>(
            MLPD, DIM, p_hh, p_hl,
            p_m2h + (size_t)l * DIM * MLPD, p_m2l + (size_t)l * DIM * MLPD,
            nullptr, nullptr, p_part, nullptr, nullptr, 0);
        reduce_add_kernel<<<ROWS * DIM / 1024, 256>>>(p_part, mlp_b2 + l * DIM, p_x, DIM);
    }

    transpose_out_kernel<<<dim3(NTOK / 32, DIM / 32, BATCH), dim3(32, 8)>>>(p_x, out);
}

// round 12
// speedup vs baseline: 5.2218x; 1.0190x over previous
#include <cuda_runtime.h>
#include <cuda_bf16.h>
#include <math.h>
#include <stdint.h>

#define DIM 768
#define NTOK 1024
#define BATCH 4
#define ROWS (BATCH * NTOK)        // 4096
#define F_DIM 256
#define HEADS 12
#define DHEAD 64
#define QKV3 (3 * DIM)             // 2304
#define MLPD 3072
#define DEPTH 8
#define LN_EPS 1e-5f

// ============================================================================
// Helpers
// ============================================================================
__device__ __forceinline__ uint32_t smem_u32(const void* p) {
    uint32_t a;
    asm("{ .reg .u64 t; cvta.to.shared.u64 t, %1; cvt.u32.u64 %0, t; }"
        : "=r"(a) : "l"(p));
    return a;
}
#define SW128(o) ((o) ^ (((o) >> 3) & 0x70))

__device__ __forceinline__ void cp16(uint32_t s, const void* g) {
    asm volatile("cp.async.cg.shared.global [%0], [%1], 16;" :: "r"(s), "l"(g));
}
#define CP_COMMIT() asm volatile("cp.async.commit_group;" ::: "memory")
#define CP_WAIT1()  asm volatile("cp.async.wait_group 1;" ::: "memory")

#define LDSM_X4(r0, r1, r2, r3, addr) \
    asm volatile("ldmatrix.sync.aligned.m8n8.x4.shared.b16 {%0,%1,%2,%3}, [%4];" \
        : "=r"(r0), "=r"(r1), "=r"(r2), "=r"(r3) : "r"(addr))
#define LDSM_X4_T(r0, r1, r2, r3, addr) \
    asm volatile("ldmatrix.sync.aligned.m8n8.x4.trans.shared.b16 {%0,%1,%2,%3}, [%4];" \
        : "=r"(r0), "=r"(r1), "=r"(r2), "=r"(r3) : "r"(addr))

__device__ __forceinline__ void mma_bf16(float* c, const uint32_t* a, const uint32_t* b) {
    asm volatile(
        "mma.sync.aligned.m16n8k16.row.col.f32.bf16.bf16.f32 "
        "{%0,%1,%2,%3}, {%4,%5,%6,%7}, {%8,%9}, {%0,%1,%2,%3};"
        : "+f"(c[0]), "+f"(c[1]), "+f"(c[2]), "+f"(c[3])
        : "r"(a[0]), "r"(a[1]), "r"(a[2]), "r"(a[3]), "r"(b[0]), "r"(b[1]));
}
__device__ __forceinline__ void mma4(float* c, const uint32_t* a, uint32_t b0, uint32_t b1) {
    uint32_t b[2] = { b0, b1 };
    mma_bf16(c, a, b);
}

__device__ __forceinline__ void split2(float v, __nv_bfloat16& h, __nv_bfloat16& l) {
    h = __float2bfloat16(v);
    l = __float2bfloat16(v - __bfloat162float(h));
}
__device__ __forceinline__ void pack_split(float a, float b, uint32_t& hi, uint32_t& lo) {
    __nv_bfloat16 ha = __float2bfloat16(a);
    __nv_bfloat16 hb = __float2bfloat16(b);
    __nv_bfloat162 H(ha, hb);
    __nv_bfloat162 L(__float2bfloat16(a - __bfloat162float(ha)),
                     __float2bfloat16(b - __bfloat162float(hb)));
    hi = *(uint32_t*)&H;
    lo = *(uint32_t*)&L;
}
__device__ __forceinline__ float gelu_f(float v) {
    return 0.5f * v * (1.0f + erff(v * 0.7071067811865475f));
}

// ============================================================================
// Scratch (device globals)
// ============================================================================
__device__ __align__(16) float g_x  [ROWS * DIM];
__device__ __align__(16) float g_part[2 * ROWS * DIM];
__device__ __align__(16) __nv_bfloat16 g_yh[ROWS * DIM],  g_yl[ROWS * DIM];
__device__ __align__(16) __nv_bfloat16 g_oh[ROWS * DIM],  g_ol[ROWS * DIM];
__device__ __align__(16) __nv_bfloat16 g_hh[ROWS * MLPD], g_hl[ROWS * MLPD];
__device__ __align__(16) __nv_bfloat16 g_qh[ROWS * QKV3], g_ql[ROWS * QKV3];
// transposed + split weights: [L][N][K]
__device__ __align__(16) __nv_bfloat16 g_qkvw_h[DEPTH * QKV3 * DIM], g_qkvw_l[DEPTH * QKV3 * DIM];
__device__ __align__(16) __nv_bfloat16 g_outw_h[DEPTH * DIM * DIM],  g_outw_l[DEPTH * DIM * DIM];
__device__ __align__(16) __nv_bfloat16 g_m1w_h [DEPTH * MLPD * DIM], g_m1w_l [DEPTH * MLPD * DIM];
__device__ __align__(16) __nv_bfloat16 g_m2w_h [DEPTH * DIM * MLPD], g_m2w_l [DEPTH * DIM * MLPD];

// ============================================================================
// Combined weight transpose + bf16 split (one launch).
// ============================================================================
#define WL_BLOCKS 6912
__global__ void wsplit_all_kernel(
    const float* __restrict__ qkv_w, const float* __restrict__ out_w,
    const float* __restrict__ m1w,   const float* __restrict__ m2w,
    __nv_bfloat16* qh, __nv_bfloat16* ql,
    __nv_bfloat16* owh, __nv_bfloat16* owl,
    __nv_bfloat16* m1h, __nv_bfloat16* m1l,
    __nv_bfloat16* m2h, __nv_bfloat16* m2l)
{
    int z = blockIdx.x;
    int l = z / WL_BLOCKS, r = z % WL_BLOCKS;
    const float* w; __nv_bfloat16 *hi, *lo; int K, N, nx, ny;
    if (r < 1728)      { w = qkv_w; hi = qh;  lo = ql;  K = DIM;  N = QKV3; nx = r % 72; ny = r / 72; }
    else if (r < 2304) { int rr = r - 1728; w = out_w; hi = owh; lo = owl; K = DIM;  N = DIM;  nx = rr % 24; ny = rr / 24; }
    else if (r < 4608) { int rr = r - 2304; w = m1w;   hi = m1h; lo = m1l; K = DIM;  N = MLPD; nx = rr % 96; ny = rr / 96; }
    else               { int rr = r - 4608; w = m2w;   hi = m2h; lo = m2l; K = MLPD; N = DIM;  nx = rr % 24; ny = rr / 24; }
    __shared__ float t[32][33];
    int n0 = nx * 32, k0 = ny * 32;
    int tx = threadIdx.x, ty = threadIdx.y;
    const float* wl = w + (size_t)l * K * N;
    for (int i = ty; i < 32; i += 8)
        t[i][tx] = wl[(size_t)(k0 + i) * N + n0 + tx];
    __syncthreads();
    size_t ob = (size_t)l * K * N;
    for (int i = ty; i < 32; i += 8) {
        float v = t[tx][i];
        __nv_bfloat16 h, lw;
        split2(v, h, lw);
        size_t o = ob + (size_t)(n0 + i) * K + k0 + tx;
        hi[o] = h; lo[o] = lw;
    }
}

// ============================================================================
// Embed GEMM with fused sine pos-embed
// ============================================================================
__device__ __forceinline__ float posval(int n, int d) {
    int r = n >> 5, c = n & 31;
    int id = (d < 384) ? d : d - 384;
    float coord = (d < 384) ? (float)(r + 1) : (float)(c + 1);
    float ang = coord * (6.283185307179586f / (32.0f + 1e-6f));
    float ex = (float)(2 * (id / 2)) * (1.0f / 384.0f);
    float p = ang / __powf(10000.0f, ex);
    return (id & 1) ? cosf(p) : sinf(p);
}

__global__ __launch_bounds__(256) void embed_kernel(
    const float* __restrict__ cf, const float* __restrict__ w,
    const float* __restrict__ bias, float* __restrict__ x)
{
    __shared__ float As[16][64];
    __shared__ float Bs[16][68];
    int b  = blockIdx.z;
    int n0 = blockIdx.x * 64, d0 = blockIdx.y * 64;
    int tid = threadIdx.x;
    int ty = tid / 16, tx = tid % 16;
    float acc[4][4] = {};
    const float* cfb = cf + (size_t)b * F_DIM * NTOK;
    for (int k0 = 0; k0 < F_DIM; k0 += 16) {
        #pragma unroll
        for (int it = 0; it < 4; it++) {
            int idx = tid + it * 256;
            As[idx >> 6][idx & 63] = cfb[(size_t)(k0 + (idx >> 6)) * NTOK + n0 + (idx & 63)];
        }
        #pragma unroll
        for (int it = 0; it < 4; it++) {
            int idx = tid + it * 256;
            Bs[idx & 15][idx >> 4] = w[(size_t)(d0 + (idx >> 4)) * F_DIM + k0 + (idx & 15)];
        }
        __syncthreads();
        #pragma unroll
        for (int kk = 0; kk < 16; kk++) {
            float a[4], bb[4];
            #pragma unroll
            for (int i = 0; i < 4; i++) a[i]  = As[kk][ty * 4 + i];
            #pragma unroll
            for (int j = 0; j < 4; j++) bb[j] = Bs[kk][tx * 4 + j];
            #pragma unroll
            for (int i = 0; i < 4; i++)
                #pragma unroll
                for (int j = 0; j < 4; j++)
                    acc[i][j] += a[i] * bb[j];
        }
        __syncthreads();
    }
    #pragma unroll
    for (int i = 0; i < 4; i++) {
        int n = n0 + ty * 4 + i;
        #pragma unroll
        for (int j = 0; j < 4; j++) {
            int d = d0 + tx * 4 + j;
            x[((size_t)b * NTOK + n) * DIM + d] = acc[i][j] + bias[d] + posval(n, d);
        }
    }
}

// ============================================================================
// LayerNorm -> split bf16 hi/lo.  Warp-per-row.
// If part != nullptr, first computes x += part0 + part1 + rbias (split-K
// reduce fused in) and writes updated x.
// ============================================================================
__global__ __launch_bounds__(256) void ln_split_kernel(
    const float* __restrict__ part, const float* __restrict__ rbias,
    float* __restrict__ x, const float* __restrict__ w,
    const float* __restrict__ bias,
    __nv_bfloat16* __restrict__ yh, __nv_bfloat16* __restrict__ yl)
{
    int warp = threadIdx.x >> 5, lane = threadIdx.x & 31;
    int row = blockIdx.x * 8 + warp;
    float4* xr = (float4*)(x + (size_t)row * DIM);
    float4 v[6];
    float s = 0.f, ss = 0.f;
    if (part) {
        const float4* p0 = (const float4*)(part + (size_t)row * DIM);
        const float4* p1 = (const float4*)(part + (size_t)(ROWS + row) * DIM);
        const float4* rb = (const float4*)rbias;
        #pragma unroll
        for (int i = 0; i < 6; i++) {
            int idx4 = lane + i * 32;
            float4 a = p0[idx4], b = p1[idx4], bb = rb[idx4];
            v[i] = xr[idx4];
            v[i].x += a.x + b.x + bb.x;
            v[i].y += a.y + b.y + bb.y;
            v[i].z += a.z + b.z + bb.z;
            v[i].w += a.w + b.w + bb.w;
            xr[idx4] = v[i];
            s  += v[i].x + v[i].y + v[i].z + v[i].w;
            ss += v[i].x * v[i].x + v[i].y * v[i].y + v[i].z * v[i].z + v[i].w * v[i].w;
        }
    } else {
        #pragma unroll
        for (int i = 0; i < 6; i++) {
            v[i] = xr[lane + i * 32];
            s  += v[i].x + v[i].y + v[i].z + v[i].w;
            ss += v[i].x * v[i].x + v[i].y * v[i].y + v[i].z * v[i].z + v[i].w * v[i].w;
        }
    }
    #pragma unroll
    for (int off = 16; off; off >>= 1) {
        s  += __shfl_xor_sync(0xffffffffu, s,  off);
        ss += __shfl_xor_sync(0xffffffffu, ss, off);
    }
    float mu  = s * (1.0f / DIM);
    float var = ss * (1.0f / DIM) - mu * mu;
    float inv = rsqrtf(var + LN_EPS);
    const float4* wv = (const float4*)w;
    const float4* bv = (const float4*)bias;
    #pragma unroll
    for (int i = 0; i < 6; i++) {
        int idx4 = lane + i * 32;
        float4 ww = wv[idx4], bb = bv[idx4];
        float y0 = (v[i].x - mu) * inv * ww.x + bb.x;
        float y1 = (v[i].y - mu) * inv * ww.y + bb.y;
        float y2 = (v[i].z - mu) * inv * ww.z + bb.z;
        float y3 = (v[i].w - mu) * inv * ww.w + bb.w;
        uint32_t h01, l01, h23, l23;
        pack_split(y0, y1, h01, l01);
        pack_split(y2, y3, h23, l23);
        uint32_t* ph = (uint32_t*)(yh + (size_t)row * DIM) + idx4 * 2;
        uint32_t* pl = (uint32_t*)(yl + (size_t)row * DIM) + idx4 * 2;
        ph[0] = h01; ph[1] = h23;
        pl[0] = l01; pl[1] = l23;
    }
}

// ============================================================================
// Tensor-core GEMM (bf16x3 split, fp32 accum), 3-stage cp.async pipeline,
// 2 CTAs/SM pinned, hoisted addressing, optional split-K via gridDim.z.
// ============================================================================
#define STG_BYTES 32768
#define MMA_SMEM  (3 * STG_BYTES)   // 98304

__global__ __launch_bounds__(256, 2) void mma_gemm_kernel(
    int K, int N,
    const __nv_bfloat16* __restrict__ Ah, const __nv_bfloat16* __restrict__ Al,
    const __nv_bfloat16* __restrict__ Bh, const __nv_bfloat16* __restrict__ Bl,
    const float* __restrict__ bias, const float* __restrict__ resid,
    float* __restrict__ outf,
    __nv_bfloat16* __restrict__ oh, __nv_bfloat16* __restrict__ ol,
    int gelu)
{
    extern __shared__ char smem[];
    uint32_t sbase = smem_u32(smem);
    int tid = threadIdx.x, wid = tid >> 5, lane = tid & 31;
    int n0 = blockIdx.x * 128, m0 = blockIdx.y * 128;

    // split-K range
    int nch_tot = K / 32;
    int per = nch_tot / gridDim.z;
    int ch_begin = blockIdx.z * per;
    int chend = ch_begin + per;

    // hoisted cp.async addressing
    int r_cp = tid >> 2, c_cp = tid & 3;
    uint32_t soff0 = SW128((uint32_t)(r_cp * 64 + c_cp * 16));
    uint32_t soff1 = SW128((uint32_t)((r_cp + 64) * 64 + c_cp * 16));
    size_t goff0 = ((size_t)r_cp * K + c_cp * 8) * 2;
    size_t goff1 = ((size_t)(r_cp + 64) * K + c_cp * 8) * 2;
    const char* pAh = (const char*)(Ah + (size_t)m0 * K);
    const char* pAl = (const char*)(Al + (size_t)m0 * K);
    const char* pBh = (const char*)(Bh + (size_t)n0 * K);
    const char* pBl = (const char*)(Bl + (size_t)n0 * K);

#define ISSUE(CH) do { \
    if ((CH) < chend) { \
        uint32_t sb0 = sbase + (uint32_t)((CH) % 3) * STG_BYTES; \
        size_t kb = (size_t)(CH) * 64; \
        cp16(sb0 +          soff0, pAh + kb + goff0); \
        cp16(sb0 +          soff1, pAh + kb + goff1); \
        cp16(sb0 + 8192  +  soff0, pAl + kb + goff0); \
        cp16(sb0 + 8192  +  soff1, pAl + kb + goff1); \
        cp16(sb0 + 16384 +  soff0, pBh + kb + goff0); \
        cp16(sb0 + 16384 +  soff1, pBh + kb + goff1); \
        cp16(sb0 + 24576 +  soff0, pBl + kb + goff0); \
        cp16(sb0 + 24576 +  soff1, pBl + kb + goff1); \
    } \
    CP_COMMIT(); } while (0)

    int wm = wid >> 2, wn = wid & 3;
    uint32_t lrow = lane & 15, lhalf = lane >> 4;

    // hoisted ldmatrix swizzled offsets (lo tile = hi addr + 8192)
    uint32_t aoff[2][4], boff[2][2];
    #pragma unroll
    for (int ks = 0; ks < 2; ks++) {
        uint32_t koff = (uint32_t)(ks * 2 + lhalf) * 16;
        #pragma unroll
        for (int mf = 0; mf < 4; mf++)
            aoff[ks][mf] = SW128((uint32_t)((wm * 64 + mf * 16 + lrow) * 64) + koff);
        #pragma unroll
        for (int nf2 = 0; nf2 < 2; nf2++)
            boff[ks][nf2] = SW128((uint32_t)((wn * 32 + nf2 * 16 + lrow) * 64) + koff);
    }

    float acc[4][4][4] = {};

    ISSUE(ch_begin);
    ISSUE(ch_begin + 1);

    for (int ch = ch_begin; ch < chend; ch++) {
        CP_WAIT1();
        __syncthreads();
        ISSUE(ch + 2);
        uint32_t st = sbase + (uint32_t)(ch % 3) * STG_BYTES;
        #pragma unroll
        for (int ks = 0; ks < 2; ks++) {
            uint32_t ah[4][4], al[4][4], bh[4][2], bl[4][2];
            #pragma unroll
            for (int mf = 0; mf < 4; mf++) {
                uint32_t a0 = st + aoff[ks][mf];
                LDSM_X4(ah[mf][0], ah[mf][1], ah[mf][2], ah[mf][3], a0);
                LDSM_X4(al[mf][0], al[mf][1], al[mf][2], al[mf][3], a0 + 8192);
            }
            #pragma unroll
            for (int nf2 = 0; nf2 < 2; nf2++) {
                uint32_t b0 = st + 16384 + boff[ks][nf2];
                uint32_t t0, t1, t2, t3;
                LDSM_X4(t0, t1, t2, t3, b0);
                bh[nf2 * 2][0] = t0; bh[nf2 * 2 + 1][0] = t1;
                bh[nf2 * 2][1] = t2; bh[nf2 * 2 + 1][1] = t3;
                LDSM_X4(t0, t1, t2, t3, b0 + 8192);
                bl[nf2 * 2][0] = t0; bl[nf2 * 2 + 1][0] = t1;
                bl[nf2 * 2][1] = t2; bl[nf2 * 2 + 1][1] = t3;
            }
            #pragma unroll
            for (int mf = 0; mf < 4; mf++) {
                #pragma unroll
                for (int nf = 0; nf < 4; nf++) {
                    mma_bf16(acc[mf][nf], ah[mf], bh[nf]);
                    mma_bf16(acc[mf][nf], ah[mf], bl[nf]);
                    mma_bf16(acc[mf][nf], al[mf], bh[nf]);
                }
            }
        }
    }
#undef ISSUE

    // Epilogue
    float* myout = outf ? (outf + (size_t)blockIdx.z * ((size_t)ROWS * N)) : (float*)0;
    int g = lane >> 2, tg = lane & 3;
    #pragma unroll
    for (int mf = 0; mf < 4; mf++) {
        #pragma unroll
        for (int nf = 0; nf < 4; nf++) {
            int col = n0 + wn * 32 + nf * 8 + tg * 2;
            float bv0 = bias ? __ldg(bias + col)     : 0.f;
            float bv1 = bias ? __ldg(bias + col + 1) : 0.f;
            #pragma unroll
            for (int half = 0; half < 2; half++) {
                int row = m0 + wm * 64 + mf * 16 + g + half * 8;
                float v0 = acc[mf][nf][half * 2 + 0] + bv0;
                float v1 = acc[mf][nf][half * 2 + 1] + bv1;
                if (gelu) { v0 = gelu_f(v0); v1 = gelu_f(v1); }
                size_t gb = (size_t)row * N + col;
                if (resid) {
                    float2 rr = *(const float2*)(resid + gb);
                    v0 += rr.x; v1 += rr.y;
                }
                if (myout) {
                    *(float2*)(myout + gb) = make_float2(v0, v1);
                } else {
                    __nv_bfloat16 h0, l0, h1, l1;
                    split2(v0, h0, l0); split2(v1, h1, l1);
                    *(__nv_bfloat162*)(oh + gb) = __nv_bfloat162(h0, h1);
                    *(__nv_bfloat162*)(ol + gb) = __nv_bfloat162(l0, l1);
                }
            }
        }
    }
}

// ============================================================================
// Split-K reduce (standalone; used only after the last layer): x += p0+p1+bias
// ============================================================================
__global__ __launch_bounds__(256) void reduce_add_kernel(
    const float* __restrict__ part, const float* __restrict__ bias,
    float* __restrict__ x, int N)
{
    int i = blockIdx.x * 256 + threadIdx.x;          // float4 index
    const float4* p0 = (const float4*)part;
    const float4* p1 = p0 + ((size_t)ROWS * N) / 4;
    float4 a = p0[i], b = p1[i];
    float4 xx = ((const float4*)x)[i];
    float4 bb = ((const float4*)bias)[i & (N / 4 - 1)];
    xx.x += a.x + b.x + bb.x;
    xx.y += a.y + b.y + bb.y;
    xx.z += a.z + b.z + bb.z;
    xx.w += a.w + b.w + bb.w;
    ((float4*)x)[i] = xx;
}

// ============================================================================
// Flash attention via mma.sync (bf16 split Q,K,V,P; fp32 softmax/accum).
// 2 CTAs/SM (64KB smem each).
// ============================================================================
#define ATT_SMEM 65536

__device__ __forceinline__ void attn_issue(
    int kt, int tid, uint32_t sb,
    const __nv_bfloat16* qh, const __nv_bfloat16* ql,
    size_t batch_row0, int kcol, int vcol)
{
    if (kt < 16) {
        uint32_t st = sb + (uint32_t)(kt & 1) * 32768;
        size_t rb = batch_row0 + (size_t)kt * 64;
        #pragma unroll
        for (int i = 0; i < 2; i++) {
            int idx = tid + i * 256;
            int r = idx >> 3, c = idx & 7;
            size_t rowoff = (rb + r) * QKV3;
            uint32_t so = SW128((uint32_t)(r * 128 + c * 16));
            cp16(st +         so, (const char*)(qh + rowoff + kcol) + c * 16);
            cp16(st + 8192  + so, (const char*)(ql + rowoff + kcol) + c * 16);
            cp16(st + 16384 + so, (const char*)(qh + rowoff + vcol) + c * 16);
            cp16(st + 24576 + so, (const char*)(ql + rowoff + vcol) + c * 16);
        }
    }
    CP_COMMIT();
}

__global__ __launch_bounds__(256, 2) void flash_mma_kernel(
    const __nv_bfloat16* __restrict__ qh, const __nv_bfloat16* __restrict__ ql,
    __nv_bfloat16* __restrict__ oh, __nv_bfloat16* __restrict__ ol)
{
    extern __shared__ char smem[];
    uint32_t sb = smem_u32(smem);
    int tid = threadIdx.x, wid = tid >> 5, lane = tid & 31;
    int qt = blockIdx.x;
    int b = blockIdx.y / HEADS, h = blockIdx.y % HEADS;
    int g = lane >> 2, tg = lane & 3;
    size_t batch_row0 = (size_t)b * NTOK;
    size_t qrow0 = batch_row0 + (size_t)qt * 128;
    int qcol = h * 64, kcol = DIM + h * 64, vcol = 2 * DIM + h * 64;

    #pragma unroll
    for (int i = 0; i < 4; i++) {
        int idx = tid + i * 256;
        int r = idx >> 3, c = idx & 7;
        size_t rowoff = (qrow0 + r) * QKV3 + qcol;
        uint32_t so = SW128((uint32_t)(r * 128 + c * 16));
        *(uint4*)(smem + so)         = *((const uint4*)(qh + rowoff) + c);
        *(uint4*)(smem + 16384 + so) = *((const uint4*)(ql + rowoff) + c);
    }
    __syncthreads();

    uint32_t ah[4][4], al[4][4];
    {
        uint32_t lrow = lane & 15, lh = lane >> 4;
        #pragma unroll
        for (int kf = 0; kf < 4; kf++) {
            uint32_t ro = (uint32_t)((wid * 16 + lrow) * 128) + kf * 32 + lh * 16;
            LDSM_X4(ah[kf][0], ah[kf][1], ah[kf][2], ah[kf][3], sb + SW128(ro));
            LDSM_X4(al[kf][0], al[kf][1], al[kf][2], al[kf][3], sb + 16384 + SW128(ro));
        }
    }
    __syncthreads();

    float m0v = -1e30f, m1v = -1e30f, l0 = 0.f, l1 = 0.f;
    float oacc[8][4] = {};
    const float scale = 0.125f;

    attn_issue(0, tid, sb, qh, ql, batch_row0, kcol, vcol);

    for (int kt = 0; kt < 16; kt++) {
        attn_issue(kt + 1, tid, sb, qh, ql, batch_row0, kcol, vcol);
        CP_WAIT1();
        __syncthreads();
        uint32_t kb = sb + (uint32_t)(kt & 1) * 32768;

        float sc[8][4] = {};
        #pragma unroll
        for (int kg = 0; kg < 4; kg++) {
            #pragma unroll
            for (int kf = 0; kf < 4; kf++) {
                uint32_t ro = (uint32_t)((kg * 16 + (lane & 15)) * 128) + kf * 32 + (lane >> 4) * 16;
                uint32_t t0, t1, t2, t3, u0, u1, u2, u3;
                LDSM_X4(t0, t1, t2, t3, kb + SW128(ro));
                LDSM_X4(u0, u1, u2, u3, kb + 8192 + SW128(ro));
                mma4(sc[2 * kg],     ah[kf], t0, t2);
                mma4(sc[2 * kg],     ah[kf], u0, u2);
                mma4(sc[2 * kg],     al[kf], t0, t2);
                mma4(sc[2 * kg + 1], ah[kf], t1, t3);
                mma4(sc[2 * kg + 1], ah[kf], u1, u3);
                mma4(sc[2 * kg + 1], al[kf], t1, t3);
            }
        }

        float mx0 = -1e30f, mx1 = -1e30f;
        #pragma unroll
        for (int nf = 0; nf < 8; nf++) {
            #pragma unroll
            for (int i = 0; i < 4; i++) sc[nf][i] *= scale;
            mx0 = fmaxf(mx0, fmaxf(sc[nf][0], sc[nf][1]));
            mx1 = fmaxf(mx1, fmaxf(sc[nf][2], sc[nf][3]));
        }
        mx0 = fmaxf(mx0, __shfl_xor_sync(0xffffffffu, mx0, 1));
        mx0 = fmaxf(mx0, __shfl_xor_sync(0xffffffffu, mx0, 2));
        mx1 = fmaxf(mx1, __shfl_xor_sync(0xffffffffu, mx1, 1));
        mx1 = fmaxf(mx1, __shfl_xor_sync(0xffffffffu, mx1, 2));
        float nm0 = fmaxf(m0v, mx0), nm1 = fmaxf(m1v, mx1);
        float c0 = __expf(m0v - nm0), c1 = __expf(m1v - nm1);
        l0 *= c0; l1 *= c1;
        #pragma unroll
        for (int nf = 0; nf < 8; nf++) {
            oacc[nf][0] *= c0; oacc[nf][1] *= c0;
            oacc[nf][2] *= c1; oacc[nf][3] *= c1;
        }
        m0v = nm0; m1v = nm1;
        float ps0 = 0.f, ps1 = 0.f;
        #pragma unroll
        for (int nf = 0; nf < 8; nf++) {
            sc[nf][0] = __expf(sc[nf][0] - nm0);
            sc[nf][1] = __expf(sc[nf][1] - nm0);
            sc[nf][2] = __expf(sc[nf][2] - nm1);
            sc[nf][3] = __expf(sc[nf][3] - nm1);
            ps0 += sc[nf][0] + sc[nf][1];
            ps1 += sc[nf][2] + sc[nf][3];
        }
        ps0 += __shfl_xor_sync(0xffffffffu, ps0, 1);
        ps0 += __shfl_xor_sync(0xffffffffu, ps0, 2);
        ps1 += __shfl_xor_sync(0xffffffffu, ps1, 1);
        ps1 += __shfl_xor_sync(0xffffffffu, ps1, 2);
        l0 += ps0; l1 += ps1;

        #pragma unroll
        for (int c = 0; c < 4; c++) {
            uint32_t pah[4], pal[4];
            pack_split(sc[2 * c][0],     sc[2 * c][1],     pah[0], pal[0]);
            pack_split(sc[2 * c][2],     sc[2 * c][3],     pah[1], pal[1]);
            pack_split(sc[2 * c + 1][0], sc[2 * c + 1][1], pah[2], pal[2]);
            pack_split(sc[2 * c + 1][2], sc[2 * c + 1][3], pah[3], pal[3]);
            #pragma unroll
            for (int dg = 0; dg < 4; dg++) {
                uint32_t ro = (uint32_t)((c * 16 + (lane & 15)) * 128) + dg * 32 + (lane >> 4) * 16;
                uint32_t t0, t1, t2, t3, u0, u1, u2, u3;
                LDSM_X4_T(t0, t1, t2, t3, kb + 16384 + SW128(ro));
                LDSM_X4_T(u0, u1, u2, u3, kb + 24576 + SW128(ro));
                mma4(oacc[2 * dg],     pah, t0, t1);
                mma4(oacc[2 * dg],     pah, u0, u1);
                mma4(oacc[2 * dg],     pal, t0, t1);
                mma4(oacc[2 * dg + 1], pah, t2, t3);
                mma4(oacc[2 * dg + 1], pah, u2, u3);
                mma4(oacc[2 * dg + 1], pal, t2, t3);
            }
        }
        __syncthreads();
    }

    float inv0 = 1.f / l0, inv1 = 1.f / l1;
    size_t r0 = qrow0 + wid * 16 + g;
    #pragma unroll
    for (int nf = 0; nf < 8; nf++) {
        int col = h * 64 + nf * 8 + tg * 2;
        float v0 = oacc[nf][0] * inv0, v1 = oacc[nf][1] * inv0;
        float v2 = oacc[nf][2] * inv1, v3 = oacc[nf][3] * inv1;
        __nv_bfloat16 h0, lo0, h1, lo1;
        split2(v0, h0, lo0); split2(v1, h1, lo1);
        *(__nv_bfloat162*)(oh + r0 * DIM + col) = __nv_bfloat162(h0, h1);
        *(__nv_bfloat162*)(ol + r0 * DIM + col) = __nv_bfloat162(lo0, lo1);
        split2(v2, h0, lo0); split2(v3, h1, lo1);
        *(__nv_bfloat162*)(oh + (r0 + 8) * DIM + col) = __nv_bfloat162(h0, h1);
        *(__nv_bfloat162*)(ol + (r0 + 8) * DIM + col) = __nv_bfloat162(lo0, lo1);
    }
}

// ============================================================================
// Final transpose: x[b,n,d] -> out[b,d,n]
// ============================================================================
__global__ void transpose_out_kernel(const float* __restrict__ x,
                                     float* __restrict__ out)
{
    __shared__ float t[32][33];
    int b = blockIdx.z;
    int n0 = blockIdx.x * 32, d0 = blockIdx.y * 32;
    int tx = threadIdx.x, ty = threadIdx.y;
    for (int i = ty; i < 32; i += 8)
        t[i][tx] = x[((size_t)b * NTOK + n0 + i) * DIM + d0 + tx];
    __syncthreads();
    for (int i = ty; i < 32; i += 8)
        out[((size_t)b * DIM + d0 + i) * NTOK + n0 + tx] = t[tx][i];
}

// ============================================================================
// Host orchestration
// ============================================================================
extern "C" void kernel_launch(void* const* d_in, const int* in_sizes, int n_in,
                              void* d_out, int out_size)
{
    const float* c_f    = (const float*)d_in[0];
    const float* conv_w = (const float*)d_in[1];
    const float* conv_b = (const float*)d_in[2];
    const float* ln1_w  = (const float*)d_in[3];
    const float* ln1_b  = (const float*)d_in[4];
    const float* qkv_w  = (const float*)d_in[5];
    const float* out_w  = (const float*)d_in[6];
    const float* out_b  = (const float*)d_in[7];
    const float* ln2_w  = (const float*)d_in[8];
    const float* ln2_b  = (const float*)d_in[9];
    const float* mlp_w1 = (const float*)d_in[10];
    const float* mlp_b1 = (const float*)d_in[11];
    const float* mlp_w2 = (const float*)d_in[12];
    const float* mlp_b2 = (const float*)d_in[13];
    float* out = (float*)d_out;

    cudaFuncSetAttribute(mma_gemm_kernel,
                         cudaFuncAttributeMaxDynamicSharedMemorySize, MMA_SMEM);
    cudaFuncSetAttribute(flash_mma_kernel,
                         cudaFuncAttributeMaxDynamicSharedMemorySize, ATT_SMEM);

    float *p_x, *p_part;
    __nv_bfloat16 *p_yh, *p_yl, *p_oh, *p_ol, *p_hh, *p_hl, *p_qh, *p_ql;
    __nv_bfloat16 *p_qwh, *p_qwl, *p_owh, *p_owl, *p_m1h, *p_m1l, *p_m2h, *p_m2l;
    cudaGetSymbolAddress((void**)&p_x,    g_x);
    cudaGetSymbolAddress((void**)&p_part, g_part);
    cudaGetSymbolAddress((void**)&p_yh,  g_yh);
    cudaGetSymbolAddress((void**)&p_yl,  g_yl);
    cudaGetSymbolAddress((void**)&p_oh,  g_oh);
    cudaGetSymbolAddress((void**)&p_ol,  g_ol);
    cudaGetSymbolAddress((void**)&p_hh,  g_hh);
    cudaGetSymbolAddress((void**)&p_hl,  g_hl);
    cudaGetSymbolAddress((void**)&p_qh,  g_qh);
    cudaGetSymbolAddress((void**)&p_ql,  g_ql);
    cudaGetSymbolAddress((void**)&p_qwh, g_qkvw_h);
    cudaGetSymbolAddress((void**)&p_qwl, g_qkvw_l);
    cudaGetSymbolAddress((void**)&p_owh, g_outw_h);
    cudaGetSymbolAddress((void**)&p_owl, g_outw_l);
    cudaGetSymbolAddress((void**)&p_m1h, g_m1w_h);
    cudaGetSymbolAddress((void**)&p_m1l, g_m1w_l);
    cudaGetSymbolAddress((void**)&p_m2h, g_m2w_h);
    cudaGetSymbolAddress((void**)&p_m2l, g_m2w_l);

    wsplit_all_kernel<<<DEPTH * WL_BLOCKS, dim3(32, 8)>>>(
        qkv_w, out_w, mlp_w1, mlp_w2,
        p_qwh, p_qwl, p_owh, p_owl, p_m1h, p_m1l, p_m2h, p_m2l);

    embed_kernel<<<dim3(NTOK / 64, DIM / 64, BATCH), 256>>>(c_f, conv_w, conv_b, p_x);

    // layer 0 LN1 (no pending split-K reduce)
    ln_split_kernel<<<ROWS / 8, 256>>>(nullptr, nullptr, p_x,
                                       ln1_w, ln1_b, p_yh, p_yl);

    for (int l = 0; l < DEPTH; l++) {
        mma_gemm_kernel<<<dim3(QKV3 / 128, ROWS / 128, 1), 256, MMA_SMEM>>>(
            DIM, QKV3, p_yh, p_yl,
            p_qwh + (size_t)l * QKV3 * DIM, p_qwl + (size_t)l * QKV3 * DIM,
            nullptr, nullptr, nullptr, p_qh, p_ql, 0);
        flash_mma_kernel<<<dim3(NTOK / 128, BATCH * HEADS), 256, ATT_SMEM>>>(
            p_qh, p_ql, p_oh, p_ol);
        // attn out-proj: split-K=2 -> partials; reduce fused into LN2
        mma_gemm_kernel<<<dim3(DIM / 128, ROWS / 128, 2), 256, MMA_SMEM>>>(
            DIM, DIM, p_oh, p_ol,
            p_owh + (size_t)l * DIM * DIM, p_owl + (size_t)l * DIM * DIM,
            nullptr, nullptr, p_part, nullptr, nullptr, 0);
        ln_split_kernel<<<ROWS / 8, 256>>>(p_part, out_b + l * DIM, p_x,
                                           ln2_w + l * DIM, ln2_b + l * DIM,
                                           p_yh, p_yl);
        mma_gemm_kernel<<<dim3(MLPD / 128, ROWS / 128, 1), 256, MMA_SMEM>>>(
            DIM, MLPD, p_yh, p_yl,
            p_m1h + (size_t)l * MLPD * DIM, p_m1l + (size_t)l * MLPD * DIM,
            mlp_b1 + l * MLPD, nullptr, nullptr, p_hh, p_hl, 1);
        // mlp2: split-K=2 -> partials; reduce fused into next layer's LN1
        mma_gemm_kernel<<<dim3(DIM / 128, ROWS / 128, 2), 256, MMA_SMEM>>>(
            MLPD, DIM, p_hh, p_hl,
            p_m2h + (size_t)l * DIM * MLPD, p_m2l + (size_t)l * DIM * MLPD,
            nullptr, nullptr, p_part, nullptr, nullptr, 0);
        if (l < DEPTH - 1) {
            ln_split_kernel<<<ROWS / 8, 256>>>(p_part, mlp_b2 + l * DIM, p_x,
                                               ln1_w + (l + 1) * DIM,
                                               ln1_b + (l + 1) * DIM,
                                               p_yh, p_yl);
        } else {
            reduce_add_kernel<<<ROWS * DIM / 1024, 256>>>(
                p_part, mlp_b2 + l * DIM, p_x, DIM);
        }
    }

    transpose_out_kernel<<<dim3(NTOK / 32, DIM / 32, BATCH), dim3(32, 8)>>>(p_x, out);
}

// round 13
// speedup vs baseline: 5.2529x; 1.0060x over previous
#include <cuda_runtime.h>
#include <cuda_bf16.h>
#include <math.h>
#include <stdint.h>

#define DIM 768
#define NTOK 1024
#define BATCH 4
#define ROWS (BATCH * NTOK)        // 4096
#define F_DIM 256
#define HEADS 12
#define DHEAD 64
#define QKV3 (3 * DIM)             // 2304
#define MLPD 3072
#define DEPTH 8
#define LN_EPS 1e-5f

// ============================================================================
// Helpers
// ============================================================================
__device__ __forceinline__ uint32_t smem_u32(const void* p) {
    uint32_t a;
    asm("{ .reg .u64 t; cvta.to.shared.u64 t, %1; cvt.u32.u64 %0, t; }"
        : "=r"(a) : "l"(p));
    return a;
}
#define SW128(o) ((o) ^ (((o) >> 3) & 0x70))

__device__ __forceinline__ void cp16(uint32_t s, const void* g) {
    asm volatile("cp.async.cg.shared.global [%0], [%1], 16;" :: "r"(s), "l"(g));
}
#define CP_COMMIT() asm volatile("cp.async.commit_group;" ::: "memory")
#define CP_WAIT1()  asm volatile("cp.async.wait_group 1;" ::: "memory")

#define LDSM_X4(r0, r1, r2, r3, addr) \
    asm volatile("ldmatrix.sync.aligned.m8n8.x4.shared.b16 {%0,%1,%2,%3}, [%4];" \
        : "=r"(r0), "=r"(r1), "=r"(r2), "=r"(r3) : "r"(addr))
#define LDSM_X4_T(r0, r1, r2, r3, addr) \
    asm volatile("ldmatrix.sync.aligned.m8n8.x4.trans.shared.b16 {%0,%1,%2,%3}, [%4];" \
        : "=r"(r0), "=r"(r1), "=r"(r2), "=r"(r3) : "r"(addr))

__device__ __forceinline__ void mma_bf16(float* c, const uint32_t* a, const uint32_t* b) {
    asm volatile(
        "mma.sync.aligned.m16n8k16.row.col.f32.bf16.bf16.f32 "
        "{%0,%1,%2,%3}, {%4,%5,%6,%7}, {%8,%9}, {%0,%1,%2,%3};"
        : "+f"(c[0]), "+f"(c[1]), "+f"(c[2]), "+f"(c[3])
        : "r"(a[0]), "r"(a[1]), "r"(a[2]), "r"(a[3]), "r"(b[0]), "r"(b[1]));
}
__device__ __forceinline__ void mma4(float* c, const uint32_t* a, uint32_t b0, uint32_t b1) {
    uint32_t b[2] = { b0, b1 };
    mma_bf16(c, a, b);
}

__device__ __forceinline__ void split2(float v, __nv_bfloat16& h, __nv_bfloat16& l) {
    h = __float2bfloat16(v);
    l = __float2bfloat16(v - __bfloat162float(h));
}
__device__ __forceinline__ void pack_split(float a, float b, uint32_t& hi, uint32_t& lo) {
    __nv_bfloat16 ha = __float2bfloat16(a);
    __nv_bfloat16 hb = __float2bfloat16(b);
    __nv_bfloat162 H(ha, hb);
    __nv_bfloat162 L(__float2bfloat16(a - __bfloat162float(ha)),
                     __float2bfloat16(b - __bfloat162float(hb)));
    hi = *(uint32_t*)&H;
    lo = *(uint32_t*)&L;
}
__device__ __forceinline__ float gelu_f(float v) {
    return 0.5f * v * (1.0f + erff(v * 0.7071067811865475f));
}

// ============================================================================
// Scratch (device globals)
// ============================================================================
__device__ __align__(16) float g_x  [ROWS * DIM];
__device__ __align__(16) float g_part[2 * ROWS * DIM];
__device__ __align__(16) __nv_bfloat16 g_yh[ROWS * DIM],  g_yl[ROWS * DIM];
__device__ __align__(16) __nv_bfloat16 g_oh[ROWS * DIM],  g_ol[ROWS * DIM];
__device__ __align__(16) __nv_bfloat16 g_hh[ROWS * MLPD], g_hl[ROWS * MLPD];
__device__ __align__(16) __nv_bfloat16 g_qh[ROWS * QKV3], g_ql[ROWS * QKV3];
// transposed + split weights: [L][N][K]
__device__ __align__(16) __nv_bfloat16 g_qkvw_h[DEPTH * QKV3 * DIM], g_qkvw_l[DEPTH * QKV3 * DIM];
__device__ __align__(16) __nv_bfloat16 g_outw_h[DEPTH * DIM * DIM],  g_outw_l[DEPTH * DIM * DIM];
__device__ __align__(16) __nv_bfloat16 g_m1w_h [DEPTH * MLPD * DIM], g_m1w_l [DEPTH * MLPD * DIM];
__device__ __align__(16) __nv_bfloat16 g_m2w_h [DEPTH * DIM * MLPD], g_m2w_l [DEPTH * DIM * MLPD];

// ============================================================================
// Combined weight transpose + bf16 split (one launch).
// ============================================================================
#define WL_BLOCKS 6912
__global__ void wsplit_all_kernel(
    const float* __restrict__ qkv_w, const float* __restrict__ out_w,
    const float* __restrict__ m1w,   const float* __restrict__ m2w,
    __nv_bfloat16* qh, __nv_bfloat16* ql,
    __nv_bfloat16* owh, __nv_bfloat16* owl,
    __nv_bfloat16* m1h, __nv_bfloat16* m1l,
    __nv_bfloat16* m2h, __nv_bfloat16* m2l)
{
    int z = blockIdx.x;
    int l = z / WL_BLOCKS, r = z % WL_BLOCKS;
    const float* w; __nv_bfloat16 *hi, *lo; int K, N, nx, ny;
    if (r < 1728)      { w = qkv_w; hi = qh;  lo = ql;  K = DIM;  N = QKV3; nx = r % 72; ny = r / 72; }
    else if (r < 2304) { int rr = r - 1728; w = out_w; hi = owh; lo = owl; K = DIM;  N = DIM;  nx = rr % 24; ny = rr / 24; }
    else if (r < 4608) { int rr = r - 2304; w = m1w;   hi = m1h; lo = m1l; K = DIM;  N = MLPD; nx = rr % 96; ny = rr / 96; }
    else               { int rr = r - 4608; w = m2w;   hi = m2h; lo = m2l; K = MLPD; N = DIM;  nx = rr % 24; ny = rr / 24; }
    __shared__ float t[32][33];
    int n0 = nx * 32, k0 = ny * 32;
    int tx = threadIdx.x, ty = threadIdx.y;
    const float* wl = w + (size_t)l * K * N;
    for (int i = ty; i < 32; i += 8)
        t[i][tx] = wl[(size_t)(k0 + i) * N + n0 + tx];
    __syncthreads();
    size_t ob = (size_t)l * K * N;
    for (int i = ty; i < 32; i += 8) {
        float v = t[tx][i];
        __nv_bfloat16 h, lw;
        split2(v, h, lw);
        size_t o = ob + (size_t)(n0 + i) * K + k0 + tx;
        hi[o] = h; lo[o] = lw;
    }
}

// ============================================================================
// Embed GEMM with fused sine pos-embed
// ============================================================================
__device__ __forceinline__ float posval(int n, int d) {
    int r = n >> 5, c = n & 31;
    int id = (d < 384) ? d : d - 384;
    float coord = (d < 384) ? (float)(r + 1) : (float)(c + 1);
    float ang = coord * (6.283185307179586f / (32.0f + 1e-6f));
    float ex = (float)(2 * (id / 2)) * (1.0f / 384.0f);
    float p = ang / __powf(10000.0f, ex);
    return (id & 1) ? cosf(p) : sinf(p);
}

__global__ __launch_bounds__(256) void embed_kernel(
    const float* __restrict__ cf, const float* __restrict__ w,
    const float* __restrict__ bias, float* __restrict__ x)
{
    __shared__ float As[16][64];
    __shared__ float Bs[16][68];
    int b  = blockIdx.z;
    int n0 = blockIdx.x * 64, d0 = blockIdx.y * 64;
    int tid = threadIdx.x;
    int ty = tid / 16, tx = tid % 16;
    float acc[4][4] = {};
    const float* cfb = cf + (size_t)b * F_DIM * NTOK;
    for (int k0 = 0; k0 < F_DIM; k0 += 16) {
        #pragma unroll
        for (int it = 0; it < 4; it++) {
            int idx = tid + it * 256;
            As[idx >> 6][idx & 63] = cfb[(size_t)(k0 + (idx >> 6)) * NTOK + n0 + (idx & 63)];
        }
        #pragma unroll
        for (int it = 0; it < 4; it++) {
            int idx = tid + it * 256;
            Bs[idx & 15][idx >> 4] = w[(size_t)(d0 + (idx >> 4)) * F_DIM + k0 + (idx & 15)];
        }
        __syncthreads();
        #pragma unroll
        for (int kk = 0; kk < 16; kk++) {
            float a[4], bb[4];
            #pragma unroll
            for (int i = 0; i < 4; i++) a[i]  = As[kk][ty * 4 + i];
            #pragma unroll
            for (int j = 0; j < 4; j++) bb[j] = Bs[kk][tx * 4 + j];
            #pragma unroll
            for (int i = 0; i < 4; i++)
                #pragma unroll
                for (int j = 0; j < 4; j++)
                    acc[i][j] += a[i] * bb[j];
        }
        __syncthreads();
    }
    #pragma unroll
    for (int i = 0; i < 4; i++) {
        int n = n0 + ty * 4 + i;
        #pragma unroll
        for (int j = 0; j < 4; j++) {
            int d = d0 + tx * 4 + j;
            x[((size_t)b * NTOK + n) * DIM + d] = acc[i][j] + bias[d] + posval(n, d);
        }
    }
}

// ============================================================================
// LayerNorm -> split bf16 hi/lo.  Warp-per-row.
// If part != nullptr, first computes x += part0 + part1 + rbias (split-K
// reduce fused in) and writes updated x.
// ============================================================================
__global__ __launch_bounds__(256) void ln_split_kernel(
    const float* __restrict__ part, const float* __restrict__ rbias,
    float* __restrict__ x, const float* __restrict__ w,
    const float* __restrict__ bias,
    __nv_bfloat16* __restrict__ yh, __nv_bfloat16* __restrict__ yl)
{
    int warp = threadIdx.x >> 5, lane = threadIdx.x & 31;
    int row = blockIdx.x * 8 + warp;
    float4* xr = (float4*)(x + (size_t)row * DIM);
    float4 v[6];
    float s = 0.f, ss = 0.f;
    if (part) {
        const float4* p0 = (const float4*)(part + (size_t)row * DIM);
        const float4* p1 = (const float4*)(part + (size_t)(ROWS + row) * DIM);
        const float4* rb = (const float4*)rbias;
        #pragma unroll
        for (int i = 0; i < 6; i++) {
            int idx4 = lane + i * 32;
            float4 a = p0[idx4], b = p1[idx4], bb = rb[idx4];
            v[i] = xr[idx4];
            v[i].x += a.x + b.x + bb.x;
            v[i].y += a.y + b.y + bb.y;
            v[i].z += a.z + b.z + bb.z;
            v[i].w += a.w + b.w + bb.w;
            xr[idx4] = v[i];
            s  += v[i].x + v[i].y + v[i].z + v[i].w;
            ss += v[i].x * v[i].x + v[i].y * v[i].y + v[i].z * v[i].z + v[i].w * v[i].w;
        }
    } else {
        #pragma unroll
        for (int i = 0; i < 6; i++) {
            v[i] = xr[lane + i * 32];
            s  += v[i].x + v[i].y + v[i].z + v[i].w;
            ss += v[i].x * v[i].x + v[i].y * v[i].y + v[i].z * v[i].z + v[i].w * v[i].w;
        }
    }
    #pragma unroll
    for (int off = 16; off; off >>= 1) {
        s  += __shfl_xor_sync(0xffffffffu, s,  off);
        ss += __shfl_xor_sync(0xffffffffu, ss, off);
    }
    float mu  = s * (1.0f / DIM);
    float var = ss * (1.0f / DIM) - mu * mu;
    float inv = rsqrtf(var + LN_EPS);
    const float4* wv = (const float4*)w;
    const float4* bv = (const float4*)bias;
    #pragma unroll
    for (int i = 0; i < 6; i++) {
        int idx4 = lane + i * 32;
        float4 ww = wv[idx4], bb = bv[idx4];
        float y0 = (v[i].x - mu) * inv * ww.x + bb.x;
        float y1 = (v[i].y - mu) * inv * ww.y + bb.y;
        float y2 = (v[i].z - mu) * inv * ww.z + bb.z;
        float y3 = (v[i].w - mu) * inv * ww.w + bb.w;
        uint32_t h01, l01, h23, l23;
        pack_split(y0, y1, h01, l01);
        pack_split(y2, y3, h23, l23);
        uint32_t* ph = (uint32_t*)(yh + (size_t)row * DIM) + idx4 * 2;
        uint32_t* pl = (uint32_t*)(yl + (size_t)row * DIM) + idx4 * 2;
        ph[0] = h01; ph[1] = h23;
        pl[0] = l01; pl[1] = l23;
    }
}

// ============================================================================
// Tensor-core GEMM (bf16x3 split, fp32 accum), 3-stage cp.async pipeline,
// 2 CTAs/SM pinned.  Split-MMA passes separated to break acc RAW chains.
// ============================================================================
#define STG_BYTES 32768
#define MMA_SMEM  (3 * STG_BYTES)   // 98304

__global__ __launch_bounds__(256, 2) void mma_gemm_kernel(
    int K, int N,
    const __nv_bfloat16* __restrict__ Ah, const __nv_bfloat16* __restrict__ Al,
    const __nv_bfloat16* __restrict__ Bh, const __nv_bfloat16* __restrict__ Bl,
    const float* __restrict__ bias, const float* __restrict__ resid,
    float* __restrict__ outf,
    __nv_bfloat16* __restrict__ oh, __nv_bfloat16* __restrict__ ol,
    int gelu)
{
    extern __shared__ char smem[];
    uint32_t sbase = smem_u32(smem);
    int tid = threadIdx.x, wid = tid >> 5, lane = tid & 31;
    int n0 = blockIdx.x * 128, m0 = blockIdx.y * 128;

    // split-K range
    int nch_tot = K / 32;
    int per = nch_tot / gridDim.z;
    int ch_begin = blockIdx.z * per;
    int chend = ch_begin + per;

    // hoisted cp.async addressing
    int r_cp = tid >> 2, c_cp = tid & 3;
    uint32_t soff0 = SW128((uint32_t)(r_cp * 64 + c_cp * 16));
    uint32_t soff1 = SW128((uint32_t)((r_cp + 64) * 64 + c_cp * 16));
    size_t goff0 = ((size_t)r_cp * K + c_cp * 8) * 2;
    size_t goff1 = ((size_t)(r_cp + 64) * K + c_cp * 8) * 2;
    const char* pAh = (const char*)(Ah + (size_t)m0 * K);
    const char* pAl = (const char*)(Al + (size_t)m0 * K);
    const char* pBh = (const char*)(Bh + (size_t)n0 * K);
    const char* pBl = (const char*)(Bl + (size_t)n0 * K);

#define ISSUE(CH) do { \
    if ((CH) < chend) { \
        uint32_t sb0 = sbase + (uint32_t)((CH) % 3) * STG_BYTES; \
        size_t kb = (size_t)(CH) * 64; \
        cp16(sb0 +          soff0, pAh + kb + goff0); \
        cp16(sb0 +          soff1, pAh + kb + goff1); \
        cp16(sb0 + 8192  +  soff0, pAl + kb + goff0); \
        cp16(sb0 + 8192  +  soff1, pAl + kb + goff1); \
        cp16(sb0 + 16384 +  soff0, pBh + kb + goff0); \
        cp16(sb0 + 16384 +  soff1, pBh + kb + goff1); \
        cp16(sb0 + 24576 +  soff0, pBl + kb + goff0); \
        cp16(sb0 + 24576 +  soff1, pBl + kb + goff1); \
    } \
    CP_COMMIT(); } while (0)

    int wm = wid >> 2, wn = wid & 3;
    uint32_t lrow = lane & 15, lhalf = lane >> 4;

    // hoisted ldmatrix swizzled offsets (lo tile = hi addr + 8192)
    uint32_t aoff[2][4], boff[2][2];
    #pragma unroll
    for (int ks = 0; ks < 2; ks++) {
        uint32_t koff = (uint32_t)(ks * 2 + lhalf) * 16;
        #pragma unroll
        for (int mf = 0; mf < 4; mf++)
            aoff[ks][mf] = SW128((uint32_t)((wm * 64 + mf * 16 + lrow) * 64) + koff);
        #pragma unroll
        for (int nf2 = 0; nf2 < 2; nf2++)
            boff[ks][nf2] = SW128((uint32_t)((wn * 32 + nf2 * 16 + lrow) * 64) + koff);
    }

    float acc[4][4][4] = {};

    ISSUE(ch_begin);
    ISSUE(ch_begin + 1);

    for (int ch = ch_begin; ch < chend; ch++) {
        CP_WAIT1();
        __syncthreads();
        ISSUE(ch + 2);
        uint32_t st = sbase + (uint32_t)(ch % 3) * STG_BYTES;
        #pragma unroll
        for (int ks = 0; ks < 2; ks++) {
            uint32_t ah[4][4], al[4][4], bh[4][2], bl[4][2];
            #pragma unroll
            for (int mf = 0; mf < 4; mf++) {
                uint32_t a0 = st + aoff[ks][mf];
                LDSM_X4(ah[mf][0], ah[mf][1], ah[mf][2], ah[mf][3], a0);
                LDSM_X4(al[mf][0], al[mf][1], al[mf][2], al[mf][3], a0 + 8192);
            }
            #pragma unroll
            for (int nf2 = 0; nf2 < 2; nf2++) {
                uint32_t b0 = st + 16384 + boff[ks][nf2];
                uint32_t t0, t1, t2, t3;
                LDSM_X4(t0, t1, t2, t3, b0);
                bh[nf2 * 2][0] = t0; bh[nf2 * 2 + 1][0] = t1;
                bh[nf2 * 2][1] = t2; bh[nf2 * 2 + 1][1] = t3;
                LDSM_X4(t0, t1, t2, t3, b0 + 8192);
                bl[nf2 * 2][0] = t0; bl[nf2 * 2 + 1][0] = t1;
                bl[nf2 * 2][1] = t2; bl[nf2 * 2 + 1][1] = t3;
            }
            // Pass 1: Ah*Bh over all 16 tiles (acc reuse distance = 16 MMAs)
            #pragma unroll
            for (int mf = 0; mf < 4; mf++)
                #pragma unroll
                for (int nf = 0; nf < 4; nf++)
                    mma_bf16(acc[mf][nf], ah[mf], bh[nf]);
            // Pass 2: Ah*Bl
            #pragma unroll
            for (int mf = 0; mf < 4; mf++)
                #pragma unroll
                for (int nf = 0; nf < 4; nf++)
                    mma_bf16(acc[mf][nf], ah[mf], bl[nf]);
            // Pass 3: Al*Bh
            #pragma unroll
            for (int mf = 0; mf < 4; mf++)
                #pragma unroll
                for (int nf = 0; nf < 4; nf++)
                    mma_bf16(acc[mf][nf], al[mf], bh[nf]);
        }
    }
#undef ISSUE

    // Epilogue
    float* myout = outf ? (outf + (size_t)blockIdx.z * ((size_t)ROWS * N)) : (float*)0;
    int g = lane >> 2, tg = lane & 3;
    #pragma unroll
    for (int mf = 0; mf < 4; mf++) {
        #pragma unroll
        for (int nf = 0; nf < 4; nf++) {
            int col = n0 + wn * 32 + nf * 8 + tg * 2;
            float bv0 = bias ? __ldg(bias + col)     : 0.f;
            float bv1 = bias ? __ldg(bias + col + 1) : 0.f;
            #pragma unroll
            for (int half = 0; half < 2; half++) {
                int row = m0 + wm * 64 + mf * 16 + g + half * 8;
                float v0 = acc[mf][nf][half * 2 + 0] + bv0;
                float v1 = acc[mf][nf][half * 2 + 1] + bv1;
                if (gelu) { v0 = gelu_f(v0); v1 = gelu_f(v1); }
                size_t gb = (size_t)row * N + col;
                if (resid) {
                    float2 rr = *(const float2*)(resid + gb);
                    v0 += rr.x; v1 += rr.y;
                }
                if (myout) {
                    *(float2*)(myout + gb) = make_float2(v0, v1);
                } else {
                    __nv_bfloat16 h0, l0, h1, l1;
                    split2(v0, h0, l0); split2(v1, h1, l1);
                    *(__nv_bfloat162*)(oh + gb) = __nv_bfloat162(h0, h1);
                    *(__nv_bfloat162*)(ol + gb) = __nv_bfloat162(l0, l1);
                }
            }
        }
    }
}

// ============================================================================
// Split-K reduce (standalone; used only after the last layer): x += p0+p1+bias
// ============================================================================
__global__ __launch_bounds__(256) void reduce_add_kernel(
    const float* __restrict__ part, const float* __restrict__ bias,
    float* __restrict__ x, int N)
{
    int i = blockIdx.x * 256 + threadIdx.x;          // float4 index
    const float4* p0 = (const float4*)part;
    const float4* p1 = p0 + ((size_t)ROWS * N) / 4;
    float4 a = p0[i], b = p1[i];
    float4 xx = ((const float4*)x)[i];
    float4 bb = ((const float4*)bias)[i & (N / 4 - 1)];
    xx.x += a.x + b.x + bb.x;
    xx.y += a.y + b.y + bb.y;
    xx.z += a.z + b.z + bb.z;
    xx.w += a.w + b.w + bb.w;
    ((float4*)x)[i] = xx;
}

// ============================================================================
// Flash attention via mma.sync (bf16 split Q,K,V,P; fp32 softmax/accum).
// 2 CTAs/SM.  Q parked in dedicated smem (64KB..96KB); fragments re-loaded
// per K-tile to keep live registers under the 128-reg cap (no spills).
// ============================================================================
#define ATT_SMEM 98304

__device__ __forceinline__ void attn_issue(
    int kt, int tid, uint32_t sb,
    const __nv_bfloat16* qh, const __nv_bfloat16* ql,
    size_t batch_row0, int kcol, int vcol)
{
    if (kt < 16) {
        uint32_t st = sb + (uint32_t)(kt & 1) * 32768;
        size_t rb = batch_row0 + (size_t)kt * 64;
        #pragma unroll
        for (int i = 0; i < 2; i++) {
            int idx = tid + i * 256;
            int r = idx >> 3, c = idx & 7;
            size_t rowoff = (rb + r) * QKV3;
            uint32_t so = SW128((uint32_t)(r * 128 + c * 16));
            cp16(st +         so, (const char*)(qh + rowoff + kcol) + c * 16);
            cp16(st + 8192  + so, (const char*)(ql + rowoff + kcol) + c * 16);
            cp16(st + 16384 + so, (const char*)(qh + rowoff + vcol) + c * 16);
            cp16(st + 24576 + so, (const char*)(ql + rowoff + vcol) + c * 16);
        }
    }
    CP_COMMIT();
}

__global__ __launch_bounds__(256, 2) void flash_mma_kernel(
    const __nv_bfloat16* __restrict__ qh, const __nv_bfloat16* __restrict__ ql,
    __nv_bfloat16* __restrict__ oh, __nv_bfloat16* __restrict__ ol)
{
    extern __shared__ char smem[];
    uint32_t sb = smem_u32(smem);
    int tid = threadIdx.x, wid = tid >> 5, lane = tid & 31;
    int qt = blockIdx.x;
    int b = blockIdx.y / HEADS, h = blockIdx.y % HEADS;
    int g = lane >> 2, tg = lane & 3;
    size_t batch_row0 = (size_t)b * NTOK;
    size_t qrow0 = batch_row0 + (size_t)qt * 128;
    int qcol = h * 64, kcol = DIM + h * 64, vcol = 2 * DIM + h * 64;

    // Stage Q into dedicated region [64KB..96KB): hi at +65536, lo at +81920
    #pragma unroll
    for (int i = 0; i < 4; i++) {
        int idx = tid + i * 256;
        int r = idx >> 3, c = idx & 7;
        size_t rowoff = (qrow0 + r) * QKV3 + qcol;
        uint32_t so = SW128((uint32_t)(r * 128 + c * 16));
        *(uint4*)(smem + 65536 + so) = *((const uint4*)(qh + rowoff) + c);
        *(uint4*)(smem + 81920 + so) = *((const uint4*)(ql + rowoff) + c);
    }

    // hoisted Q fragment offsets
    uint32_t qoff[4];
    {
        uint32_t lrow = lane & 15, lh = lane >> 4;
        #pragma unroll
        for (int kf = 0; kf < 4; kf++)
            qoff[kf] = SW128((uint32_t)((wid * 16 + lrow) * 128) + kf * 32 + lh * 16);
    }
    __syncthreads();

    float m0v = -1e30f, m1v = -1e30f, l0 = 0.f, l1 = 0.f;
    float oacc[8][4] = {};
    const float scale = 0.125f;

    attn_issue(0, tid, sb, qh, ql, batch_row0, kcol, vcol);

    for (int kt = 0; kt < 16; kt++) {
        attn_issue(kt + 1, tid, sb, qh, ql, batch_row0, kcol, vcol);
        CP_WAIT1();
        __syncthreads();
        uint32_t kb = sb + (uint32_t)(kt & 1) * 32768;

        // S = Q @ K^T (3-split); Q frags re-loaded from smem per tile
        float sc[8][4] = {};
        #pragma unroll
        for (int kf = 0; kf < 4; kf++) {
            uint32_t ah[4], al[4];
            LDSM_X4(ah[0], ah[1], ah[2], ah[3], sb + 65536 + qoff[kf]);
            LDSM_X4(al[0], al[1], al[2], al[3], sb + 81920 + qoff[kf]);
            #pragma unroll
            for (int kg = 0; kg < 4; kg++) {
                uint32_t ro = (uint32_t)((kg * 16 + (lane & 15)) * 128) + kf * 32 + (lane >> 4) * 16;
                uint32_t t0, t1, t2, t3, u0, u1, u2, u3;
                LDSM_X4(t0, t1, t2, t3, kb + SW128(ro));
                LDSM_X4(u0, u1, u2, u3, kb + 8192 + SW128(ro));
                mma4(sc[2 * kg],     ah, t0, t2);
                mma4(sc[2 * kg],     ah, u0, u2);
                mma4(sc[2 * kg],     al, t0, t2);
                mma4(sc[2 * kg + 1], ah, t1, t3);
                mma4(sc[2 * kg + 1], ah, u1, u3);
                mma4(sc[2 * kg + 1], al, t1, t3);
            }
        }

        // Online softmax
        float mx0 = -1e30f, mx1 = -1e30f;
        #pragma unroll
        for (int nf = 0; nf < 8; nf++) {
            #pragma unroll
            for (int i = 0; i < 4; i++) sc[nf][i] *= scale;
            mx0 = fmaxf(mx0, fmaxf(sc[nf][0], sc[nf][1]));
            mx1 = fmaxf(mx1, fmaxf(sc[nf][2], sc[nf][3]));
        }
        mx0 = fmaxf(mx0, __shfl_xor_sync(0xffffffffu, mx0, 1));
        mx0 = fmaxf(mx0, __shfl_xor_sync(0xffffffffu, mx0, 2));
        mx1 = fmaxf(mx1, __shfl_xor_sync(0xffffffffu, mx1, 1));
        mx1 = fmaxf(mx1, __shfl_xor_sync(0xffffffffu, mx1, 2));
        float nm0 = fmaxf(m0v, mx0), nm1 = fmaxf(m1v, mx1);
        float c0 = __expf(m0v - nm0), c1 = __expf(m1v - nm1);
        l0 *= c0; l1 *= c1;
        #pragma unroll
        for (int nf = 0; nf < 8; nf++) {
            oacc[nf][0] *= c0; oacc[nf][1] *= c0;
            oacc[nf][2] *= c1; oacc[nf][3] *= c1;
        }
        m0v = nm0; m1v = nm1;
        float ps0 = 0.f, ps1 = 0.f;
        #pragma unroll
        for (int nf = 0; nf < 8; nf++) {
            sc[nf][0] = __expf(sc[nf][0] - nm0);
            sc[nf][1] = __expf(sc[nf][1] - nm0);
            sc[nf][2] = __expf(sc[nf][2] - nm1);
            sc[nf][3] = __expf(sc[nf][3] - nm1);
            ps0 += sc[nf][0] + sc[nf][1];
            ps1 += sc[nf][2] + sc[nf][3];
        }
        ps0 += __shfl_xor_sync(0xffffffffu, ps0, 1);
        ps0 += __shfl_xor_sync(0xffffffffu, ps0, 2);
        ps1 += __shfl_xor_sync(0xffffffffu, ps1, 1);
        ps1 += __shfl_xor_sync(0xffffffffu, ps1, 2);
        l0 += ps0; l1 += ps1;

        // O += P @ V
        #pragma unroll
        for (int c = 0; c < 4; c++) {
            uint32_t pah[4], pal[4];
            pack_split(sc[2 * c][0],     sc[2 * c][1],     pah[0], pal[0]);
            pack_split(sc[2 * c][2],     sc[2 * c][3],     pah[1], pal[1]);
            pack_split(sc[2 * c + 1][0], sc[2 * c + 1][1], pah[2], pal[2]);
            pack_split(sc[2 * c + 1][2], sc[2 * c + 1][3], pah[3], pal[3]);
            #pragma unroll
            for (int dg = 0; dg < 4; dg++) {
                uint32_t ro = (uint32_t)((c * 16 + (lane & 15)) * 128) + dg * 32 + (lane >> 4) * 16;
                uint32_t t0, t1, t2, t3, u0, u1, u2, u3;
                LDSM_X4_T(t0, t1, t2, t3, kb + 16384 + SW128(ro));
                LDSM_X4_T(u0, u1, u2, u3, kb + 24576 + SW128(ro));
                mma4(oacc[2 * dg],     pah, t0, t1);
                mma4(oacc[2 * dg],     pah, u0, u1);
                mma4(oacc[2 * dg],     pal, t0, t1);
                mma4(oacc[2 * dg + 1], pah, t2, t3);
                mma4(oacc[2 * dg + 1], pah, u2, u3);
                mma4(oacc[2 * dg + 1], pal, t2, t3);
            }
        }
        __syncthreads();
    }

    float inv0 = 1.f / l0, inv1 = 1.f / l1;
    size_t r0 = qrow0 + wid * 16 + g;
    #pragma unroll
    for (int nf = 0; nf < 8; nf++) {
        int col = h * 64 + nf * 8 + tg * 2;
        float v0 = oacc[nf][0] * inv0, v1 = oacc[nf][1] * inv0;
        float v2 = oacc[nf][2] * inv1, v3 = oacc[nf][3] * inv1;
        __nv_bfloat16 h0, lo0, h1, lo1;
        split2(v0, h0, lo0); split2(v1, h1, lo1);
        *(__nv_bfloat162*)(oh + r0 * DIM + col) = __nv_bfloat162(h0, h1);
        *(__nv_bfloat162*)(ol + r0 * DIM + col) = __nv_bfloat162(lo0, lo1);
        split2(v2, h0, lo0); split2(v3, h1, lo1);
        *(__nv_bfloat162*)(oh + (r0 + 8) * DIM + col) = __nv_bfloat162(h0, h1);
        *(__nv_bfloat162*)(ol + (r0 + 8) * DIM + col) = __nv_bfloat162(lo0, lo1);
    }
}

// ============================================================================
// Final transpose: x[b,n,d] -> out[b,d,n]
// ============================================================================
__global__ void transpose_out_kernel(const float* __restrict__ x,
                                     float* __restrict__ out)
{
    __shared__ float t[32][33];
    int b = blockIdx.z;
    int n0 = blockIdx.x * 32, d0 = blockIdx.y * 32;
    int tx = threadIdx.x, ty = threadIdx.y;
    for (int i = ty; i < 32; i += 8)
        t[i][tx] = x[((size_t)b * NTOK + n0 + i) * DIM + d0 + tx];
    __syncthreads();
    for (int i = ty; i < 32; i += 8)
        out[((size_t)b * DIM + d0 + i) * NTOK + n0 + tx] = t[tx][i];
}

// ============================================================================
// Host orchestration
// ============================================================================
extern "C" void kernel_launch(void* const* d_in, const int* in_sizes, int n_in,
                              void* d_out, int out_size)
{
    const float* c_f    = (const float*)d_in[0];
    const float* conv_w = (const float*)d_in[1];
    const float* conv_b = (const float*)d_in[2];
    const float* ln1_w  = (const float*)d_in[3];
    const float* ln1_b  = (const float*)d_in[4];
    const float* qkv_w  = (const float*)d_in[5];
    const float* out_w  = (const float*)d_in[6];
    const float* out_b  = (const float*)d_in[7];
    const float* ln2_w  = (const float*)d_in[8];
    const float* ln2_b  = (const float*)d_in[9];
    const float* mlp_w1 = (const float*)d_in[10];
    const float* mlp_b1 = (const float*)d_in[11];
    const float* mlp_w2 = (const float*)d_in[12];
    const float* mlp_b2 = (const float*)d_in[13];
    float* out = (float*)d_out;

    cudaFuncSetAttribute(mma_gemm_kernel,
                         cudaFuncAttributeMaxDynamicSharedMemorySize, MMA_SMEM);
    cudaFuncSetAttribute(flash_mma_kernel,
                         cudaFuncAttributeMaxDynamicSharedMemorySize, ATT_SMEM);

    float *p_x, *p_part;
    __nv_bfloat16 *p_yh, *p_yl, *p_oh, *p_ol, *p_hh, *p_hl, *p_qh, *p_ql;
    __nv_bfloat16 *p_qwh, *p_qwl, *p_owh, *p_owl, *p_m1h, *p_m1l, *p_m2h, *p_m2l;
    cudaGetSymbolAddress((void**)&p_x,    g_x);
    cudaGetSymbolAddress((void**)&p_part, g_part);
    cudaGetSymbolAddress((void**)&p_yh,  g_yh);
    cudaGetSymbolAddress((void**)&p_yl,  g_yl);
    cudaGetSymbolAddress((void**)&p_oh,  g_oh);
    cudaGetSymbolAddress((void**)&p_ol,  g_ol);
    cudaGetSymbolAddress((void**)&p_hh,  g_hh);
    cudaGetSymbolAddress((void**)&p_hl,  g_hl);
    cudaGetSymbolAddress((void**)&p_qh,  g_qh);
    cudaGetSymbolAddress((void**)&p_ql,  g_ql);
    cudaGetSymbolAddress((void**)&p_qwh, g_qkvw_h);
    cudaGetSymbolAddress((void**)&p_qwl, g_qkvw_l);
    cudaGetSymbolAddress((void**)&p_owh, g_outw_h);
    cudaGetSymbolAddress((void**)&p_owl, g_outw_l);
    cudaGetSymbolAddress((void**)&p_m1h, g_m1w_h);
    cudaGetSymbolAddress((void**)&p_m1l, g_m1w_l);
    cudaGetSymbolAddress((void**)&p_m2h, g_m2w_h);
    cudaGetSymbolAddress((void**)&p_m2l, g_m2w_l);

    wsplit_all_kernel<<<DEPTH * WL_BLOCKS, dim3(32, 8)>>>(
        qkv_w, out_w, mlp_w1, mlp_w2,
        p_qwh, p_qwl, p_owh, p_owl, p_m1h, p_m1l, p_m2h, p_m2l);

    embed_kernel<<<dim3(NTOK / 64, DIM / 64, BATCH), 256>>>(c_f, conv_w, conv_b, p_x);

    // layer 0 LN1 (no pending split-K reduce)
    ln_split_kernel<<<ROWS / 8, 256>>>(nullptr, nullptr, p_x,
                                       ln1_w, ln1_b, p_yh, p_yl);

    for (int l = 0; l < DEPTH; l++) {
        mma_gemm_kernel<<<dim3(QKV3 / 128, ROWS / 128, 1), 256, MMA_SMEM>>>(
            DIM, QKV3, p_yh, p_yl,
            p_qwh + (size_t)l * QKV3 * DIM, p_qwl + (size_t)l * QKV3 * DIM,
            nullptr, nullptr, nullptr, p_qh, p_ql, 0);
        flash_mma_kernel<<<dim3(NTOK / 128, BATCH * HEADS), 256, ATT_SMEM>>>(
            p_qh, p_ql, p_oh, p_ol);
        // attn out-proj: split-K=2 -> partials; reduce fused into LN2
        mma_gemm_kernel<<<dim3(DIM / 128, ROWS / 128, 2), 256, MMA_SMEM>>>(
            DIM, DIM, p_oh, p_ol,
            p_owh + (size_t)l * DIM * DIM, p_owl + (size_t)l * DIM * DIM,
            nullptr, nullptr, p_part, nullptr, nullptr, 0);
        ln_split_kernel<<<ROWS / 8, 256>>>(p_part, out_b + l * DIM, p_x,
                                           ln2_w + l * DIM, ln2_b + l * DIM,
                                           p_yh, p_yl);
        mma_gemm_kernel<<<dim3(MLPD / 128, ROWS / 128, 1), 256, MMA_SMEM>>>(
            DIM, MLPD, p_yh, p_yl,
            p_m1h + (size_t)l * MLPD * DIM, p_m1l + (size_t)l * MLPD * DIM,
            mlp_b1 + l * MLPD, nullptr, nullptr, p_hh, p_hl, 1);
        // mlp2: split-K=2 -> partials; reduce fused into next layer's LN1
        mma_gemm_kernel<<<dim3(DIM / 128, ROWS / 128, 2), 256, MMA_SMEM>>>(
            MLPD, DIM, p_hh, p_hl,
            p_m2h + (size_t)l * DIM * MLPD, p_m2l + (size_t)l * DIM * MLPD,
            nullptr, nullptr, p_part, nullptr, nullptr, 0);
        if (l < DEPTH - 1) {
            ln_split_kernel<<<ROWS / 8, 256>>>(p_part, mlp_b2 + l * DIM, p_x,
                                               ln1_w + (l + 1) * DIM,
                                               ln1_b + (l + 1) * DIM,
                                               p_yh, p_yl);
        } else {
            reduce_add_kernel<<<ROWS * DIM / 1024, 256>>>(
                p_part, mlp_b2 + l * DIM, p_x, DIM);
        }
    }

    transpose_out_kernel<<<dim3(NTOK / 32, DIM / 32, BATCH), dim3(32, 8)>>>(p_x, out);
}